// round 2
// baseline (speedup 1.0000x reference)
#include <cuda_runtime.h>
#include <math.h>

#define NI 128
#define BSZ 32
#define NS 4
#define SEQ 2048
#define DIM 256
#define SROWS (NI*BSZ*NS)
#define LST 18
#define ATTN_SMEM ((SEQ*LST + 16*DIM + 16)*4)

typedef unsigned long long ull;

__device__ float g_k[BSZ*SEQ*DIM];
__device__ float g_v[BSZ*SEQ*DIM];
__device__ float g_slots[SROWS*DIM];
__device__ float g_qslot[SROWS*DIM];
__device__ float g_h[SROWS*DIM];
__device__ float g_t[SROWS*2*DIM];
__device__ float g_qintent[NI*DIM];
__device__ float g_qn[NI*DIM];
__device__ float g_clsn[BSZ*DIM];

__device__ __forceinline__ ull fma2(ull a, ull b, ull c){
    ull d; asm("fma.rn.f32x2 %0, %1, %2, %3;" : "=l"(d) : "l"(a),"l"(b),"l"(c)); return d;
}
__device__ __forceinline__ ull pack2(float x, float y){
    ull d; asm("mov.b64 %0, {%1, %2};" : "=l"(d) : "f"(x),"f"(y)); return d;
}
__device__ __forceinline__ float2 up2(ull v){
    float2 r; asm("mov.b64 {%0, %1}, %2;" : "=f"(r.x),"=f"(r.y) : "l"(v)); return r;
}
__device__ __forceinline__ float wsum(float v){
    #pragma unroll
    for(int o=16;o>0;o>>=1) v += __shfl_xor_sync(0xffffffffu, v, o);
    return v;
}
__device__ __forceinline__ float wmax(float v){
    #pragma unroll
    for(int o=16;o>0;o>>=1) v = fmaxf(v, __shfl_xor_sync(0xffffffffu, v, o));
    return v;
}

// C[M,N] = A@B + bias ; mode 0: none, 1: +extra[(row>>7)*N+col], 2: gelu, 3: +extra[row*N+col]
__global__ void __launch_bounds__(256) sgemm_kernel(
    const float* __restrict__ A, const float* __restrict__ B,
    const float* __restrict__ bias, const float* __restrict__ extra,
    float* __restrict__ C, int M, int N, int K, int mode)
{
    __shared__ float As[8][132];
    __shared__ float Bs[8][128];
    const int t = threadIdx.x;
    const int m0 = blockIdx.y<<7, n0 = blockIdx.x<<7;
    const int arow = t>>1, acol = (t&1)<<2;
    const int brow = t>>5, bcol = (t&31)<<2;
    const float* Ap = A + (size_t)(m0+arow)*K + acol;
    const float* Bp = B + (size_t)brow*N + n0 + bcol;
    float4 ar = *(const float4*)Ap;
    float4 br = *(const float4*)Bp;
    float c[8][8];
    #pragma unroll
    for(int i=0;i<8;i++)
        #pragma unroll
        for(int j=0;j<8;j++) c[i][j]=0.f;
    const int tm=(t>>4)<<3, tn=(t&15)<<3;
    const int nt = K>>3;
    for(int kt=0;kt<nt;kt++){
        As[acol+0][arow]=ar.x; As[acol+1][arow]=ar.y;
        As[acol+2][arow]=ar.z; As[acol+3][arow]=ar.w;
        *(float4*)&Bs[brow][bcol]=br;
        __syncthreads();
        if(kt+1<nt){
            ar = *(const float4*)(Ap + ((kt+1)<<3));
            br = *(const float4*)(Bp + (size_t)((kt+1)<<3)*N);
        }
        #pragma unroll
        for(int kk=0;kk<8;kk++){
            float4 a0=*(const float4*)&As[kk][tm];
            float4 a1=*(const float4*)&As[kk][tm+4];
            float4 b0=*(const float4*)&Bs[kk][tn];
            float4 b1=*(const float4*)&Bs[kk][tn+4];
            float a[8]={a0.x,a0.y,a0.z,a0.w,a1.x,a1.y,a1.z,a1.w};
            float bb[8]={b0.x,b0.y,b0.z,b0.w,b1.x,b1.y,b1.z,b1.w};
            #pragma unroll
            for(int i=0;i<8;i++)
                #pragma unroll
                for(int j=0;j<8;j++) c[i][j]=fmaf(a[i],bb[j],c[i][j]);
        }
        __syncthreads();
    }
    float bs[8];
    #pragma unroll
    for(int j=0;j<8;j++) bs[j]=bias[n0+tn+j];
    #pragma unroll
    for(int i=0;i<8;i++){
        const int row=m0+tm+i;
        float v[8];
        #pragma unroll
        for(int j=0;j<8;j++){
            float x=c[i][j]+bs[j];
            if(mode==1)      x += extra[(size_t)(row>>7)*N + n0+tn+j];
            else if(mode==2) x = 0.5f*x*(1.0f+erff(x*0.70710678118654752f));
            else if(mode==3) x += extra[(size_t)row*N + n0+tn+j];
            v[j]=x;
        }
        *(float4*)&C[(size_t)row*N + n0+tn]   = make_float4(v[0],v[1],v[2],v[3]);
        *(float4*)&C[(size_t)row*N + n0+tn+4] = make_float4(v[4],v[5],v[6],v[7]);
    }
}

__global__ void init_slots_kernel(const float* __restrict__ noise,
                                  const float* __restrict__ mu,
                                  const float* __restrict__ sigma,
                                  float* __restrict__ slots)
{
    for(int idx = blockIdx.x*blockDim.x + threadIdx.x; idx < SROWS*DIM;
        idx += gridDim.x*blockDim.x){
        int d = idx & (DIM-1);
        int n = (idx>>8)&3;
        slots[idx] = mu[n*DIM+d] + noise[idx]*sigma[n*DIM+d];
    }
}

__global__ void norm_rows_kernel(const float* __restrict__ iq,
                                 const float* __restrict__ cls,
                                 float* __restrict__ qn, float* __restrict__ clsn)
{
    const int row = blockIdx.x, lane = threadIdx.x;
    const float* src; float* dst;
    if(row < NI){ src = iq + (size_t)row*DIM; dst = qn + (size_t)row*DIM; }
    else        { src = cls + (size_t)(row-NI)*DIM; dst = clsn + (size_t)(row-NI)*DIM; }
    float4 a0=*(const float4*)(src + (lane<<2));
    float4 a1=*(const float4*)(src + 128 + (lane<<2));
    float ss=a0.x*a0.x+a0.y*a0.y+a0.z*a0.z+a0.w*a0.w
            +a1.x*a1.x+a1.y*a1.y+a1.z*a1.z+a1.w*a1.w;
    ss = wsum(ss);
    float inv = 1.0f/fmaxf(sqrtf(ss), 1e-12f);
    *(float4*)(dst+(lane<<2))     = make_float4(a0.x*inv,a0.y*inv,a0.z*inv,a0.w*inv);
    *(float4*)(dst+128+(lane<<2)) = make_float4(a1.x*inv,a1.y*inv,a1.z*inv,a1.w*inv);
}

// y = LN(x) * g + b, 8 rows per block (256 threads, 1 warp/row)
__global__ void __launch_bounds__(256) ln_rows_kernel(
    const float* __restrict__ x, const float* __restrict__ g,
    const float* __restrict__ bb, float* __restrict__ y)
{
    const int row = (blockIdx.x<<3) + (threadIdx.x>>5);
    const int lane = threadIdx.x & 31;
    const float* xp = x + (size_t)row*DIM;
    float4 a0=*(const float4*)(xp+(lane<<2));
    float4 a1=*(const float4*)(xp+128+(lane<<2));
    float v[8]={a0.x,a0.y,a0.z,a0.w,a1.x,a1.y,a1.z,a1.w};
    float s1=0.f,s2=0.f;
    #pragma unroll
    for(int q=0;q<8;q++){ s1+=v[q]; s2+=v[q]*v[q]; }
    s1=wsum(s1); s2=wsum(s2);
    float mean=s1*(1.0f/256.0f);
    float rstd=rsqrtf(s2*(1.0f/256.0f)-mean*mean + 1e-5f);
    float4 g0=*(const float4*)(g+(lane<<2)),  g1=*(const float4*)(g+128+(lane<<2));
    float4 b0=*(const float4*)(bb+(lane<<2)), b1=*(const float4*)(bb+128+(lane<<2));
    float* yp = y + (size_t)row*DIM;
    *(float4*)(yp+(lane<<2)) = make_float4(
        (v[0]-mean)*rstd*g0.x+b0.x,(v[1]-mean)*rstd*g0.y+b0.y,
        (v[2]-mean)*rstd*g0.z+b0.z,(v[3]-mean)*rstd*g0.w+b0.w);
    *(float4*)(yp+128+(lane<<2)) = make_float4(
        (v[4]-mean)*rstd*g1.x+b1.x,(v[5]-mean)*rstd*g1.y+b1.y,
        (v[6]-mean)*rstd*g1.z+b1.z,(v[7]-mean)*rstd*g1.w+b1.w);
}

// grid (NI/4, BSZ), 256 threads. slots_out = slots_in + attn@v (raw, LN done after)
__global__ void __launch_bounds__(256) attn_kernel(
    const float* __restrict__ qslot, float* __restrict__ slots)
{
    extern __shared__ float sm[];
    float* logit = sm;                       // [SEQ][LST]
    float* qbuf  = sm + SEQ*LST;             // [16][256]
    float* invs  = sm + SEQ*LST + 16*DIM;    // [16]
    const int b = blockIdx.y, i0 = blockIdx.x<<2, t = threadIdx.x;

    int gid[16];
    #pragma unroll
    for(int r=0;r<16;r++){
        gid[r] = ((i0 + (r>>2))*BSZ + b)*NS + (r&3);
        qbuf[r*DIM + t] = qslot[(size_t)gid[r]*DIM + t];
    }
    __syncthreads();

    // phase 1: logits (2 seq rows per thread-iteration, packed f32x2)
    const float* kb = g_k + (size_t)b*SEQ*DIM;
    for(int j=0;j<4;j++){
        const int s0 = (j<<9) + t;
        const ull* kp0 = (const ull*)(kb + (size_t)s0*DIM);
        const ull* kp1 = (const ull*)(kb + (size_t)(s0+256)*DIM);
        ull a0[16], a1[16];
        #pragma unroll
        for(int r=0;r<16;r++){ a0[r]=0ull; a1[r]=0ull; }
        #pragma unroll 2
        for(int d2=0;d2<128;d2++){
            ull k0=kp0[d2], k1=kp1[d2];
            #pragma unroll
            for(int r=0;r<16;r++){
                ull qq = *(const ull*)(qbuf + r*DIM + (d2<<1));
                a0[r]=fma2(qq,k0,a0[r]);
                a1[r]=fma2(qq,k1,a1[r]);
            }
        }
        #pragma unroll
        for(int r=0;r<16;r++){
            float2 p0=up2(a0[r]), p1=up2(a1[r]);
            logit[(size_t)s0*LST + r]       = (p0.x+p0.y)*0.0625f;
            logit[(size_t)(s0+256)*LST + r] = (p1.x+p1.y)*0.0625f;
        }
    }
    __syncthreads();

    // softmax: warp w owns rows 2w, 2w+1
    {
        const int w=t>>5, lane=t&31;
        float m0=-3.0e38f, m1=-3.0e38f;
        for(int jj=0;jj<SEQ/32;jj++){
            float2 p = *(const float2*)(logit + (size_t)(lane+(jj<<5))*LST + (w<<1));
            m0=fmaxf(m0,p.x); m1=fmaxf(m1,p.y);
        }
        m0=wmax(m0); m1=wmax(m1);
        float s0=0.f,s1=0.f;
        for(int jj=0;jj<SEQ/32;jj++){
            float* pp = logit + (size_t)(lane+(jj<<5))*LST + (w<<1);
            float e0=expf(pp[0]-m0), e1=expf(pp[1]-m1);
            pp[0]=e0; pp[1]=e1; s0+=e0; s1+=e1;
        }
        s0=wsum(s0); s1=wsum(s1);
        if(lane==0){ invs[(w<<1)]=1.0f/s0; invs[(w<<1)+1]=1.0f/s1; }
    }
    __syncthreads();

    // phase 2: upd = attn @ v ; thread owns column d=t for all 16 rows
    const float* vb = g_v + (size_t)b*SEQ*DIM + t;
    ull acc[8];
    #pragma unroll
    for(int p=0;p<8;p++) acc[p]=0ull;
    #pragma unroll 4
    for(int s=0;s<SEQ;s++){
        float vv = vb[(size_t)s*DIM];
        ull vvp = pack2(vv,vv);
        const float* lr = logit + (size_t)s*LST;
        #pragma unroll
        for(int p=0;p<8;p++)
            acc[p] = fma2(*(const ull*)(lr+(p<<1)), vvp, acc[p]);
    }
    #pragma unroll
    for(int p=0;p<8;p++){
        float2 u = up2(acc[p]);
        int r0=p<<1, r1=r0+1;
        slots[(size_t)gid[r0]*DIM + t] += u.x*invs[r0];
        slots[(size_t)gid[r1]*DIM + t] += u.y*invs[r1];
    }
}

// grid (NI, BSZ), 128 threads: final scoring
__global__ void __launch_bounds__(128) final_kernel(
    const float* __restrict__ slots, const float* __restrict__ qn,
    const float* __restrict__ clsn, const float* __restrict__ alpha,
    const float* __restrict__ temp, float* __restrict__ out)
{
    __shared__ float sh[4];
    const int i = blockIdx.x, b = blockIdx.y;
    const int w = threadIdx.x>>5, lane = threadIdx.x&31;
    const size_t base = ((size_t)(i*BSZ + b))*NS;
    const float* qp = qn + (size_t)i*DIM;
    const float* sp = slots + (base+w)*DIM;
    float ss=0.f, dq=0.f;
    #pragma unroll
    for(int q=0;q<8;q++){
        float x=sp[lane+(q<<5)], y=qp[lane+(q<<5)];
        ss+=x*x; dq+=x*y;
    }
    ss=wsum(ss); dq=wsum(dq);
    if(lane==0) sh[w] = dq / fmaxf(sqrtf(ss), 1e-12f);
    __syncthreads();
    float m=fmaxf(fmaxf(sh[0],sh[1]),fmaxf(sh[2],sh[3]));
    float e0=expf(sh[0]-m),e1=expf(sh[1]-m),e2=expf(sh[2]-m),e3=expf(sh[3]-m);
    float inv=1.0f/(e0+e1+e2+e3);
    float a4[4]={e0*inv,e1*inv,e2*inv,e3*inv};
    __syncthreads();
    const int d0=threadIdx.x, d1=threadIdx.x+128;
    float s0=0.f, s1=0.f;
    #pragma unroll
    for(int n=0;n<4;n++){
        const float* rp = slots + (base+n)*DIM;
        s0 += a4[n]*rp[d0]; s1 += a4[n]*rp[d1];
    }
    float pp = wsum(s0*s0 + s1*s1);
    if(lane==0) sh[w]=pp;
    __syncthreads();
    float nrm = fmaxf(sqrtf(sh[0]+sh[1]+sh[2]+sh[3]), 1e-12f);
    float al = *alpha;
    const float* cp = clsn + (size_t)b*DIM;
    float f0 = cp[d0] + al*s0/nrm;
    float f1 = cp[d1] + al*s1/nrm;
    float dot = wsum(f0*qp[d0] + f1*qp[d1]);
    __syncthreads();
    if(lane==0) sh[w]=dot;
    __syncthreads();
    if(threadIdx.x==0)
        out[(size_t)b*NI + i] = (sh[0]+sh[1]+sh[2]+sh[3]) / fmaxf(*temp, 1e-4f);
}

extern "C" void kernel_launch(void* const* d_in, const int* in_sizes, int n_in,
                              void* d_out, int out_size)
{
    const float* tokens=(const float*)d_in[0];
    const float* cls   =(const float*)d_in[1];
    const float* iq    =(const float*)d_in[2];
    const float* noise =(const float*)d_in[3];
    const float* Wk=(const float*)d_in[4],  *bk=(const float*)d_in[5];
    const float* Wv=(const float*)d_in[6],  *bv=(const float*)d_in[7];
    const float* Wqs=(const float*)d_in[8], *bqs=(const float*)d_in[9];
    const float* Wqi=(const float*)d_in[10],*bqi=(const float*)d_in[11];
    const float* ln1g=(const float*)d_in[12],*ln1b=(const float*)d_in[13];
    const float* ln2g=(const float*)d_in[14],*ln2b=(const float*)d_in[15];
    const float* Wf1=(const float*)d_in[16],*bf1=(const float*)d_in[17];
    const float* Wf2=(const float*)d_in[18],*bf2=(const float*)d_in[19];
    const float* mu=(const float*)d_in[20], *sg=(const float*)d_in[21];
    const float* alpha=(const float*)d_in[22],*temp=(const float*)d_in[23];
    float* out=(float*)d_out;

    float *k,*v,*slots,*qslot,*h,*tb,*qi,*qnp,*clsn;
    cudaGetSymbolAddress((void**)&k, g_k);
    cudaGetSymbolAddress((void**)&v, g_v);
    cudaGetSymbolAddress((void**)&slots, g_slots);
    cudaGetSymbolAddress((void**)&qslot, g_qslot);
    cudaGetSymbolAddress((void**)&h, g_h);
    cudaGetSymbolAddress((void**)&tb, g_t);
    cudaGetSymbolAddress((void**)&qi, g_qintent);
    cudaGetSymbolAddress((void**)&qnp, g_qn);
    cudaGetSymbolAddress((void**)&clsn, g_clsn);

    cudaFuncSetAttribute(attn_kernel, cudaFuncAttributeMaxDynamicSharedMemorySize, ATTN_SMEM);

    sgemm_kernel<<<dim3(2,512),256>>>(tokens, Wk, bk, nullptr, k, BSZ*SEQ, DIM, DIM, 0);
    sgemm_kernel<<<dim3(2,512),256>>>(tokens, Wv, bv, nullptr, v, BSZ*SEQ, DIM, DIM, 0);
    sgemm_kernel<<<dim3(2,1),  256>>>(iq, Wqi, bqi, nullptr, qi, NI, DIM, DIM, 0);
    init_slots_kernel<<<4096,256>>>(noise, mu, sg, slots);
    norm_rows_kernel<<<NI+BSZ,32>>>(iq, cls, qnp, clsn);

    for(int it=0; it<3; it++){
        sgemm_kernel<<<dim3(2,128),256>>>(slots, Wqs, bqs, qi, qslot, SROWS, DIM, DIM, 1);
        attn_kernel<<<dim3(NI/4,BSZ),256,ATTN_SMEM>>>(qslot, slots);
        ln_rows_kernel<<<SROWS/8,256>>>(slots, ln1g, ln1b, slots);
        ln_rows_kernel<<<SROWS/8,256>>>(slots, ln2g, ln2b, h);
        sgemm_kernel<<<dim3(4,128),256>>>(h, Wf1, bf1, nullptr, tb, SROWS, 2*DIM, DIM, 2);
        sgemm_kernel<<<dim3(2,128),256>>>(tb, Wf2, bf2, slots, slots, SROWS, DIM, 2*DIM, 3);
    }
    final_kernel<<<dim3(NI,BSZ),128>>>(slots, qnp, clsn, alpha, temp, out);
}

// round 3
// speedup vs baseline: 2.5918x; 2.5918x over previous
#include <cuda_runtime.h>
#include <math.h>

#define NI 128
#define BSZ 32
#define NS 4
#define SEQ 2048
#define DIM 256
#define SROWS (NI*BSZ*NS)
#define RPB (NI*NS)

typedef unsigned long long ull;

__device__ float g_k[BSZ*SEQ*DIM];
__device__ float g_v[BSZ*SEQ*DIM];
__device__ float g_L[(size_t)BSZ*RPB*SEQ];
__device__ float g_inv[SROWS];
__device__ float g_slots[SROWS*DIM];
__device__ float g_qslot[SROWS*DIM];
__device__ float g_h[SROWS*DIM];
__device__ float g_t[SROWS*2*DIM];
__device__ float g_qintent[NI*DIM];
__device__ float g_qn[NI*DIM];
__device__ float g_clsn[BSZ*DIM];

__device__ __forceinline__ ull fma2(ull a, ull b, ull c){
    ull d; asm("fma.rn.f32x2 %0, %1, %2, %3;" : "=l"(d) : "l"(a),"l"(b),"l"(c)); return d;
}
__device__ __forceinline__ ull pack2(float x, float y){
    ull d; asm("mov.b64 %0, {%1, %2};" : "=l"(d) : "f"(x),"f"(y)); return d;
}
__device__ __forceinline__ float2 up2(ull v){
    float2 r; asm("mov.b64 {%0, %1}, %2;" : "=f"(r.x),"=f"(r.y) : "l"(v)); return r;
}
__device__ __forceinline__ float wsum(float v){
    #pragma unroll
    for(int o=16;o>0;o>>=1) v += __shfl_xor_sync(0xffffffffu, v, o);
    return v;
}
__device__ __forceinline__ float wmax(float v){
    #pragma unroll
    for(int o=16;o>0;o>>=1) v = fmaxf(v, __shfl_xor_sync(0xffffffffu, v, o));
    return v;
}

// ---------------- packed-f32x2 NN GEMM, 128x128 tile ----------------
// C = A@B (+bias); modes: 0 none, 1 +extra[((row>>2)&127)*N+col],
// 2 gelu, 3 +extra[row*N+col], 4 *rowscale[row] + extra[row*N+col]
__global__ void __launch_bounds__(256) sgemm_nn(
    const float* __restrict__ A, const float* __restrict__ B,
    const float* __restrict__ bias, const float* __restrict__ extra,
    const float* __restrict__ rowscale, float* __restrict__ C,
    int M, int N, int K, int mode,
    size_t sA, size_t sB, size_t sC)
{
    __shared__ float As[8][132];
    __shared__ float Bs[8][128];
    const int t = threadIdx.x, z = blockIdx.z;
    A += (size_t)z*sA; B += (size_t)z*sB; C += (size_t)z*sC;
    const float* ext = extra ? extra + ((mode>=3)? (size_t)z*sC : 0) : extra;
    const float* rs  = rowscale ? rowscale + (size_t)z*M : rowscale;
    const int m0 = blockIdx.y<<7, n0 = blockIdx.x<<7;
    const int arow = t>>1, acol = (t&1)<<2;
    const int brow = t>>5, bcol = (t&31)<<2;
    const float* Ap = A + (size_t)(m0+arow)*K + acol;
    const float* Bp = B + (size_t)brow*N + n0 + bcol;
    float4 ar = *(const float4*)Ap;
    float4 br = *(const float4*)Bp;
    ull c2[8][4];
    #pragma unroll
    for(int i=0;i<8;i++){ c2[i][0]=0; c2[i][1]=0; c2[i][2]=0; c2[i][3]=0; }
    const int tm=(t>>4)<<3, tn=(t&15)<<3;
    const int nt = K>>3;
    for(int kt=0;kt<nt;kt++){
        As[acol+0][arow]=ar.x; As[acol+1][arow]=ar.y;
        As[acol+2][arow]=ar.z; As[acol+3][arow]=ar.w;
        *(float4*)&Bs[brow][bcol]=br;
        __syncthreads();
        if(kt+1<nt){
            ar = *(const float4*)(Ap + ((kt+1)<<3));
            br = *(const float4*)(Bp + (size_t)((kt+1)<<3)*N);
        }
        #pragma unroll
        for(int kk=0;kk<8;kk++){
            float4 a0=*(const float4*)&As[kk][tm];
            float4 a1=*(const float4*)&As[kk][tm+4];
            ulonglong2 w0=*(const ulonglong2*)&Bs[kk][tn];
            ulonglong2 w1=*(const ulonglong2*)&Bs[kk][tn+4];
            float a[8]={a0.x,a0.y,a0.z,a0.w,a1.x,a1.y,a1.z,a1.w};
            #pragma unroll
            for(int i=0;i<8;i++){
                ull ap = pack2(a[i],a[i]);
                c2[i][0]=fma2(ap,w0.x,c2[i][0]);
                c2[i][1]=fma2(ap,w0.y,c2[i][1]);
                c2[i][2]=fma2(ap,w1.x,c2[i][2]);
                c2[i][3]=fma2(ap,w1.y,c2[i][3]);
            }
        }
        __syncthreads();
    }
    float bs[8];
    #pragma unroll
    for(int j=0;j<8;j++) bs[j] = bias ? bias[n0+tn+j] : 0.f;
    #pragma unroll
    for(int i=0;i<8;i++){
        const int row=m0+tm+i;
        float v[8];
        #pragma unroll
        for(int p=0;p<4;p++){ float2 u=up2(c2[i][p]); v[2*p]=u.x; v[2*p+1]=u.y; }
        #pragma unroll
        for(int j=0;j<8;j++){
            float x=v[j]+bs[j];
            if(mode==1)      x += ext[(size_t)((row>>2)&127)*N + n0+tn+j];
            else if(mode==2) x = 0.5f*x*(1.0f+erff(x*0.70710678118654752f));
            else if(mode==3) x += ext[(size_t)row*N + n0+tn+j];
            else if(mode==4) x = x*rs[row] + ext[(size_t)row*N + n0+tn+j];
            v[j]=x;
        }
        *(float4*)&C[(size_t)row*N + n0+tn]   = make_float4(v[0],v[1],v[2],v[3]);
        *(float4*)&C[(size_t)row*N + n0+tn+4] = make_float4(v[4],v[5],v[6],v[7]);
    }
}

// ---------------- packed NT GEMM for logits: C=(A@B^T)/16 per batch ----------------
// A=qslot_b [RPB x DIM], B=k_b [SEQ x DIM], C=L_b [RPB x SEQ]; grid (SEQ/128, RPB/128, BSZ)
__global__ void __launch_bounds__(256) sgemm_nt_logits(
    const float* __restrict__ Aq, const float* __restrict__ Bk, float* __restrict__ C)
{
    __shared__ float As[8][132];
    __shared__ float Bs[8][132];
    const int t = threadIdx.x, z = blockIdx.z;
    const float* A = Aq + (size_t)z*RPB*DIM;
    const float* B = Bk + (size_t)z*SEQ*DIM;
    float* Cz = C + (size_t)z*RPB*SEQ;
    const int m0 = blockIdx.y<<7, n0 = blockIdx.x<<7;
    const int arow = t>>1, acol = (t&1)<<2;
    const float* Ap = A + (size_t)(m0+arow)*DIM + acol;
    const float* Bp = B + (size_t)(n0+arow)*DIM + acol;
    float4 ar = *(const float4*)Ap;
    float4 br = *(const float4*)Bp;
    ull c2[8][4];
    #pragma unroll
    for(int i=0;i<8;i++){ c2[i][0]=0; c2[i][1]=0; c2[i][2]=0; c2[i][3]=0; }
    const int tm=(t>>4)<<3, tn=(t&15)<<3;
    for(int kt=0;kt<DIM/8;kt++){
        As[acol+0][arow]=ar.x; As[acol+1][arow]=ar.y;
        As[acol+2][arow]=ar.z; As[acol+3][arow]=ar.w;
        Bs[acol+0][arow]=br.x; Bs[acol+1][arow]=br.y;
        Bs[acol+2][arow]=br.z; Bs[acol+3][arow]=br.w;
        __syncthreads();
        if(kt+1<DIM/8){
            ar = *(const float4*)(Ap + ((kt+1)<<3));
            br = *(const float4*)(Bp + ((kt+1)<<3));
        }
        #pragma unroll
        for(int kk=0;kk<8;kk++){
            float4 a0=*(const float4*)&As[kk][tm];
            float4 a1=*(const float4*)&As[kk][tm+4];
            ulonglong2 w0=*(const ulonglong2*)&Bs[kk][tn];
            ulonglong2 w1=*(const ulonglong2*)&Bs[kk][tn+4];
            float a[8]={a0.x,a0.y,a0.z,a0.w,a1.x,a1.y,a1.z,a1.w};
            #pragma unroll
            for(int i=0;i<8;i++){
                ull ap = pack2(a[i],a[i]);
                c2[i][0]=fma2(ap,w0.x,c2[i][0]);
                c2[i][1]=fma2(ap,w0.y,c2[i][1]);
                c2[i][2]=fma2(ap,w1.x,c2[i][2]);
                c2[i][3]=fma2(ap,w1.y,c2[i][3]);
            }
        }
        __syncthreads();
    }
    #pragma unroll
    for(int i=0;i<8;i++){
        const int row=m0+tm+i;
        float v[8];
        #pragma unroll
        for(int p=0;p<4;p++){ float2 u=up2(c2[i][p]); v[2*p]=u.x*0.0625f; v[2*p+1]=u.y*0.0625f; }
        *(float4*)&Cz[(size_t)row*SEQ + n0+tn]   = make_float4(v[0],v[1],v[2],v[3]);
        *(float4*)&Cz[(size_t)row*SEQ + n0+tn+4] = make_float4(v[4],v[5],v[6],v[7]);
    }
}

// ---------------- softmax: exp(x-max) stored, inv-sum saved ----------------
__global__ void __launch_bounds__(256) softmax_kernel(float* __restrict__ L, float* __restrict__ inv)
{
    __shared__ float sm[8];
    const size_t row = blockIdx.x;
    float4* rp = (float4*)(L + row*SEQ);
    const int t = threadIdx.x, w = t>>5, lane = t&31;
    float4 x0 = rp[t], x1 = rp[t+256];
    float m = fmaxf(fmaxf(fmaxf(x0.x,x0.y),fmaxf(x0.z,x0.w)),
                    fmaxf(fmaxf(x1.x,x1.y),fmaxf(x1.z,x1.w)));
    m = wmax(m);
    if(lane==0) sm[w]=m;
    __syncthreads();
    m = sm[0];
    #pragma unroll
    for(int q=1;q<8;q++) m = fmaxf(m, sm[q]);
    __syncthreads();
    x0.x=__expf(x0.x-m); x0.y=__expf(x0.y-m); x0.z=__expf(x0.z-m); x0.w=__expf(x0.w-m);
    x1.x=__expf(x1.x-m); x1.y=__expf(x1.y-m); x1.z=__expf(x1.z-m); x1.w=__expf(x1.w-m);
    float s = x0.x+x0.y+x0.z+x0.w + x1.x+x1.y+x1.z+x1.w;
    s = wsum(s);
    if(lane==0) sm[w]=s;
    rp[t]=x0; rp[t+256]=x1;
    __syncthreads();
    if(t==0){
        float tot = sm[0]+sm[1]+sm[2]+sm[3]+sm[4]+sm[5]+sm[6]+sm[7];
        inv[row] = 1.0f/tot;
    }
}

__global__ void init_slots_kernel(const float* __restrict__ noise,
                                  const float* __restrict__ mu,
                                  const float* __restrict__ sigma,
                                  float* __restrict__ slots)
{
    for(int idx = blockIdx.x*blockDim.x + threadIdx.x; idx < SROWS*DIM;
        idx += gridDim.x*blockDim.x){
        int d = idx & 255, ns = (idx>>8)&3, i = (idx>>10)&127, b = idx>>17;
        slots[idx] = mu[ns*DIM+d] + noise[(size_t)(((i*BSZ+b)*NS+ns))*DIM+d]*sigma[ns*DIM+d];
    }
}

__global__ void norm_rows_kernel(const float* __restrict__ iq,
                                 const float* __restrict__ cls,
                                 float* __restrict__ qn, float* __restrict__ clsn)
{
    const int row = blockIdx.x, lane = threadIdx.x;
    const float* src; float* dst;
    if(row < NI){ src = iq + (size_t)row*DIM; dst = qn + (size_t)row*DIM; }
    else        { src = cls + (size_t)(row-NI)*DIM; dst = clsn + (size_t)(row-NI)*DIM; }
    float4 a0=*(const float4*)(src + (lane<<2));
    float4 a1=*(const float4*)(src + 128 + (lane<<2));
    float ss=a0.x*a0.x+a0.y*a0.y+a0.z*a0.z+a0.w*a0.w
            +a1.x*a1.x+a1.y*a1.y+a1.z*a1.z+a1.w*a1.w;
    ss = wsum(ss);
    float inv = 1.0f/fmaxf(sqrtf(ss), 1e-12f);
    *(float4*)(dst+(lane<<2))     = make_float4(a0.x*inv,a0.y*inv,a0.z*inv,a0.w*inv);
    *(float4*)(dst+128+(lane<<2)) = make_float4(a1.x*inv,a1.y*inv,a1.z*inv,a1.w*inv);
}

__global__ void __launch_bounds__(256) ln_rows_kernel(
    const float* __restrict__ x, const float* __restrict__ g,
    const float* __restrict__ bb, float* __restrict__ y)
{
    const int row = (blockIdx.x<<3) + (threadIdx.x>>5);
    const int lane = threadIdx.x & 31;
    const float* xp = x + (size_t)row*DIM;
    float4 a0=*(const float4*)(xp+(lane<<2));
    float4 a1=*(const float4*)(xp+128+(lane<<2));
    float v[8]={a0.x,a0.y,a0.z,a0.w,a1.x,a1.y,a1.z,a1.w};
    float s1=0.f,s2=0.f;
    #pragma unroll
    for(int q=0;q<8;q++){ s1+=v[q]; s2+=v[q]*v[q]; }
    s1=wsum(s1); s2=wsum(s2);
    float mean=s1*(1.0f/256.0f);
    float rstd=rsqrtf(s2*(1.0f/256.0f)-mean*mean + 1e-5f);
    float4 g0=*(const float4*)(g+(lane<<2)),  g1=*(const float4*)(g+128+(lane<<2));
    float4 b0=*(const float4*)(bb+(lane<<2)), b1=*(const float4*)(bb+128+(lane<<2));
    float* yp = y + (size_t)row*DIM;
    *(float4*)(yp+(lane<<2)) = make_float4(
        (v[0]-mean)*rstd*g0.x+b0.x,(v[1]-mean)*rstd*g0.y+b0.y,
        (v[2]-mean)*rstd*g0.z+b0.z,(v[3]-mean)*rstd*g0.w+b0.w);
    *(float4*)(yp+128+(lane<<2)) = make_float4(
        (v[4]-mean)*rstd*g1.x+b1.x,(v[5]-mean)*rstd*g1.y+b1.y,
        (v[6]-mean)*rstd*g1.z+b1.z,(v[7]-mean)*rstd*g1.w+b1.w);
}

__global__ void __launch_bounds__(128) final_kernel(
    const float* __restrict__ slots, const float* __restrict__ qn,
    const float* __restrict__ clsn, const float* __restrict__ alpha,
    const float* __restrict__ temp, float* __restrict__ out)
{
    __shared__ float sh[4];
    const int i = blockIdx.x, b = blockIdx.y;
    const int w = threadIdx.x>>5, lane = threadIdx.x&31;
    const size_t base = ((size_t)(b*NI + i))*NS;
    const float* qp = qn + (size_t)i*DIM;
    const float* sp = slots + (base+w)*DIM;
    float ss=0.f, dq=0.f;
    #pragma unroll
    for(int q=0;q<8;q++){
        float x=sp[lane+(q<<5)], y=qp[lane+(q<<5)];
        ss+=x*x; dq+=x*y;
    }
    ss=wsum(ss); dq=wsum(dq);
    if(lane==0) sh[w] = dq / fmaxf(sqrtf(ss), 1e-12f);
    __syncthreads();
    float m=fmaxf(fmaxf(sh[0],sh[1]),fmaxf(sh[2],sh[3]));
    float e0=expf(sh[0]-m),e1=expf(sh[1]-m),e2=expf(sh[2]-m),e3=expf(sh[3]-m);
    float inv=1.0f/(e0+e1+e2+e3);
    float a4[4]={e0*inv,e1*inv,e2*inv,e3*inv};
    __syncthreads();
    const int d0=threadIdx.x, d1=threadIdx.x+128;
    float s0=0.f, s1=0.f;
    #pragma unroll
    for(int n=0;n<4;n++){
        const float* rp = slots + (base+n)*DIM;
        s0 += a4[n]*rp[d0]; s1 += a4[n]*rp[d1];
    }
    float pp = wsum(s0*s0 + s1*s1);
    if(lane==0) sh[w]=pp;
    __syncthreads();
    float nrm = fmaxf(sqrtf(sh[0]+sh[1]+sh[2]+sh[3]), 1e-12f);
    float al = *alpha;
    const float* cp = clsn + (size_t)b*DIM;
    float f0 = cp[d0] + al*s0/nrm;
    float f1 = cp[d1] + al*s1/nrm;
    float dot = wsum(f0*qp[d0] + f1*qp[d1]);
    __syncthreads();
    if(lane==0) sh[w]=dot;
    __syncthreads();
    if(threadIdx.x==0)
        out[(size_t)b*NI + i] = (sh[0]+sh[1]+sh[2]+sh[3]) / fmaxf(*temp, 1e-4f);
}

extern "C" void kernel_launch(void* const* d_in, const int* in_sizes, int n_in,
                              void* d_out, int out_size)
{
    const float* tokens=(const float*)d_in[0];
    const float* cls   =(const float*)d_in[1];
    const float* iq    =(const float*)d_in[2];
    const float* noise =(const float*)d_in[3];
    const float* Wk=(const float*)d_in[4],  *bk=(const float*)d_in[5];
    const float* Wv=(const float*)d_in[6],  *bv=(const float*)d_in[7];
    const float* Wqs=(const float*)d_in[8], *bqs=(const float*)d_in[9];
    const float* Wqi=(const float*)d_in[10],*bqi=(const float*)d_in[11];
    const float* ln1g=(const float*)d_in[12],*ln1b=(const float*)d_in[13];
    const float* ln2g=(const float*)d_in[14],*ln2b=(const float*)d_in[15];
    const float* Wf1=(const float*)d_in[16],*bf1=(const float*)d_in[17];
    const float* Wf2=(const float*)d_in[18],*bf2=(const float*)d_in[19];
    const float* mu=(const float*)d_in[20], *sg=(const float*)d_in[21];
    const float* alpha=(const float*)d_in[22],*temp=(const float*)d_in[23];
    float* out=(float*)d_out;

    float *k,*v,*L,*invp,*slots,*qslot,*h,*tb,*qi,*qnp,*clsn;
    cudaGetSymbolAddress((void**)&k, g_k);
    cudaGetSymbolAddress((void**)&v, g_v);
    cudaGetSymbolAddress((void**)&L, g_L);
    cudaGetSymbolAddress((void**)&invp, g_inv);
    cudaGetSymbolAddress((void**)&slots, g_slots);
    cudaGetSymbolAddress((void**)&qslot, g_qslot);
    cudaGetSymbolAddress((void**)&h, g_h);
    cudaGetSymbolAddress((void**)&tb, g_t);
    cudaGetSymbolAddress((void**)&qi, g_qintent);
    cudaGetSymbolAddress((void**)&qnp, g_qn);
    cudaGetSymbolAddress((void**)&clsn, g_clsn);

    sgemm_nn<<<dim3(2,512),256>>>(tokens, Wk, bk, nullptr, nullptr, k, BSZ*SEQ, DIM, DIM, 0, 0,0,0);
    sgemm_nn<<<dim3(2,512),256>>>(tokens, Wv, bv, nullptr, nullptr, v, BSZ*SEQ, DIM, DIM, 0, 0,0,0);
    sgemm_nn<<<dim3(2,1),  256>>>(iq, Wqi, bqi, nullptr, nullptr, qi, NI, DIM, DIM, 0, 0,0,0);
    init_slots_kernel<<<4096,256>>>(noise, mu, sg, slots);
    norm_rows_kernel<<<NI+BSZ,32>>>(iq, cls, qnp, clsn);

    for(int it=0; it<3; it++){
        sgemm_nn<<<dim3(2,128),256>>>(slots, Wqs, bqs, qi, nullptr, qslot, SROWS, DIM, DIM, 1, 0,0,0);
        sgemm_nt_logits<<<dim3(SEQ/128, RPB/128, BSZ),256>>>(qslot, k, L);
        softmax_kernel<<<SROWS,256>>>(L, invp);
        sgemm_nn<<<dim3(2,4,BSZ),256>>>(L, v, nullptr, slots, invp, slots,
                                        RPB, DIM, SEQ, 4,
                                        (size_t)RPB*SEQ, (size_t)SEQ*DIM, (size_t)RPB*DIM);
        ln_rows_kernel<<<SROWS/8,256>>>(slots, ln1g, ln1b, slots);
        ln_rows_kernel<<<SROWS/8,256>>>(slots, ln2g, ln2b, h);
        sgemm_nn<<<dim3(4,128),256>>>(h, Wf1, bf1, nullptr, nullptr, tb, SROWS, 2*DIM, DIM, 2, 0,0,0);
        sgemm_nn<<<dim3(2,128),256>>>(tb, Wf2, bf2, slots, nullptr, slots, SROWS, DIM, 2*DIM, 3, 0,0,0);
    }
    final_kernel<<<dim3(NI,BSZ),128>>>(slots, qnp, clsn, alpha, temp, out);
}

// round 6
// speedup vs baseline: 5.4336x; 2.0965x over previous
#include <cuda_runtime.h>
#include <cuda_bf16.h>
#include <cstdint>
#include <math.h>

#define NI 128
#define BSZ 32
#define NS 4
#define SEQ 2048
#define DIM 256
#define SROWS (NI*BSZ*NS)
#define RPB (NI*NS)

typedef unsigned long long ull;

__device__ float g_k[BSZ*SEQ*DIM];
__device__ float g_v[BSZ*SEQ*DIM];
__device__ __nv_bfloat16 g_kbf[BSZ*SEQ*DIM];
__device__ __nv_bfloat16 g_vt[BSZ*SEQ*DIM];     // [b][d][s]
__device__ __nv_bfloat16 g_qbf[SROWS*DIM];
__device__ __nv_bfloat16 g_P[(size_t)BSZ*RPB*SEQ];
__device__ float g_L[(size_t)BSZ*RPB*SEQ];
__device__ float g_inv[SROWS];
__device__ float g_slots[SROWS*DIM];
__device__ float g_qslot[SROWS*DIM];
__device__ float g_h[SROWS*DIM];
__device__ float g_t[SROWS*2*DIM];
__device__ float g_qintent[NI*DIM];
__device__ float g_qn[NI*DIM];
__device__ float g_clsn[BSZ*DIM];

__device__ __forceinline__ ull fma2(ull a, ull b, ull c){
    ull d; asm("fma.rn.f32x2 %0, %1, %2, %3;" : "=l"(d) : "l"(a),"l"(b),"l"(c)); return d;
}
__device__ __forceinline__ ull pack2(float x, float y){
    ull d; asm("mov.b64 %0, {%1, %2};" : "=l"(d) : "f"(x),"f"(y)); return d;
}
__device__ __forceinline__ float2 up2(ull v){
    float2 r; asm("mov.b64 {%0, %1}, %2;" : "=f"(r.x),"=f"(r.y) : "l"(v)); return r;
}
__device__ __forceinline__ float wsum(float v){
    #pragma unroll
    for(int o=16;o>0;o>>=1) v += __shfl_xor_sync(0xffffffffu, v, o);
    return v;
}
__device__ __forceinline__ float wmax(float v){
    #pragma unroll
    for(int o=16;o>0;o>>=1) v = fmaxf(v, __shfl_xor_sync(0xffffffffu, v, o));
    return v;
}
__device__ __forceinline__ uint32_t smem_u32(const void* p){
    uint32_t a; asm("{ .reg .u64 t; cvta.to.shared.u64 t, %1; cvt.u32.u64 %0, t; }" : "=r"(a) : "l"(p));
    return a;
}
#define SW128(o) ((o) ^ (((o)>>3)&0x70))

__device__ __forceinline__ void ldsm4(uint32_t& r0,uint32_t& r1,uint32_t& r2,uint32_t& r3,uint32_t a){
    asm volatile("ldmatrix.sync.aligned.m8n8.x4.shared.b16 {%0,%1,%2,%3}, [%4];"
        : "=r"(r0),"=r"(r1),"=r"(r2),"=r"(r3) : "r"(a) : "memory");
}
__device__ __forceinline__ void mma16816(float* c,uint32_t a0,uint32_t a1,uint32_t a2,uint32_t a3,uint32_t b0,uint32_t b1){
    asm volatile("mma.sync.aligned.m16n8k16.row.col.f32.bf16.bf16.f32 "
        "{%0,%1,%2,%3},{%4,%5,%6,%7},{%8,%9},{%0,%1,%2,%3};"
        : "+f"(c[0]),"+f"(c[1]),"+f"(c[2]),"+f"(c[3])
        : "r"(a0),"r"(a1),"r"(a2),"r"(a3),"r"(b0),"r"(b1));
}
__device__ __forceinline__ void cpa16(uint32_t d, const void* s){
    asm volatile("cp.async.cg.shared.global [%0], [%1], 16;" :: "r"(d), "l"(s));
}
#define CP_COMMIT() asm volatile("cp.async.commit_group;" ::: "memory")
#define CP_WAIT0()  asm volatile("cp.async.wait_group 0;" ::: "memory")

// ============ bf16 NT GEMM via mma.sync: C[M,N] = A[M,K] @ B[N,K]^T ============
// mode 0: C = acc/16 ; mode 1: C = acc*inv[row] + res[row*ldc+col]
// grid (N/128, M/128, BSZ), 256 threads, 64KB dyn smem
__global__ void __launch_bounds__(256) mma_nt(
    const __nv_bfloat16* __restrict__ A, const __nv_bfloat16* __restrict__ B,
    float* __restrict__ C, int lda, int ldb, int ldc, int K,
    size_t sA, size_t sB, size_t sC, int mode,
    const float* __restrict__ inv, const float* __restrict__ res)
{
    extern __shared__ char sm[];
    const uint32_t su = smem_u32(sm);
    const int t = threadIdx.x, wid = t>>5, lane = t&31, z = blockIdx.z;
    const int m0 = blockIdx.y<<7, n0 = blockIdx.x<<7;
    A += (size_t)z*sA + (size_t)m0*lda;
    B += (size_t)z*sB + (size_t)n0*ldb;
    C += (size_t)z*sC;

    const int row_ld = t>>3, col_ld = t&7;     // thread loads rows row_ld, +32, +64, +96
    const uint32_t swoff = SW128((uint32_t)(row_ld*128 + col_ld*16));
    const int nsteps = K>>6;

    float acc[2][8][4];
    #pragma unroll
    for(int i=0;i<2;i++)
        #pragma unroll
        for(int j=0;j<8;j++){ acc[i][j][0]=0.f; acc[i][j][1]=0.f; acc[i][j][2]=0.f; acc[i][j][3]=0.f; }

    // preload step 0
    {
        const __nv_bfloat16* Ag = A + col_ld*8;
        const __nv_bfloat16* Bg = B + col_ld*8;
        #pragma unroll
        for(int j=0;j<4;j++){
            cpa16(su + swoff + j*4096, Ag + (size_t)(row_ld + j*32)*lda);
            cpa16(su + 16384 + swoff + j*4096, Bg + (size_t)(row_ld + j*32)*ldb);
        }
        CP_COMMIT(); CP_WAIT0();
    }
    __syncthreads();

    const int mw = (wid&3)<<5, nw = (wid>>2)<<6;
    for(int s=0;s<nsteps;s++){
        const uint32_t bufc = su + (uint32_t)((s&1)*32768);
        if(s+1<nsteps){
            const uint32_t bufn = su + (uint32_t)(((s+1)&1)*32768);
            const __nv_bfloat16* Ag = A + (size_t)(s+1)*64 + col_ld*8;
            const __nv_bfloat16* Bg = B + (size_t)(s+1)*64 + col_ld*8;
            #pragma unroll
            for(int j=0;j<4;j++){
                cpa16(bufn + swoff + j*4096, Ag + (size_t)(row_ld + j*32)*lda);
                cpa16(bufn + 16384 + swoff + j*4096, Bg + (size_t)(row_ld + j*32)*ldb);
            }
            CP_COMMIT();
        }
        #pragma unroll
        for(int kk=0;kk<4;kk++){
            const int kb = kk*32 + ((lane>>4)*16);
            uint32_t a[2][4];
            #pragma unroll
            for(int mf=0;mf<2;mf++){
                int row = mw + mf*16 + (lane&15);
                ldsm4(a[mf][0],a[mf][1],a[mf][2],a[mf][3], bufc + SW128((uint32_t)(row*128 + kb)));
            }
            #pragma unroll
            for(int ng=0;ng<4;ng++){
                int row = nw + ng*16 + (lane&15);
                uint32_t b0,b1,b2,b3;
                ldsm4(b0,b1,b2,b3, bufc + 16384 + SW128((uint32_t)(row*128 + kb)));
                #pragma unroll
                for(int mf=0;mf<2;mf++){
                    mma16816(acc[mf][ng*2+0], a[mf][0],a[mf][1],a[mf][2],a[mf][3], b0, b2);
                    mma16816(acc[mf][ng*2+1], a[mf][0],a[mf][1],a[mf][2],a[mf][3], b1, b3);
                }
            }
        }
        if(s+1<nsteps) CP_WAIT0();
        __syncthreads();
    }

    // epilogue
    const int gr = lane>>2, gc = (lane&3)<<1;
    #pragma unroll
    for(int mf=0;mf<2;mf++){
        const int r0 = m0 + mw + mf*16 + gr;
        float i0=0.0625f, i1=0.0625f;
        if(mode==1){ i0 = inv[z*RPB + r0]; i1 = inv[z*RPB + r0 + 8]; }
        #pragma unroll
        for(int ng=0;ng<4;ng++){
            #pragma unroll
            for(int h=0;h<2;h++){
                const int col = n0 + nw + ng*16 + h*8 + gc;
                float* cc = acc[mf][ng*2+h];
                if(mode==0){
                    C[(size_t)r0*ldc + col]       = cc[0]*0.0625f;
                    C[(size_t)r0*ldc + col + 1]   = cc[1]*0.0625f;
                    C[(size_t)(r0+8)*ldc + col]   = cc[2]*0.0625f;
                    C[(size_t)(r0+8)*ldc + col+1] = cc[3]*0.0625f;
                } else {
                    const float* rz = res + (size_t)z*sC;
                    C[(size_t)r0*ldc + col]       = cc[0]*i0 + rz[(size_t)r0*ldc + col];
                    C[(size_t)r0*ldc + col + 1]   = cc[1]*i0 + rz[(size_t)r0*ldc + col + 1];
                    C[(size_t)(r0+8)*ldc + col]   = cc[2]*i1 + rz[(size_t)(r0+8)*ldc + col];
                    C[(size_t)(r0+8)*ldc + col+1] = cc[3]*i1 + rz[(size_t)(r0+8)*ldc + col+1];
                }
            }
        }
    }
}

// ================= fp32 -> bf16 =================
__global__ void __launch_bounds__(256) f2bf_kernel(
    const float* __restrict__ x, __nv_bfloat16* __restrict__ y, int n4)
{
    int i = blockIdx.x*blockDim.x + threadIdx.x;
    if (i >= n4) return;
    float4 v = ((const float4*)x)[i];
    __nv_bfloat162 a; a.x=__float2bfloat16(v.x); a.y=__float2bfloat16(v.y);
    __nv_bfloat162 b; b.x=__float2bfloat16(v.z); b.y=__float2bfloat16(v.w);
    ((__nv_bfloat162*)y)[2*i] = a;
    ((__nv_bfloat162*)y)[2*i+1] = b;
}

// ======= transpose+convert: v[b][s][d] fp32 -> vt[b][d][s] bf16; grid (SEQ/64, DIM/64, BSZ) =======
__global__ void __launch_bounds__(256) transpose_bf_kernel(
    const float* __restrict__ v, __nv_bfloat16* __restrict__ vt)
{
    __shared__ __nv_bfloat16 tl[64][65];
    const int s0 = blockIdx.x<<6, d0 = blockIdx.y<<6, z = blockIdx.z;
    const float* vz = v + (size_t)z*SEQ*DIM;
    __nv_bfloat16* vtz = vt + (size_t)z*SEQ*DIM;
    const int t = threadIdx.x;
    #pragma unroll
    for(int j=0;j<16;j++){
        int idx = j*256 + t, r = idx>>6, c = idx&63;
        tl[r][c] = __float2bfloat16(vz[(size_t)(s0+r)*DIM + d0 + c]);
    }
    __syncthreads();
    #pragma unroll
    for(int j=0;j<16;j++){
        int idx = j*256 + t, r = idx>>6, c = idx&63;
        vtz[(size_t)(d0+r)*SEQ + s0 + c] = tl[c][r];
    }
}

// ================= packed-f32x2 NN GEMM =================
__global__ void __launch_bounds__(256) sgemm_nn(
    const float* __restrict__ A, const float* __restrict__ B,
    const float* __restrict__ bias, const float* __restrict__ extra,
    float* __restrict__ C, __nv_bfloat16* __restrict__ Cb,
    int M, int N, int K, int mode)
{
    __shared__ float As[8][132];
    __shared__ float Bs[8][128];
    const int t = threadIdx.x;
    const int m0 = blockIdx.y<<7, n0 = blockIdx.x<<7;
    const int arow = t>>1, acol = (t&1)<<2;
    const int brow = t>>5, bcol = (t&31)<<2;
    const float* Ap = A + (size_t)(m0+arow)*K + acol;
    const float* Bp = B + (size_t)brow*N + n0 + bcol;
    float4 ar = *(const float4*)Ap;
    float4 br = *(const float4*)Bp;
    ull c2[8][4];
    #pragma unroll
    for(int i=0;i<8;i++){ c2[i][0]=0; c2[i][1]=0; c2[i][2]=0; c2[i][3]=0; }
    const int tm=(t>>4)<<3, tn=(t&15)<<3;
    const int nt = K>>3;
    for(int kt=0;kt<nt;kt++){
        As[acol+0][arow]=ar.x; As[acol+1][arow]=ar.y;
        As[acol+2][arow]=ar.z; As[acol+3][arow]=ar.w;
        *(float4*)&Bs[brow][bcol]=br;
        __syncthreads();
        if(kt+1<nt){
            ar = *(const float4*)(Ap + ((kt+1)<<3));
            br = *(const float4*)(Bp + (size_t)((kt+1)<<3)*N);
        }
        #pragma unroll
        for(int kk=0;kk<8;kk++){
            float4 a0=*(const float4*)&As[kk][tm];
            float4 a1=*(const float4*)&As[kk][tm+4];
            ulonglong2 w0=*(const ulonglong2*)&Bs[kk][tn];
            ulonglong2 w1=*(const ulonglong2*)&Bs[kk][tn+4];
            float a[8]={a0.x,a0.y,a0.z,a0.w,a1.x,a1.y,a1.z,a1.w};
            #pragma unroll
            for(int i=0;i<8;i++){
                ull ap = pack2(a[i],a[i]);
                c2[i][0]=fma2(ap,w0.x,c2[i][0]);
                c2[i][1]=fma2(ap,w0.y,c2[i][1]);
                c2[i][2]=fma2(ap,w1.x,c2[i][2]);
                c2[i][3]=fma2(ap,w1.y,c2[i][3]);
            }
        }
        __syncthreads();
    }
    float bs[8];
    #pragma unroll
    for(int j=0;j<8;j++) bs[j] = bias ? bias[n0+tn+j] : 0.f;
    #pragma unroll
    for(int i=0;i<8;i++){
        const int row=m0+tm+i;
        float v[8];
        #pragma unroll
        for(int p=0;p<4;p++){ float2 u=up2(c2[i][p]); v[2*p]=u.x; v[2*p+1]=u.y; }
        #pragma unroll
        for(int j=0;j<8;j++){
            float x=v[j]+bs[j];
            if(mode==1)      x += extra[(size_t)((row>>2)&127)*N + n0+tn+j];
            else if(mode==2) x = 0.5f*x*(1.0f+erff(x*0.70710678118654752f));
            else if(mode==3) x += extra[(size_t)row*N + n0+tn+j];
            v[j]=x;
        }
        *(float4*)&C[(size_t)row*N + n0+tn]   = make_float4(v[0],v[1],v[2],v[3]);
        *(float4*)&C[(size_t)row*N + n0+tn+4] = make_float4(v[4],v[5],v[6],v[7]);
        if(Cb){
            __nv_bfloat16 tb8[8];
            #pragma unroll
            for(int j=0;j<8;j++) tb8[j]=__float2bfloat16(v[j]);
            *(uint4*)&Cb[(size_t)row*N + n0+tn] = *(uint4*)tb8;
        }
    }
}

// softmax: reads L fp32, writes P bf16 + inv-sum
__global__ void __launch_bounds__(256) softmax_kernel(
    const float* __restrict__ L, __nv_bfloat16* __restrict__ P, float* __restrict__ inv)
{
    __shared__ float sm[8];
    const size_t row = blockIdx.x;
    const float4* rp = (const float4*)(L + row*SEQ);
    __nv_bfloat162* pp = (__nv_bfloat162*)(P + row*SEQ);
    const int t = threadIdx.x, w = t>>5, lane = t&31;
    float4 x0 = rp[t], x1 = rp[t+256];
    float m = fmaxf(fmaxf(fmaxf(x0.x,x0.y),fmaxf(x0.z,x0.w)),
                    fmaxf(fmaxf(x1.x,x1.y),fmaxf(x1.z,x1.w)));
    m = wmax(m);
    if(lane==0) sm[w]=m;
    __syncthreads();
    m = sm[0];
    #pragma unroll
    for(int q=1;q<8;q++) m = fmaxf(m, sm[q]);
    __syncthreads();
    x0.x=__expf(x0.x-m); x0.y=__expf(x0.y-m); x0.z=__expf(x0.z-m); x0.w=__expf(x0.w-m);
    x1.x=__expf(x1.x-m); x1.y=__expf(x1.y-m); x1.z=__expf(x1.z-m); x1.w=__expf(x1.w-m);
    float s = x0.x+x0.y+x0.z+x0.w + x1.x+x1.y+x1.z+x1.w;
    s = wsum(s);
    if(lane==0) sm[w]=s;
    __nv_bfloat162 p0; p0.x=__float2bfloat16(x0.x); p0.y=__float2bfloat16(x0.y);
    __nv_bfloat162 p1; p1.x=__float2bfloat16(x0.z); p1.y=__float2bfloat16(x0.w);
    __nv_bfloat162 p2; p2.x=__float2bfloat16(x1.x); p2.y=__float2bfloat16(x1.y);
    __nv_bfloat162 p3; p3.x=__float2bfloat16(x1.z); p3.y=__float2bfloat16(x1.w);
    pp[2*t]=p0; pp[2*t+1]=p1; pp[512+2*t]=p2; pp[512+2*t+1]=p3;
    __syncthreads();
    if(t==0){
        float tot = sm[0]+sm[1]+sm[2]+sm[3]+sm[4]+sm[5]+sm[6]+sm[7];
        inv[row] = 1.0f/tot;
    }
}

__global__ void init_slots_kernel(const float* __restrict__ noise,
                                  const float* __restrict__ mu,
                                  const float* __restrict__ sigma,
                                  float* __restrict__ slots)
{
    for(int idx = blockIdx.x*blockDim.x + threadIdx.x; idx < SROWS*DIM;
        idx += gridDim.x*blockDim.x){
        int d = idx & 255, ns = (idx>>8)&3, i = (idx>>10)&127, b = idx>>17;
        slots[idx] = mu[ns*DIM+d] + noise[(size_t)(((i*BSZ+b)*NS+ns))*DIM+d]*sigma[ns*DIM+d];
    }
}

__global__ void norm_rows_kernel(const float* __restrict__ iq,
                                 const float* __restrict__ cls,
                                 float* __restrict__ qn, float* __restrict__ clsn)
{
    const int row = blockIdx.x, lane = threadIdx.x;
    const float* src; float* dst;
    if(row < NI){ src = iq + (size_t)row*DIM; dst = qn + (size_t)row*DIM; }
    else        { src = cls + (size_t)(row-NI)*DIM; dst = clsn + (size_t)(row-NI)*DIM; }
    float4 a0=*(const float4*)(src + (lane<<2));
    float4 a1=*(const float4*)(src + 128 + (lane<<2));
    float ss=a0.x*a0.x+a0.y*a0.y+a0.z*a0.z+a0.w*a0.w
            +a1.x*a1.x+a1.y*a1.y+a1.z*a1.z+a1.w*a1.w;
    ss = wsum(ss);
    float inv = 1.0f/fmaxf(sqrtf(ss), 1e-12f);
    *(float4*)(dst+(lane<<2))     = make_float4(a0.x*inv,a0.y*inv,a0.z*inv,a0.w*inv);
    *(float4*)(dst+128+(lane<<2)) = make_float4(a1.x*inv,a1.y*inv,a1.z*inv,a1.w*inv);
}

__global__ void __launch_bounds__(256) ln_rows_kernel(
    const float* __restrict__ x, const float* __restrict__ g,
    const float* __restrict__ bb, float* __restrict__ y)
{
    const int row = (blockIdx.x<<3) + (threadIdx.x>>5);
    const int lane = threadIdx.x & 31;
    const float* xp = x + (size_t)row*DIM;
    float4 a0=*(const float4*)(xp+(lane<<2));
    float4 a1=*(const float4*)(xp+128+(lane<<2));
    float v[8]={a0.x,a0.y,a0.z,a0.w,a1.x,a1.y,a1.z,a1.w};
    float s1=0.f,s2=0.f;
    #pragma unroll
    for(int q=0;q<8;q++){ s1+=v[q]; s2+=v[q]*v[q]; }
    s1=wsum(s1); s2=wsum(s2);
    float mean=s1*(1.0f/256.0f);
    float rstd=rsqrtf(s2*(1.0f/256.0f)-mean*mean + 1e-5f);
    float4 g0=*(const float4*)(g+(lane<<2)),  g1=*(const float4*)(g+128+(lane<<2));
    float4 b0=*(const float4*)(bb+(lane<<2)), b1=*(const float4*)(bb+128+(lane<<2));
    float* yp = y + (size_t)row*DIM;
    *(float4*)(yp+(lane<<2)) = make_float4(
        (v[0]-mean)*rstd*g0.x+b0.x,(v[1]-mean)*rstd*g0.y+b0.y,
        (v[2]-mean)*rstd*g0.z+b0.z,(v[3]-mean)*rstd*g0.w+b0.w);
    *(float4*)(yp+128+(lane<<2)) = make_float4(
        (v[4]-mean)*rstd*g1.x+b1.x,(v[5]-mean)*rstd*g1.y+b1.y,
        (v[6]-mean)*rstd*g1.z+b1.z,(v[7]-mean)*rstd*g1.w+b1.w);
}

__global__ void __launch_bounds__(128) final_kernel(
    const float* __restrict__ slots, const float* __restrict__ qn,
    const float* __restrict__ clsn, const float* __restrict__ alpha,
    const float* __restrict__ temp, float* __restrict__ out)
{
    __shared__ float sh[4];
    const int i = blockIdx.x, b = blockIdx.y;
    const int w = threadIdx.x>>5, lane = threadIdx.x&31;
    const size_t base = ((size_t)(b*NI + i))*NS;
    const float* qp = qn + (size_t)i*DIM;
    const float* sp = slots + (base+w)*DIM;
    float ss=0.f, dq=0.f;
    #pragma unroll
    for(int q=0;q<8;q++){
        float x=sp[lane+(q<<5)], y=qp[lane+(q<<5)];
        ss+=x*x; dq+=x*y;
    }
    ss=wsum(ss); dq=wsum(dq);
    if(lane==0) sh[w] = dq / fmaxf(sqrtf(ss), 1e-12f);
    __syncthreads();
    float m=fmaxf(fmaxf(sh[0],sh[1]),fmaxf(sh[2],sh[3]));
    float e0=expf(sh[0]-m),e1=expf(sh[1]-m),e2=expf(sh[2]-m),e3=expf(sh[3]-m);
    float inv=1.0f/(e0+e1+e2+e3);
    float a4[4]={e0*inv,e1*inv,e2*inv,e3*inv};
    __syncthreads();
    const int d0=threadIdx.x, d1=threadIdx.x+128;
    float s0=0.f, s1=0.f;
    #pragma unroll
    for(int n=0;n<4;n++){
        const float* rp = slots + (base+n)*DIM;
        s0 += a4[n]*rp[d0]; s1 += a4[n]*rp[d1];
    }
    float pp = wsum(s0*s0 + s1*s1);
    if(lane==0) sh[w]=pp;
    __syncthreads();
    float nrm = fmaxf(sqrtf(sh[0]+sh[1]+sh[2]+sh[3]), 1e-12f);
    float al = *alpha;
    const float* cp = clsn + (size_t)b*DIM;
    float f0 = cp[d0] + al*s0/nrm;
    float f1 = cp[d1] + al*s1/nrm;
    float dot = wsum(f0*qp[d0] + f1*qp[d1]);
    __syncthreads();
    if(lane==0) sh[w]=dot;
    __syncthreads();
    if(threadIdx.x==0)
        out[(size_t)b*NI + i] = (sh[0]+sh[1]+sh[2]+sh[3]) / fmaxf(*temp, 1e-4f);
}

extern "C" void kernel_launch(void* const* d_in, const int* in_sizes, int n_in,
                              void* d_out, int out_size)
{
    const float* tokens=(const float*)d_in[0];
    const float* cls   =(const float*)d_in[1];
    const float* iq    =(const float*)d_in[2];
    const float* noise =(const float*)d_in[3];
    const float* Wk=(const float*)d_in[4],  *bk=(const float*)d_in[5];
    const float* Wv=(const float*)d_in[6],  *bv=(const float*)d_in[7];
    const float* Wqs=(const float*)d_in[8], *bqs=(const float*)d_in[9];
    const float* Wqi=(const float*)d_in[10],*bqi=(const float*)d_in[11];
    const float* ln1g=(const float*)d_in[12],*ln1b=(const float*)d_in[13];
    const float* ln2g=(const float*)d_in[14],*ln2b=(const float*)d_in[15];
    const float* Wf1=(const float*)d_in[16],*bf1=(const float*)d_in[17];
    const float* Wf2=(const float*)d_in[18],*bf2=(const float*)d_in[19];
    const float* mu=(const float*)d_in[20], *sg=(const float*)d_in[21];
    const float* alpha=(const float*)d_in[22],*temp=(const float*)d_in[23];
    float* out=(float*)d_out;

    float *k,*v,*L,*invp,*slots,*qslot,*h,*tb,*qi,*qnp,*clsn;
    __nv_bfloat16 *kbf,*vt,*qbf,*P;
    cudaGetSymbolAddress((void**)&k, g_k);
    cudaGetSymbolAddress((void**)&v, g_v);
    cudaGetSymbolAddress((void**)&kbf, g_kbf);
    cudaGetSymbolAddress((void**)&vt, g_vt);
    cudaGetSymbolAddress((void**)&qbf, g_qbf);
    cudaGetSymbolAddress((void**)&P, g_P);
    cudaGetSymbolAddress((void**)&L, g_L);
    cudaGetSymbolAddress((void**)&invp, g_inv);
    cudaGetSymbolAddress((void**)&slots, g_slots);
    cudaGetSymbolAddress((void**)&qslot, g_qslot);
    cudaGetSymbolAddress((void**)&h, g_h);
    cudaGetSymbolAddress((void**)&tb, g_t);
    cudaGetSymbolAddress((void**)&qi, g_qintent);
    cudaGetSymbolAddress((void**)&qnp, g_qn);
    cudaGetSymbolAddress((void**)&clsn, g_clsn);

    cudaFuncSetAttribute(mma_nt, cudaFuncAttributeMaxDynamicSharedMemorySize, 65536);

    init_slots_kernel<<<4096,256>>>(noise, mu, sg, slots);
    norm_rows_kernel<<<NI+BSZ,32>>>(iq, cls, qnp, clsn);
    sgemm_nn<<<dim3(2,1),  256>>>(iq, Wqi, bqi, nullptr, qi, nullptr, NI, DIM, DIM, 0);
    sgemm_nn<<<dim3(2,512),256>>>(tokens, Wk, bk, nullptr, k, nullptr, BSZ*SEQ, DIM, DIM, 0);
    sgemm_nn<<<dim3(2,512),256>>>(tokens, Wv, bv, nullptr, v, nullptr, BSZ*SEQ, DIM, DIM, 0);
    f2bf_kernel<<<(BSZ*SEQ*DIM/4+255)/256,256>>>(k, kbf, BSZ*SEQ*DIM/4);
    transpose_bf_kernel<<<dim3(SEQ/64, DIM/64, BSZ),256>>>(v, vt);

    for(int it=0; it<3; it++){
        sgemm_nn<<<dim3(2,128),256>>>(slots, Wqs, bqs, qi, qslot, qbf, SROWS, DIM, DIM, 1);
        mma_nt<<<dim3(SEQ/128, RPB/128, BSZ),256,65536>>>(
            qbf, kbf, L, DIM, DIM, SEQ, DIM,
            (size_t)RPB*DIM, (size_t)SEQ*DIM, (size_t)RPB*SEQ, 0, nullptr, nullptr);
        softmax_kernel<<<SROWS,256>>>(L, P, invp);
        mma_nt<<<dim3(DIM/128, RPB/128, BSZ),256,65536>>>(
            P, vt, slots, SEQ, SEQ, DIM, SEQ,
            (size_t)RPB*SEQ, (size_t)DIM*SEQ, (size_t)RPB*DIM, 1, invp, slots);
        ln_rows_kernel<<<SROWS/8,256>>>(slots, ln1g, ln1b, slots);
        ln_rows_kernel<<<SROWS/8,256>>>(slots, ln2g, ln2b, h);
        sgemm_nn<<<dim3(4,128),256>>>(h, Wf1, bf1, nullptr, tb, nullptr, SROWS, 2*DIM, DIM, 2);
        sgemm_nn<<<dim3(2,128),256>>>(tb, Wf2, bf2, slots, slots, nullptr, SROWS, DIM, 2*DIM, 3);
    }
    final_kernel<<<dim3(NI,BSZ),128>>>(slots, qnp, clsn, alpha, temp, out);
}

// round 7
// speedup vs baseline: 7.5006x; 1.3804x over previous
#include <cuda_runtime.h>
#include <cuda_bf16.h>
#include <cstdint>
#include <math.h>

#define NI 128
#define BSZ 32
#define NS 4
#define SEQ 2048
#define DIM 256
#define SROWS (NI*BSZ*NS)
#define RPB (NI*NS)

typedef unsigned long long ull;
typedef __nv_bfloat16 bf16;
typedef __nv_bfloat162 bf162;

__device__ float g_v[BSZ*SEQ*DIM];
__device__ bf16 g_kbf[BSZ*SEQ*DIM];
__device__ bf16 g_vt[BSZ*SEQ*DIM];
__device__ bf16 g_qbf[SROWS*DIM];
__device__ bf16 g_P[(size_t)BSZ*RPB*SEQ];
__device__ float g_L[(size_t)BSZ*RPB*SEQ];
__device__ float g_inv[SROWS];
__device__ float g_slots[SROWS*DIM];
__device__ float g_h[SROWS*DIM];
__device__ float g_qintent[NI*DIM];
__device__ float g_qn[NI*DIM];
__device__ float g_clsn[BSZ*DIM];
// split activations
__device__ bf16 g_tokh[BSZ*SEQ*DIM];
__device__ bf16 g_tokl[BSZ*SEQ*DIM];
__device__ bf16 g_slh[SROWS*DIM];
__device__ bf16 g_sll[SROWS*DIM];
__device__ bf16 g_hh[SROWS*DIM];
__device__ bf16 g_hl[SROWS*DIM];
__device__ bf16 g_tbh[SROWS*2*DIM];
__device__ bf16 g_tbl[SROWS*2*DIM];
// transposed split weights
__device__ bf16 g_WkTh[DIM*DIM];
__device__ bf16 g_WkTl[DIM*DIM];
__device__ bf16 g_WvTh[DIM*DIM];
__device__ bf16 g_WvTl[DIM*DIM];
__device__ bf16 g_WqsTh[DIM*DIM];
__device__ bf16 g_WqsTl[DIM*DIM];
__device__ bf16 g_Wf1Th[2*DIM*DIM];
__device__ bf16 g_Wf1Tl[2*DIM*DIM];
__device__ bf16 g_Wf2Th[2*DIM*DIM];
__device__ bf16 g_Wf2Tl[2*DIM*DIM];

__device__ __forceinline__ ull fma2(ull a, ull b, ull c){
    ull d; asm("fma.rn.f32x2 %0, %1, %2, %3;" : "=l"(d) : "l"(a),"l"(b),"l"(c)); return d;
}
__device__ __forceinline__ ull pack2(float x, float y){
    ull d; asm("mov.b64 %0, {%1, %2};" : "=l"(d) : "f"(x),"f"(y)); return d;
}
__device__ __forceinline__ float2 up2(ull v){
    float2 r; asm("mov.b64 {%0, %1}, %2;" : "=f"(r.x),"=f"(r.y) : "l"(v)); return r;
}
__device__ __forceinline__ float wsum(float v){
    #pragma unroll
    for(int o=16;o>0;o>>=1) v += __shfl_xor_sync(0xffffffffu, v, o);
    return v;
}
__device__ __forceinline__ float wmax(float v){
    #pragma unroll
    for(int o=16;o>0;o>>=1) v = fmaxf(v, __shfl_xor_sync(0xffffffffu, v, o));
    return v;
}
__device__ __forceinline__ uint32_t smem_u32(const void* p){
    uint32_t a; asm("{ .reg .u64 t; cvta.to.shared.u64 t, %1; cvt.u32.u64 %0, t; }" : "=r"(a) : "l"(p));
    return a;
}
#define SW128(o) ((o) ^ (((o)>>3)&0x70))
__device__ __forceinline__ void ldsm4(uint32_t& r0,uint32_t& r1,uint32_t& r2,uint32_t& r3,uint32_t a){
    asm volatile("ldmatrix.sync.aligned.m8n8.x4.shared.b16 {%0,%1,%2,%3}, [%4];"
        : "=r"(r0),"=r"(r1),"=r"(r2),"=r"(r3) : "r"(a) : "memory");
}
__device__ __forceinline__ void mma16816(float* c,uint32_t a0,uint32_t a1,uint32_t a2,uint32_t a3,uint32_t b0,uint32_t b1){
    asm volatile("mma.sync.aligned.m16n8k16.row.col.f32.bf16.bf16.f32 "
        "{%0,%1,%2,%3},{%4,%5,%6,%7},{%8,%9},{%0,%1,%2,%3};"
        : "+f"(c[0]),"+f"(c[1]),"+f"(c[2]),"+f"(c[3])
        : "r"(a0),"r"(a1),"r"(a2),"r"(a3),"r"(b0),"r"(b1));
}
__device__ __forceinline__ void cpa16(uint32_t d, const void* s){
    asm volatile("cp.async.cg.shared.global [%0], [%1], 16;" :: "r"(d), "l"(s));
}
#define CP_COMMIT() asm volatile("cp.async.commit_group;" ::: "memory")
#define CP_WAIT0()  asm volatile("cp.async.wait_group 0;" ::: "memory")
__device__ __forceinline__ float geluf(float x){
    return 0.5f*x*(1.0f+erff(x*0.70710678118654752f));
}

// ============ bf16 NT GEMM (1-pass, attention): C[M,N] = A@B^T ============
// mode 0: C=acc/16 ; mode 1: C=acc*inv[row]+res
__global__ void __launch_bounds__(256) mma_nt(
    const bf16* __restrict__ A, const bf16* __restrict__ B,
    float* __restrict__ C, int lda, int ldb, int ldc, int K,
    size_t sA, size_t sB, size_t sC, int mode,
    const float* __restrict__ inv, const float* __restrict__ res)
{
    extern __shared__ char sm[];
    const uint32_t su = smem_u32(sm);
    const int t = threadIdx.x, wid = t>>5, lane = t&31, z = blockIdx.z;
    const int m0 = blockIdx.y<<7, n0 = blockIdx.x<<7;
    A += (size_t)z*sA + (size_t)m0*lda;
    B += (size_t)z*sB + (size_t)n0*ldb;
    C += (size_t)z*sC;
    const int row_ld = t>>3, col_ld = t&7;
    const uint32_t swoff = SW128((uint32_t)(row_ld*128 + col_ld*16));
    const int nsteps = K>>6;
    float acc[2][8][4];
    #pragma unroll
    for(int i=0;i<2;i++)
        #pragma unroll
        for(int j=0;j<8;j++){ acc[i][j][0]=0.f; acc[i][j][1]=0.f; acc[i][j][2]=0.f; acc[i][j][3]=0.f; }
    {
        const bf16* Ag = A + col_ld*8;
        const bf16* Bg = B + col_ld*8;
        #pragma unroll
        for(int j=0;j<4;j++){
            cpa16(su + swoff + j*4096, Ag + (size_t)(row_ld + j*32)*lda);
            cpa16(su + 16384 + swoff + j*4096, Bg + (size_t)(row_ld + j*32)*ldb);
        }
        CP_COMMIT(); CP_WAIT0();
    }
    __syncthreads();
    const int mw = (wid&3)<<5, nw = (wid>>2)<<6;
    for(int s=0;s<nsteps;s++){
        const uint32_t bufc = su + (uint32_t)((s&1)*32768);
        if(s+1<nsteps){
            const uint32_t bufn = su + (uint32_t)(((s+1)&1)*32768);
            const bf16* Ag = A + (size_t)(s+1)*64 + col_ld*8;
            const bf16* Bg = B + (size_t)(s+1)*64 + col_ld*8;
            #pragma unroll
            for(int j=0;j<4;j++){
                cpa16(bufn + swoff + j*4096, Ag + (size_t)(row_ld + j*32)*lda);
                cpa16(bufn + 16384 + swoff + j*4096, Bg + (size_t)(row_ld + j*32)*ldb);
            }
            CP_COMMIT();
        }
        #pragma unroll
        for(int kk=0;kk<4;kk++){
            const int kb = kk*32 + ((lane>>4)*16);
            uint32_t a[2][4];
            #pragma unroll
            for(int mf=0;mf<2;mf++){
                int row = mw + mf*16 + (lane&15);
                ldsm4(a[mf][0],a[mf][1],a[mf][2],a[mf][3], bufc + SW128((uint32_t)(row*128 + kb)));
            }
            #pragma unroll
            for(int ng=0;ng<4;ng++){
                int row = nw + ng*16 + (lane&15);
                uint32_t b0,b1,b2,b3;
                ldsm4(b0,b1,b2,b3, bufc + 16384 + SW128((uint32_t)(row*128 + kb)));
                #pragma unroll
                for(int mf=0;mf<2;mf++){
                    mma16816(acc[mf][ng*2+0], a[mf][0],a[mf][1],a[mf][2],a[mf][3], b0, b2);
                    mma16816(acc[mf][ng*2+1], a[mf][0],a[mf][1],a[mf][2],a[mf][3], b1, b3);
                }
            }
        }
        if(s+1<nsteps) CP_WAIT0();
        __syncthreads();
    }
    const int gr = lane>>2, gc = (lane&3)<<1;
    #pragma unroll
    for(int mf=0;mf<2;mf++){
        const int r0 = m0 + mw + mf*16 + gr;
        float i0=0.0625f, i1=0.0625f;
        if(mode==1){ i0 = inv[z*RPB + r0]; i1 = inv[z*RPB + r0 + 8]; }
        #pragma unroll
        for(int ng=0;ng<4;ng++){
            #pragma unroll
            for(int h=0;h<2;h++){
                const int col = n0 + nw + ng*16 + h*8 + gc;
                float* cc = acc[mf][ng*2+h];
                if(mode==0){
                    C[(size_t)r0*ldc + col]       = cc[0]*0.0625f;
                    C[(size_t)r0*ldc + col + 1]   = cc[1]*0.0625f;
                    C[(size_t)(r0+8)*ldc + col]   = cc[2]*0.0625f;
                    C[(size_t)(r0+8)*ldc + col+1] = cc[3]*0.0625f;
                } else {
                    const float* rz = res + (size_t)z*sC;
                    C[(size_t)r0*ldc + col]       = cc[0]*i0 + rz[(size_t)r0*ldc + col];
                    C[(size_t)r0*ldc + col + 1]   = cc[1]*i0 + rz[(size_t)r0*ldc + col + 1];
                    C[(size_t)(r0+8)*ldc + col]   = cc[2]*i1 + rz[(size_t)(r0+8)*ldc + col];
                    C[(size_t)(r0+8)*ldc + col+1] = cc[3]*i1 + rz[(size_t)(r0+8)*ldc + col+1];
                }
            }
        }
    }
}

// ============ split-bf16 3-pass NT GEMM: C = Ah@BhT + Ah@BlT + Al@BhT ============
// A [M,K] hi/lo, B [N,K] hi/lo (row-major, ld=K). modes:
// 0: +bias (C fp32 opt, Cbh bf16 opt)  1: +bias+ext[(row>>2)*ldc+col] (Cbh)
// 2: gelu(+bias) -> Cbh/Cbl            3: +bias+ext[row*ldc+col] -> C
__global__ void __launch_bounds__(256) mma_nt3(
    const bf16* __restrict__ Ah, const bf16* __restrict__ Al,
    const bf16* __restrict__ Bh, const bf16* __restrict__ Bl,
    const float* __restrict__ bias, const float* __restrict__ ext,
    float* __restrict__ C, bf16* __restrict__ Cbh, bf16* __restrict__ Cbl,
    int ldc, int K, size_t sA, size_t sC, int mode)
{
    extern __shared__ char sm[];
    const uint32_t su = smem_u32(sm);
    const int t = threadIdx.x, wid = t>>5, lane = t&31, z = blockIdx.z;
    const int m0 = blockIdx.y<<7, n0 = blockIdx.x<<7;
    Ah += (size_t)z*sA + (size_t)m0*K;
    Al += (size_t)z*sA + (size_t)m0*K;
    Bh += (size_t)n0*K;
    Bl += (size_t)n0*K;
    const int row_ld = t>>3, col_ld = t&7;
    const uint32_t swoff = SW128((uint32_t)(row_ld*128 + col_ld*16));
    const int nsteps = K>>6;
    float acc[2][8][4];
    #pragma unroll
    for(int i=0;i<2;i++)
        #pragma unroll
        for(int j=0;j<8;j++){ acc[i][j][0]=0.f; acc[i][j][1]=0.f; acc[i][j][2]=0.f; acc[i][j][3]=0.f; }
    {
        #pragma unroll
        for(int j=0;j<4;j++){
            size_t ro = (size_t)(row_ld + j*32)*K + col_ld*8;
            cpa16(su +         swoff + j*4096, Ah + ro);
            cpa16(su + 16384 + swoff + j*4096, Al + ro);
            cpa16(su + 32768 + swoff + j*4096, Bh + ro);
            cpa16(su + 49152 + swoff + j*4096, Bl + ro);
        }
        CP_COMMIT(); CP_WAIT0();
    }
    __syncthreads();
    const int mw = (wid&3)<<5, nw = (wid>>2)<<6;
    for(int s=0;s<nsteps;s++){
        const uint32_t bufc = su + (uint32_t)((s&1)*65536);
        if(s+1<nsteps){
            const uint32_t bufn = su + (uint32_t)(((s+1)&1)*65536);
            const size_t ko = (size_t)(s+1)*64 + col_ld*8;
            #pragma unroll
            for(int j=0;j<4;j++){
                size_t ro = (size_t)(row_ld + j*32)*K + ko;
                cpa16(bufn +         swoff + j*4096, Ah + ro);
                cpa16(bufn + 16384 + swoff + j*4096, Al + ro);
                cpa16(bufn + 32768 + swoff + j*4096, Bh + ro);
                cpa16(bufn + 49152 + swoff + j*4096, Bl + ro);
            }
            CP_COMMIT();
        }
        #pragma unroll
        for(int kk=0;kk<4;kk++){
            const int kb = kk*32 + ((lane>>4)*16);
            uint32_t ah[2][4], al[2][4];
            #pragma unroll
            for(int mf=0;mf<2;mf++){
                int row = mw + mf*16 + (lane&15);
                uint32_t so = SW128((uint32_t)(row*128 + kb));
                ldsm4(ah[mf][0],ah[mf][1],ah[mf][2],ah[mf][3], bufc + so);
                ldsm4(al[mf][0],al[mf][1],al[mf][2],al[mf][3], bufc + 16384 + so);
            }
            #pragma unroll
            for(int ng=0;ng<4;ng++){
                int row = nw + ng*16 + (lane&15);
                uint32_t so = SW128((uint32_t)(row*128 + kb));
                uint32_t bh0,bh1,bh2,bh3, bl0,bl1,bl2,bl3;
                ldsm4(bh0,bh1,bh2,bh3, bufc + 32768 + so);
                ldsm4(bl0,bl1,bl2,bl3, bufc + 49152 + so);
                #pragma unroll
                for(int mf=0;mf<2;mf++){
                    mma16816(acc[mf][ng*2+0], ah[mf][0],ah[mf][1],ah[mf][2],ah[mf][3], bh0, bh2);
                    mma16816(acc[mf][ng*2+1], ah[mf][0],ah[mf][1],ah[mf][2],ah[mf][3], bh1, bh3);
                    mma16816(acc[mf][ng*2+0], ah[mf][0],ah[mf][1],ah[mf][2],ah[mf][3], bl0, bl2);
                    mma16816(acc[mf][ng*2+1], ah[mf][0],ah[mf][1],ah[mf][2],ah[mf][3], bl1, bl3);
                    mma16816(acc[mf][ng*2+0], al[mf][0],al[mf][1],al[mf][2],al[mf][3], bh0, bh2);
                    mma16816(acc[mf][ng*2+1], al[mf][0],al[mf][1],al[mf][2],al[mf][3], bh1, bh3);
                }
            }
        }
        if(s+1<nsteps) CP_WAIT0();
        __syncthreads();
    }
    if(C)   C   += (size_t)z*sC;
    if(Cbh) Cbh += (size_t)z*sC;
    if(Cbl) Cbl += (size_t)z*sC;
    const float* extz = (mode==3 && ext) ? ext + (size_t)z*sC : ext;
    const int gr = lane>>2, gc = (lane&3)<<1;
    #pragma unroll
    for(int mf=0;mf<2;mf++){
        const int r0 = m0 + mw + mf*16 + gr, r1 = r0 + 8;
        #pragma unroll
        for(int ng=0;ng<4;ng++){
            #pragma unroll
            for(int h=0;h<2;h++){
                const int col = n0 + nw + ng*16 + h*8 + gc;
                float* cc = acc[mf][ng*2+h];
                float b0 = bias ? bias[col] : 0.f, b1 = bias ? bias[col+1] : 0.f;
                float x00=cc[0]+b0, x01=cc[1]+b1, x10=cc[2]+b0, x11=cc[3]+b1;
                if(mode==1){
                    x00 += extz[(size_t)(r0>>2)*ldc + col];
                    x01 += extz[(size_t)(r0>>2)*ldc + col + 1];
                    x10 += extz[(size_t)(r1>>2)*ldc + col];
                    x11 += extz[(size_t)(r1>>2)*ldc + col + 1];
                } else if(mode==2){
                    x00=geluf(x00); x01=geluf(x01); x10=geluf(x10); x11=geluf(x11);
                } else if(mode==3){
                    x00 += extz[(size_t)r0*ldc + col];
                    x01 += extz[(size_t)r0*ldc + col + 1];
                    x10 += extz[(size_t)r1*ldc + col];
                    x11 += extz[(size_t)r1*ldc + col + 1];
                }
                if(C){
                    C[(size_t)r0*ldc + col]   = x00; C[(size_t)r0*ldc + col+1] = x01;
                    C[(size_t)r1*ldc + col]   = x10; C[(size_t)r1*ldc + col+1] = x11;
                }
                if(Cbh){
                    bf162 p0; p0.x=__float2bfloat16(x00); p0.y=__float2bfloat16(x01);
                    bf162 p1; p1.x=__float2bfloat16(x10); p1.y=__float2bfloat16(x11);
                    *(bf162*)&Cbh[(size_t)r0*ldc + col] = p0;
                    *(bf162*)&Cbh[(size_t)r1*ldc + col] = p1;
                    if(Cbl){
                        bf162 q0, q1;
                        q0.x=__float2bfloat16(x00-__bfloat162float(p0.x));
                        q0.y=__float2bfloat16(x01-__bfloat162float(p0.y));
                        q1.x=__float2bfloat16(x10-__bfloat162float(p1.x));
                        q1.y=__float2bfloat16(x11-__bfloat162float(p1.y));
                        *(bf162*)&Cbl[(size_t)r0*ldc + col] = q0;
                        *(bf162*)&Cbl[(size_t)r1*ldc + col] = q1;
                    }
                }
            }
        }
    }
}

// ================= fp32 -> bf16 hi/lo split =================
__global__ void __launch_bounds__(256) split_bf16_kernel(
    const float* __restrict__ x, bf16* __restrict__ hi, bf16* __restrict__ lo, int n4)
{
    int i = blockIdx.x*blockDim.x + threadIdx.x;
    if (i >= n4) return;
    float4 v = ((const float4*)x)[i];
    bf16 h0=__float2bfloat16(v.x), h1=__float2bfloat16(v.y);
    bf16 h2=__float2bfloat16(v.z), h3=__float2bfloat16(v.w);
    bf162 a; a.x=h0; a.y=h1;
    bf162 b; b.x=h2; b.y=h3;
    bf162 c; c.x=__float2bfloat16(v.x-__bfloat162float(h0)); c.y=__float2bfloat16(v.y-__bfloat162float(h1));
    bf162 d; d.x=__float2bfloat16(v.z-__bfloat162float(h2)); d.y=__float2bfloat16(v.w-__bfloat162float(h3));
    ((bf162*)hi)[2*i]   = a;
    ((bf162*)hi)[2*i+1] = b;
    ((bf162*)lo)[2*i]   = c;
    ((bf162*)lo)[2*i+1] = d;
}

// ===== weight transpose + split: W[K][N] fp32 -> T[N][K] bf16 hi/lo; grid (K/32, N/32) =====
__global__ void __launch_bounds__(256) txsplit_kernel(
    const float* __restrict__ W, bf16* __restrict__ Th, bf16* __restrict__ Tl, int K, int N)
{
    __shared__ float tl[32][33];
    const int k0 = blockIdx.x<<5, n0 = blockIdx.y<<5;
    const int t = threadIdx.x, r = t>>5, c = t&31;
    #pragma unroll
    for(int j=0;j<4;j++)
        tl[r+j*8][c] = W[(size_t)(k0+r+j*8)*N + n0 + c];
    __syncthreads();
    #pragma unroll
    for(int j=0;j<4;j++){
        float x = tl[c][r+j*8];
        bf16 h = __float2bfloat16(x);
        Th[(size_t)(n0+r+j*8)*K + k0 + c] = h;
        Tl[(size_t)(n0+r+j*8)*K + k0 + c] = __float2bfloat16(x-__bfloat162float(h));
    }
}

// ======= transpose+convert: v[b][s][d] fp32 -> vt[b][d][s] bf16 =======
__global__ void __launch_bounds__(256) transpose_bf_kernel(
    const float* __restrict__ v, bf16* __restrict__ vt)
{
    __shared__ bf16 tl[64][65];
    const int s0 = blockIdx.x<<6, d0 = blockIdx.y<<6, z = blockIdx.z;
    const float* vz = v + (size_t)z*SEQ*DIM;
    bf16* vtz = vt + (size_t)z*SEQ*DIM;
    const int t = threadIdx.x;
    #pragma unroll
    for(int j=0;j<16;j++){
        int idx = j*256 + t, r = idx>>6, c = idx&63;
        tl[r][c] = __float2bfloat16(vz[(size_t)(s0+r)*DIM + d0 + c]);
    }
    __syncthreads();
    #pragma unroll
    for(int j=0;j<16;j++){
        int idx = j*256 + t, r = idx>>6, c = idx&63;
        vtz[(size_t)(d0+r)*SEQ + s0 + c] = tl[c][r];
    }
}

// ================= packed-f32x2 NN GEMM (kept for tiny Wqi) =================
__global__ void __launch_bounds__(256) sgemm_nn(
    const float* __restrict__ A, const float* __restrict__ B,
    const float* __restrict__ bias, float* __restrict__ C,
    int M, int N, int K)
{
    __shared__ float As[8][132];
    __shared__ float Bs[8][128];
    const int t = threadIdx.x;
    const int m0 = blockIdx.y<<7, n0 = blockIdx.x<<7;
    const int arow = t>>1, acol = (t&1)<<2;
    const int brow = t>>5, bcol = (t&31)<<2;
    const float* Ap = A + (size_t)(m0+arow)*K + acol;
    const float* Bp = B + (size_t)brow*N + n0 + bcol;
    float4 ar = *(const float4*)Ap;
    float4 br = *(const float4*)Bp;
    ull c2[8][4];
    #pragma unroll
    for(int i=0;i<8;i++){ c2[i][0]=0; c2[i][1]=0; c2[i][2]=0; c2[i][3]=0; }
    const int tm=(t>>4)<<3, tn=(t&15)<<3;
    const int nt = K>>3;
    for(int kt=0;kt<nt;kt++){
        As[acol+0][arow]=ar.x; As[acol+1][arow]=ar.y;
        As[acol+2][arow]=ar.z; As[acol+3][arow]=ar.w;
        *(float4*)&Bs[brow][bcol]=br;
        __syncthreads();
        if(kt+1<nt){
            ar = *(const float4*)(Ap + ((kt+1)<<3));
            br = *(const float4*)(Bp + (size_t)((kt+1)<<3)*N);
        }
        #pragma unroll
        for(int kk=0;kk<8;kk++){
            float4 a0=*(const float4*)&As[kk][tm];
            float4 a1=*(const float4*)&As[kk][tm+4];
            ulonglong2 w0=*(const ulonglong2*)&Bs[kk][tn];
            ulonglong2 w1=*(const ulonglong2*)&Bs[kk][tn+4];
            float a[8]={a0.x,a0.y,a0.z,a0.w,a1.x,a1.y,a1.z,a1.w};
            #pragma unroll
            for(int i=0;i<8;i++){
                ull ap = pack2(a[i],a[i]);
                c2[i][0]=fma2(ap,w0.x,c2[i][0]);
                c2[i][1]=fma2(ap,w0.y,c2[i][1]);
                c2[i][2]=fma2(ap,w1.x,c2[i][2]);
                c2[i][3]=fma2(ap,w1.y,c2[i][3]);
            }
        }
        __syncthreads();
    }
    #pragma unroll
    for(int i=0;i<8;i++){
        const int row=m0+tm+i;
        float v[8];
        #pragma unroll
        for(int p=0;p<4;p++){ float2 u=up2(c2[i][p]); v[2*p]=u.x; v[2*p+1]=u.y; }
        #pragma unroll
        for(int j=0;j<8;j++) v[j] += bias[n0+tn+j];
        *(float4*)&C[(size_t)row*N + n0+tn]   = make_float4(v[0],v[1],v[2],v[3]);
        *(float4*)&C[(size_t)row*N + n0+tn+4] = make_float4(v[4],v[5],v[6],v[7]);
    }
}

__global__ void __launch_bounds__(256) softmax_kernel(
    const float* __restrict__ L, bf16* __restrict__ P, float* __restrict__ inv)
{
    __shared__ float sm[8];
    const size_t row = blockIdx.x;
    const float4* rp = (const float4*)(L + row*SEQ);
    bf162* pp = (bf162*)(P + row*SEQ);
    const int t = threadIdx.x, w = t>>5, lane = t&31;
    float4 x0 = rp[t], x1 = rp[t+256];
    float m = fmaxf(fmaxf(fmaxf(x0.x,x0.y),fmaxf(x0.z,x0.w)),
                    fmaxf(fmaxf(x1.x,x1.y),fmaxf(x1.z,x1.w)));
    m = wmax(m);
    if(lane==0) sm[w]=m;
    __syncthreads();
    m = sm[0];
    #pragma unroll
    for(int q=1;q<8;q++) m = fmaxf(m, sm[q]);
    __syncthreads();
    x0.x=__expf(x0.x-m); x0.y=__expf(x0.y-m); x0.z=__expf(x0.z-m); x0.w=__expf(x0.w-m);
    x1.x=__expf(x1.x-m); x1.y=__expf(x1.y-m); x1.z=__expf(x1.z-m); x1.w=__expf(x1.w-m);
    float s = x0.x+x0.y+x0.z+x0.w + x1.x+x1.y+x1.z+x1.w;
    s = wsum(s);
    if(lane==0) sm[w]=s;
    bf162 p0; p0.x=__float2bfloat16(x0.x); p0.y=__float2bfloat16(x0.y);
    bf162 p1; p1.x=__float2bfloat16(x0.z); p1.y=__float2bfloat16(x0.w);
    bf162 p2; p2.x=__float2bfloat16(x1.x); p2.y=__float2bfloat16(x1.y);
    bf162 p3; p3.x=__float2bfloat16(x1.z); p3.y=__float2bfloat16(x1.w);
    pp[2*t]=p0; pp[2*t+1]=p1; pp[512+2*t]=p2; pp[512+2*t+1]=p3;
    __syncthreads();
    if(t==0){
        float tot = sm[0]+sm[1]+sm[2]+sm[3]+sm[4]+sm[5]+sm[6]+sm[7];
        inv[row] = 1.0f/tot;
    }
}

__global__ void init_slots_kernel(const float* __restrict__ noise,
                                  const float* __restrict__ mu,
                                  const float* __restrict__ sigma,
                                  float* __restrict__ slots)
{
    for(int idx = blockIdx.x*blockDim.x + threadIdx.x; idx < SROWS*DIM;
        idx += gridDim.x*blockDim.x){
        int d = idx & 255, ns = (idx>>8)&3, i = (idx>>10)&127, b = idx>>17;
        slots[idx] = mu[ns*DIM+d] + noise[(size_t)(((i*BSZ+b)*NS+ns))*DIM+d]*sigma[ns*DIM+d];
    }
}

__global__ void norm_rows_kernel(const float* __restrict__ iq,
                                 const float* __restrict__ cls,
                                 float* __restrict__ qn, float* __restrict__ clsn)
{
    const int row = blockIdx.x, lane = threadIdx.x;
    const float* src; float* dst;
    if(row < NI){ src = iq + (size_t)row*DIM; dst = qn + (size_t)row*DIM; }
    else        { src = cls + (size_t)(row-NI)*DIM; dst = clsn + (size_t)(row-NI)*DIM; }
    float4 a0=*(const float4*)(src + (lane<<2));
    float4 a1=*(const float4*)(src + 128 + (lane<<2));
    float ss=a0.x*a0.x+a0.y*a0.y+a0.z*a0.z+a0.w*a0.w
            +a1.x*a1.x+a1.y*a1.y+a1.z*a1.z+a1.w*a1.w;
    ss = wsum(ss);
    float inv = 1.0f/fmaxf(sqrtf(ss), 1e-12f);
    *(float4*)(dst+(lane<<2))     = make_float4(a0.x*inv,a0.y*inv,a0.z*inv,a0.w*inv);
    *(float4*)(dst+128+(lane<<2)) = make_float4(a1.x*inv,a1.y*inv,a1.z*inv,a1.w*inv);
}

__global__ void __launch_bounds__(256) ln_rows_kernel(
    const float* __restrict__ x, const float* __restrict__ g,
    const float* __restrict__ bb, float* __restrict__ y)
{
    const int row = (blockIdx.x<<3) + (threadIdx.x>>5);
    const int lane = threadIdx.x & 31;
    const float* xp = x + (size_t)row*DIM;
    float4 a0=*(const float4*)(xp+(lane<<2));
    float4 a1=*(const float4*)(xp+128+(lane<<2));
    float v[8]={a0.x,a0.y,a0.z,a0.w,a1.x,a1.y,a1.z,a1.w};
    float s1=0.f,s2=0.f;
    #pragma unroll
    for(int q=0;q<8;q++){ s1+=v[q]; s2+=v[q]*v[q]; }
    s1=wsum(s1); s2=wsum(s2);
    float mean=s1*(1.0f/256.0f);
    float rstd=rsqrtf(s2*(1.0f/256.0f)-mean*mean + 1e-5f);
    float4 g0=*(const float4*)(g+(lane<<2)),  g1=*(const float4*)(g+128+(lane<<2));
    float4 b0=*(const float4*)(bb+(lane<<2)), b1=*(const float4*)(bb+128+(lane<<2));
    float* yp = y + (size_t)row*DIM;
    *(float4*)(yp+(lane<<2)) = make_float4(
        (v[0]-mean)*rstd*g0.x+b0.x,(v[1]-mean)*rstd*g0.y+b0.y,
        (v[2]-mean)*rstd*g0.z+b0.z,(v[3]-mean)*rstd*g0.w+b0.w);
    *(float4*)(yp+128+(lane<<2)) = make_float4(
        (v[4]-mean)*rstd*g1.x+b1.x,(v[5]-mean)*rstd*g1.y+b1.y,
        (v[6]-mean)*rstd*g1.z+b1.z,(v[7]-mean)*rstd*g1.w+b1.w);
}

__global__ void __launch_bounds__(128) final_kernel(
    const float* __restrict__ slots, const float* __restrict__ qn,
    const float* __restrict__ clsn, const float* __restrict__ alpha,
    const float* __restrict__ temp, float* __restrict__ out)
{
    __shared__ float sh[4];
    const int i = blockIdx.x, b = blockIdx.y;
    const int w = threadIdx.x>>5, lane = threadIdx.x&31;
    const size_t base = ((size_t)(b*NI + i))*NS;
    const float* qp = qn + (size_t)i*DIM;
    const float* sp = slots + (base+w)*DIM;
    float ss=0.f, dq=0.f;
    #pragma unroll
    for(int q=0;q<8;q++){
        float x=sp[lane+(q<<5)], y=qp[lane+(q<<5)];
        ss+=x*x; dq+=x*y;
    }
    ss=wsum(ss); dq=wsum(dq);
    if(lane==0) sh[w] = dq / fmaxf(sqrtf(ss), 1e-12f);
    __syncthreads();
    float m=fmaxf(fmaxf(sh[0],sh[1]),fmaxf(sh[2],sh[3]));
    float e0=expf(sh[0]-m),e1=expf(sh[1]-m),e2=expf(sh[2]-m),e3=expf(sh[3]-m);
    float inv=1.0f/(e0+e1+e2+e3);
    float a4[4]={e0*inv,e1*inv,e2*inv,e3*inv};
    __syncthreads();
    const int d0=threadIdx.x, d1=threadIdx.x+128;
    float s0=0.f, s1=0.f;
    #pragma unroll
    for(int n=0;n<4;n++){
        const float* rp = slots + (base+n)*DIM;
        s0 += a4[n]*rp[d0]; s1 += a4[n]*rp[d1];
    }
    float pp = wsum(s0*s0 + s1*s1);
    if(lane==0) sh[w]=pp;
    __syncthreads();
    float nrm = fmaxf(sqrtf(sh[0]+sh[1]+sh[2]+sh[3]), 1e-12f);
    float al = *alpha;
    const float* cp = clsn + (size_t)b*DIM;
    float f0 = cp[d0] + al*s0/nrm;
    float f1 = cp[d1] + al*s1/nrm;
    float dot = wsum(f0*qp[d0] + f1*qp[d1]);
    __syncthreads();
    if(lane==0) sh[w]=dot;
    __syncthreads();
    if(threadIdx.x==0)
        out[(size_t)b*NI + i] = (sh[0]+sh[1]+sh[2]+sh[3]) / fmaxf(*temp, 1e-4f);
}

#define GSYM(p, s) cudaGetSymbolAddress((void**)&p, s)

extern "C" void kernel_launch(void* const* d_in, const int* in_sizes, int n_in,
                              void* d_out, int out_size)
{
    const float* tokens=(const float*)d_in[0];
    const float* cls   =(const float*)d_in[1];
    const float* iq    =(const float*)d_in[2];
    const float* noise =(const float*)d_in[3];
    const float* Wk=(const float*)d_in[4],  *bk=(const float*)d_in[5];
    const float* Wv=(const float*)d_in[6],  *bv=(const float*)d_in[7];
    const float* Wqs=(const float*)d_in[8], *bqs=(const float*)d_in[9];
    const float* Wqi=(const float*)d_in[10],*bqi=(const float*)d_in[11];
    const float* ln1g=(const float*)d_in[12],*ln1b=(const float*)d_in[13];
    const float* ln2g=(const float*)d_in[14],*ln2b=(const float*)d_in[15];
    const float* Wf1=(const float*)d_in[16],*bf1=(const float*)d_in[17];
    const float* Wf2=(const float*)d_in[18],*bf2=(const float*)d_in[19];
    const float* mu=(const float*)d_in[20], *sg=(const float*)d_in[21];
    const float* alpha=(const float*)d_in[22],*temp=(const float*)d_in[23];
    float* out=(float*)d_out;

    float *v,*L,*invp,*slots,*h,*qi,*qnp,*clsn;
    bf16 *kbf,*vt,*qbf,*P,*tokh,*tokl,*slh,*sll,*hh,*hl,*tbh,*tbl;
    bf16 *WkTh,*WkTl,*WvTh,*WvTl,*WqsTh,*WqsTl,*Wf1Th,*Wf1Tl,*Wf2Th,*Wf2Tl;
    GSYM(v,g_v); GSYM(L,g_L); GSYM(invp,g_inv); GSYM(slots,g_slots);
    GSYM(h,g_h); GSYM(qi,g_qintent); GSYM(qnp,g_qn); GSYM(clsn,g_clsn);
    GSYM(kbf,g_kbf); GSYM(vt,g_vt); GSYM(qbf,g_qbf); GSYM(P,g_P);
    GSYM(tokh,g_tokh); GSYM(tokl,g_tokl); GSYM(slh,g_slh); GSYM(sll,g_sll);
    GSYM(hh,g_hh); GSYM(hl,g_hl); GSYM(tbh,g_tbh); GSYM(tbl,g_tbl);
    GSYM(WkTh,g_WkTh); GSYM(WkTl,g_WkTl); GSYM(WvTh,g_WvTh); GSYM(WvTl,g_WvTl);
    GSYM(WqsTh,g_WqsTh); GSYM(WqsTl,g_WqsTl);
    GSYM(Wf1Th,g_Wf1Th); GSYM(Wf1Tl,g_Wf1Tl); GSYM(Wf2Th,g_Wf2Th); GSYM(Wf2Tl,g_Wf2Tl);

    cudaFuncSetAttribute(mma_nt,  cudaFuncAttributeMaxDynamicSharedMemorySize, 65536);
    cudaFuncSetAttribute(mma_nt3, cudaFuncAttributeMaxDynamicSharedMemorySize, 131072);

    init_slots_kernel<<<4096,256>>>(noise, mu, sg, slots);
    norm_rows_kernel<<<NI+BSZ,32>>>(iq, cls, qnp, clsn);
    sgemm_nn<<<dim3(2,1),256>>>(iq, Wqi, bqi, qi, NI, DIM, DIM);
    split_bf16_kernel<<<(BSZ*SEQ*DIM/4+255)/256,256>>>(tokens, tokh, tokl, BSZ*SEQ*DIM/4);
    txsplit_kernel<<<dim3(DIM/32,DIM/32),256>>>(Wk, WkTh, WkTl, DIM, DIM);
    txsplit_kernel<<<dim3(DIM/32,DIM/32),256>>>(Wv, WvTh, WvTl, DIM, DIM);
    txsplit_kernel<<<dim3(DIM/32,DIM/32),256>>>(Wqs, WqsTh, WqsTl, DIM, DIM);
    txsplit_kernel<<<dim3(DIM/32,2*DIM/32),256>>>(Wf1, Wf1Th, Wf1Tl, DIM, 2*DIM);
    txsplit_kernel<<<dim3(2*DIM/32,DIM/32),256>>>(Wf2, Wf2Th, Wf2Tl, 2*DIM, DIM);
    // k projection: write bf16 kbf directly
    mma_nt3<<<dim3(2,512,1),256,131072>>>(tokh, tokl, WkTh, WkTl, bk, nullptr,
                                          nullptr, kbf, nullptr, DIM, DIM, 0, 0, 0);
    // v projection: fp32 out
    mma_nt3<<<dim3(2,512,1),256,131072>>>(tokh, tokl, WvTh, WvTl, bv, nullptr,
                                          v, nullptr, nullptr, DIM, DIM, 0, 0, 0);
    transpose_bf_kernel<<<dim3(SEQ/64, DIM/64, BSZ),256>>>(v, vt);

    for(int it=0; it<3; it++){
        split_bf16_kernel<<<(SROWS*DIM/4+255)/256,256>>>(slots, slh, sll, SROWS*DIM/4);
        mma_nt3<<<dim3(2,4,BSZ),256,131072>>>(slh, sll, WqsTh, WqsTl, bqs, qi,
                                              nullptr, qbf, nullptr, DIM, DIM,
                                              (size_t)RPB*DIM, (size_t)RPB*DIM, 1);
        mma_nt<<<dim3(SEQ/128, RPB/128, BSZ),256,65536>>>(
            qbf, kbf, L, DIM, DIM, SEQ, DIM,
            (size_t)RPB*DIM, (size_t)SEQ*DIM, (size_t)RPB*SEQ, 0, nullptr, nullptr);
        softmax_kernel<<<SROWS,256>>>(L, P, invp);
        mma_nt<<<dim3(DIM/128, RPB/128, BSZ),256,65536>>>(
            P, vt, slots, SEQ, SEQ, DIM, SEQ,
            (size_t)RPB*SEQ, (size_t)DIM*SEQ, (size_t)RPB*DIM, 1, invp, slots);
        ln_rows_kernel<<<SROWS/8,256>>>(slots, ln1g, ln1b, slots);
        ln_rows_kernel<<<SROWS/8,256>>>(slots, ln2g, ln2b, h);
        split_bf16_kernel<<<(SROWS*DIM/4+255)/256,256>>>(h, hh, hl, SROWS*DIM/4);
        mma_nt3<<<dim3(4,128,1),256,131072>>>(hh, hl, Wf1Th, Wf1Tl, bf1, nullptr,
                                              nullptr, tbh, tbl, 2*DIM, DIM, 0, 0, 2);
        mma_nt3<<<dim3(2,128,1),256,131072>>>(tbh, tbl, Wf2Th, Wf2Tl, bf2, slots,
                                              slots, nullptr, nullptr, DIM, 2*DIM, 0, 0, 3);
    }
    final_kernel<<<dim3(NI,BSZ),128>>>(slots, qnp, clsn, alpha, temp, out);
}

// round 8
// speedup vs baseline: 8.2927x; 1.1056x over previous
#include <cuda_runtime.h>
#include <cuda_bf16.h>
#include <cstdint>
#include <math.h>

#define NI 128
#define BSZ 32
#define NS 4
#define SEQ 2048
#define DIM 256
#define SROWS (NI*BSZ*NS)
#define RPB (NI*NS)

typedef unsigned long long ull;
typedef __nv_bfloat16 bf16;
typedef __nv_bfloat162 bf162;

__device__ float g_v[BSZ*SEQ*DIM];
__device__ bf16 g_kbf[BSZ*SEQ*DIM];
__device__ bf16 g_vt[BSZ*SEQ*DIM];
__device__ bf16 g_qbf[SROWS*DIM];
__device__ bf16 g_P[(size_t)BSZ*RPB*SEQ];
__device__ float g_psum[SROWS];
__device__ float g_slots[SROWS*DIM];
__device__ float g_h[SROWS*DIM];
__device__ float g_qintent[NI*DIM];
__device__ float g_qn[NI*DIM];
__device__ float g_clsn[BSZ*DIM];
__device__ bf16 g_tokh[BSZ*SEQ*DIM];
__device__ bf16 g_tokl[BSZ*SEQ*DIM];
__device__ bf16 g_slh[SROWS*DIM];
__device__ bf16 g_sll[SROWS*DIM];
__device__ bf16 g_hh[SROWS*DIM];
__device__ bf16 g_hl[SROWS*DIM];
__device__ bf16 g_tbh[SROWS*2*DIM];
__device__ bf16 g_tbl[SROWS*2*DIM];
__device__ bf16 g_WkTh[DIM*DIM];
__device__ bf16 g_WkTl[DIM*DIM];
__device__ bf16 g_WvTh[DIM*DIM];
__device__ bf16 g_WvTl[DIM*DIM];
__device__ bf16 g_WqsTh[DIM*DIM];
__device__ bf16 g_WqsTl[DIM*DIM];
__device__ bf16 g_Wf1Th[2*DIM*DIM];
__device__ bf16 g_Wf1Tl[2*DIM*DIM];
__device__ bf16 g_Wf2Th[2*DIM*DIM];
__device__ bf16 g_Wf2Tl[2*DIM*DIM];

__device__ __forceinline__ ull fma2(ull a, ull b, ull c){
    ull d; asm("fma.rn.f32x2 %0, %1, %2, %3;" : "=l"(d) : "l"(a),"l"(b),"l"(c)); return d;
}
__device__ __forceinline__ ull pack2(float x, float y){
    ull d; asm("mov.b64 %0, {%1, %2};" : "=l"(d) : "f"(x),"f"(y)); return d;
}
__device__ __forceinline__ float2 up2(ull v){
    float2 r; asm("mov.b64 {%0, %1}, %2;" : "=f"(r.x),"=f"(r.y) : "l"(v)); return r;
}
__device__ __forceinline__ float wsum(float v){
    #pragma unroll
    for(int o=16;o>0;o>>=1) v += __shfl_xor_sync(0xffffffffu, v, o);
    return v;
}
__device__ __forceinline__ uint32_t smem_u32(const void* p){
    uint32_t a; asm("{ .reg .u64 t; cvta.to.shared.u64 t, %1; cvt.u32.u64 %0, t; }" : "=r"(a) : "l"(p));
    return a;
}
#define SW128(o) ((o) ^ (((o)>>3)&0x70))
__device__ __forceinline__ void ldsm4(uint32_t& r0,uint32_t& r1,uint32_t& r2,uint32_t& r3,uint32_t a){
    asm volatile("ldmatrix.sync.aligned.m8n8.x4.shared.b16 {%0,%1,%2,%3}, [%4];"
        : "=r"(r0),"=r"(r1),"=r"(r2),"=r"(r3) : "r"(a) : "memory");
}
__device__ __forceinline__ void mma16816(float* c,uint32_t a0,uint32_t a1,uint32_t a2,uint32_t a3,uint32_t b0,uint32_t b1){
    asm volatile("mma.sync.aligned.m16n8k16.row.col.f32.bf16.bf16.f32 "
        "{%0,%1,%2,%3},{%4,%5,%6,%7},{%8,%9},{%0,%1,%2,%3};"
        : "+f"(c[0]),"+f"(c[1]),"+f"(c[2]),"+f"(c[3])
        : "r"(a0),"r"(a1),"r"(a2),"r"(a3),"r"(b0),"r"(b1));
}
__device__ __forceinline__ void cpa16(uint32_t d, const void* s){
    asm volatile("cp.async.cg.shared.global [%0], [%1], 16;" :: "r"(d), "l"(s));
}
#define CP_COMMIT() asm volatile("cp.async.commit_group;" ::: "memory")
#define CP_WAIT0()  asm volatile("cp.async.wait_group 0;" ::: "memory")
__device__ __forceinline__ float geluf(float x){
    return 0.5f*x*(1.0f+erff(x*0.70710678118654752f));
}

__global__ void zero_psum_kernel(float* __restrict__ p){
    p[blockIdx.x*256 + threadIdx.x] = 0.f;
}

// ============ bf16 NT GEMM (attention) ============
// mode 0 (logits+softmax): Pb[row][col] = exp(acc/16) bf16; atomicAdd psum[row]
// mode 1 (upd): C = acc/psum[row] + res
__global__ void __launch_bounds__(256) mma_nt(
    const bf16* __restrict__ A, const bf16* __restrict__ B,
    bf16* __restrict__ Pb, float* __restrict__ psum, float* __restrict__ C,
    int lda, int ldb, int ldc, int K,
    size_t sA, size_t sB, size_t sC, int mode, const float* __restrict__ res)
{
    extern __shared__ char sm[];
    const uint32_t su = smem_u32(sm);
    const int t = threadIdx.x, wid = t>>5, lane = t&31, z = blockIdx.z;
    const int m0 = blockIdx.y<<7, n0 = blockIdx.x<<7;
    A += (size_t)z*sA + (size_t)m0*lda;
    B += (size_t)z*sB + (size_t)n0*ldb;
    const int row_ld = t>>3, col_ld = t&7;
    const uint32_t swoff = SW128((uint32_t)(row_ld*128 + col_ld*16));
    const int nsteps = K>>6;
    float acc[2][8][4];
    #pragma unroll
    for(int i=0;i<2;i++)
        #pragma unroll
        for(int j=0;j<8;j++){ acc[i][j][0]=0.f; acc[i][j][1]=0.f; acc[i][j][2]=0.f; acc[i][j][3]=0.f; }
    {
        const bf16* Ag = A + col_ld*8;
        const bf16* Bg = B + col_ld*8;
        #pragma unroll
        for(int j=0;j<4;j++){
            cpa16(su + swoff + j*4096, Ag + (size_t)(row_ld + j*32)*lda);
            cpa16(su + 16384 + swoff + j*4096, Bg + (size_t)(row_ld + j*32)*ldb);
        }
        CP_COMMIT(); CP_WAIT0();
    }
    __syncthreads();
    const int mw = (wid&3)<<5, nw = (wid>>2)<<6;
    for(int s=0;s<nsteps;s++){
        const uint32_t bufc = su + (uint32_t)((s&1)*32768);
        if(s+1<nsteps){
            const uint32_t bufn = su + (uint32_t)(((s+1)&1)*32768);
            const bf16* Ag = A + (size_t)(s+1)*64 + col_ld*8;
            const bf16* Bg = B + (size_t)(s+1)*64 + col_ld*8;
            #pragma unroll
            for(int j=0;j<4;j++){
                cpa16(bufn + swoff + j*4096, Ag + (size_t)(row_ld + j*32)*lda);
                cpa16(bufn + 16384 + swoff + j*4096, Bg + (size_t)(row_ld + j*32)*ldb);
            }
            CP_COMMIT();
        }
        #pragma unroll
        for(int kk=0;kk<4;kk++){
            const int kb = kk*32 + ((lane>>4)*16);
            uint32_t a[2][4];
            #pragma unroll
            for(int mf=0;mf<2;mf++){
                int row = mw + mf*16 + (lane&15);
                ldsm4(a[mf][0],a[mf][1],a[mf][2],a[mf][3], bufc + SW128((uint32_t)(row*128 + kb)));
            }
            #pragma unroll
            for(int ng=0;ng<4;ng++){
                int row = nw + ng*16 + (lane&15);
                uint32_t b0,b1,b2,b3;
                ldsm4(b0,b1,b2,b3, bufc + 16384 + SW128((uint32_t)(row*128 + kb)));
                #pragma unroll
                for(int mf=0;mf<2;mf++){
                    mma16816(acc[mf][ng*2+0], a[mf][0],a[mf][1],a[mf][2],a[mf][3], b0, b2);
                    mma16816(acc[mf][ng*2+1], a[mf][0],a[mf][1],a[mf][2],a[mf][3], b1, b3);
                }
            }
        }
        if(s+1<nsteps) CP_WAIT0();
        __syncthreads();
    }
    const int gr = lane>>2, gc = (lane&3)<<1;
    if(mode==0){
        Pb += (size_t)z*sC;
        #pragma unroll
        for(int mf=0;mf<2;mf++){
            const int r0 = m0 + mw + mf*16 + gr, r1 = r0 + 8;
            float s0=0.f, s1=0.f;
            #pragma unroll
            for(int ng=0;ng<4;ng++){
                #pragma unroll
                for(int h=0;h<2;h++){
                    const int col = n0 + nw + ng*16 + h*8 + gc;
                    float* cc = acc[mf][ng*2+h];
                    float e00=__expf(cc[0]*0.0625f), e01=__expf(cc[1]*0.0625f);
                    float e10=__expf(cc[2]*0.0625f), e11=__expf(cc[3]*0.0625f);
                    bf162 p0; p0.x=__float2bfloat16(e00); p0.y=__float2bfloat16(e01);
                    bf162 p1; p1.x=__float2bfloat16(e10); p1.y=__float2bfloat16(e11);
                    *(bf162*)&Pb[(size_t)r0*ldc + col] = p0;
                    *(bf162*)&Pb[(size_t)r1*ldc + col] = p1;
                    s0 += e00+e01; s1 += e10+e11;
                }
            }
            s0 += __shfl_xor_sync(0xffffffffu, s0, 1);
            s0 += __shfl_xor_sync(0xffffffffu, s0, 2);
            s1 += __shfl_xor_sync(0xffffffffu, s1, 1);
            s1 += __shfl_xor_sync(0xffffffffu, s1, 2);
            if((lane&3)==0){
                atomicAdd(&psum[z*RPB + r0], s0);
                atomicAdd(&psum[z*RPB + r1], s1);
            }
        }
    } else {
        C += (size_t)z*sC;
        const float* rz = res + (size_t)z*sC;
        #pragma unroll
        for(int mf=0;mf<2;mf++){
            const int r0 = m0 + mw + mf*16 + gr, r1 = r0 + 8;
            const float i0 = 1.0f/psum[z*RPB + r0];
            const float i1 = 1.0f/psum[z*RPB + r1];
            #pragma unroll
            for(int ng=0;ng<4;ng++){
                #pragma unroll
                for(int h=0;h<2;h++){
                    const int col = n0 + nw + ng*16 + h*8 + gc;
                    float* cc = acc[mf][ng*2+h];
                    C[(size_t)r0*ldc + col]   = cc[0]*i0 + rz[(size_t)r0*ldc + col];
                    C[(size_t)r0*ldc + col+1] = cc[1]*i0 + rz[(size_t)r0*ldc + col+1];
                    C[(size_t)r1*ldc + col]   = cc[2]*i1 + rz[(size_t)r1*ldc + col];
                    C[(size_t)r1*ldc + col+1] = cc[3]*i1 + rz[(size_t)r1*ldc + col+1];
                }
            }
        }
    }
}

// ============ split-bf16 3-pass NT GEMM ============
// modes: 0 +bias (C/Cbh opt); 1 +bias+ext[(row>>2)*ldc+col] (Cbh);
// 2 gelu(+bias) -> Cbh/Cbl; 3 +bias+ext[row*ldc+col] -> C (+Cbh/Cbl split)
__global__ void __launch_bounds__(256) mma_nt3(
    const bf16* __restrict__ Ah, const bf16* __restrict__ Al,
    const bf16* __restrict__ Bh, const bf16* __restrict__ Bl,
    const float* __restrict__ bias, const float* __restrict__ ext,
    float* __restrict__ C, bf16* __restrict__ Cbh, bf16* __restrict__ Cbl,
    int ldc, int K, size_t sA, size_t sC, int mode)
{
    extern __shared__ char sm[];
    const uint32_t su = smem_u32(sm);
    const int t = threadIdx.x, wid = t>>5, lane = t&31, z = blockIdx.z;
    const int m0 = blockIdx.y<<7, n0 = blockIdx.x<<7;
    Ah += (size_t)z*sA + (size_t)m0*K;
    Al += (size_t)z*sA + (size_t)m0*K;
    Bh += (size_t)n0*K;
    Bl += (size_t)n0*K;
    const int row_ld = t>>3, col_ld = t&7;
    const uint32_t swoff = SW128((uint32_t)(row_ld*128 + col_ld*16));
    const int nsteps = K>>6;
    float acc[2][8][4];
    #pragma unroll
    for(int i=0;i<2;i++)
        #pragma unroll
        for(int j=0;j<8;j++){ acc[i][j][0]=0.f; acc[i][j][1]=0.f; acc[i][j][2]=0.f; acc[i][j][3]=0.f; }
    {
        #pragma unroll
        for(int j=0;j<4;j++){
            size_t ro = (size_t)(row_ld + j*32)*K + col_ld*8;
            cpa16(su +         swoff + j*4096, Ah + ro);
            cpa16(su + 16384 + swoff + j*4096, Al + ro);
            cpa16(su + 32768 + swoff + j*4096, Bh + ro);
            cpa16(su + 49152 + swoff + j*4096, Bl + ro);
        }
        CP_COMMIT(); CP_WAIT0();
    }
    __syncthreads();
    const int mw = (wid&3)<<5, nw = (wid>>2)<<6;
    for(int s=0;s<nsteps;s++){
        const uint32_t bufc = su + (uint32_t)((s&1)*65536);
        if(s+1<nsteps){
            const uint32_t bufn = su + (uint32_t)(((s+1)&1)*65536);
            const size_t ko = (size_t)(s+1)*64 + col_ld*8;
            #pragma unroll
            for(int j=0;j<4;j++){
                size_t ro = (size_t)(row_ld + j*32)*K + ko;
                cpa16(bufn +         swoff + j*4096, Ah + ro);
                cpa16(bufn + 16384 + swoff + j*4096, Al + ro);
                cpa16(bufn + 32768 + swoff + j*4096, Bh + ro);
                cpa16(bufn + 49152 + swoff + j*4096, Bl + ro);
            }
            CP_COMMIT();
        }
        #pragma unroll
        for(int kk=0;kk<4;kk++){
            const int kb = kk*32 + ((lane>>4)*16);
            uint32_t ah[2][4], al[2][4];
            #pragma unroll
            for(int mf=0;mf<2;mf++){
                int row = mw + mf*16 + (lane&15);
                uint32_t so = SW128((uint32_t)(row*128 + kb));
                ldsm4(ah[mf][0],ah[mf][1],ah[mf][2],ah[mf][3], bufc + so);
                ldsm4(al[mf][0],al[mf][1],al[mf][2],al[mf][3], bufc + 16384 + so);
            }
            #pragma unroll
            for(int ng=0;ng<4;ng++){
                int row = nw + ng*16 + (lane&15);
                uint32_t so = SW128((uint32_t)(row*128 + kb));
                uint32_t bh0,bh1,bh2,bh3, bl0,bl1,bl2,bl3;
                ldsm4(bh0,bh1,bh2,bh3, bufc + 32768 + so);
                ldsm4(bl0,bl1,bl2,bl3, bufc + 49152 + so);
                #pragma unroll
                for(int mf=0;mf<2;mf++){
                    mma16816(acc[mf][ng*2+0], ah[mf][0],ah[mf][1],ah[mf][2],ah[mf][3], bh0, bh2);
                    mma16816(acc[mf][ng*2+1], ah[mf][0],ah[mf][1],ah[mf][2],ah[mf][3], bh1, bh3);
                    mma16816(acc[mf][ng*2+0], ah[mf][0],ah[mf][1],ah[mf][2],ah[mf][3], bl0, bl2);
                    mma16816(acc[mf][ng*2+1], ah[mf][0],ah[mf][1],ah[mf][2],ah[mf][3], bl1, bl3);
                    mma16816(acc[mf][ng*2+0], al[mf][0],al[mf][1],al[mf][2],al[mf][3], bh0, bh2);
                    mma16816(acc[mf][ng*2+1], al[mf][0],al[mf][1],al[mf][2],al[mf][3], bh1, bh3);
                }
            }
        }
        if(s+1<nsteps) CP_WAIT0();
        __syncthreads();
    }
    if(C)   C   += (size_t)z*sC;
    if(Cbh) Cbh += (size_t)z*sC;
    if(Cbl) Cbl += (size_t)z*sC;
    const float* extz = (mode==3 && ext) ? ext + (size_t)z*sC : ext;
    const int gr = lane>>2, gc = (lane&3)<<1;
    #pragma unroll
    for(int mf=0;mf<2;mf++){
        const int r0 = m0 + mw + mf*16 + gr, r1 = r0 + 8;
        #pragma unroll
        for(int ng=0;ng<4;ng++){
            #pragma unroll
            for(int h=0;h<2;h++){
                const int col = n0 + nw + ng*16 + h*8 + gc;
                float* cc = acc[mf][ng*2+h];
                float b0 = bias ? bias[col] : 0.f, b1 = bias ? bias[col+1] : 0.f;
                float x00=cc[0]+b0, x01=cc[1]+b1, x10=cc[2]+b0, x11=cc[3]+b1;
                if(mode==1){
                    x00 += extz[(size_t)(r0>>2)*ldc + col];
                    x01 += extz[(size_t)(r0>>2)*ldc + col + 1];
                    x10 += extz[(size_t)(r1>>2)*ldc + col];
                    x11 += extz[(size_t)(r1>>2)*ldc + col + 1];
                } else if(mode==2){
                    x00=geluf(x00); x01=geluf(x01); x10=geluf(x10); x11=geluf(x11);
                } else if(mode==3){
                    x00 += extz[(size_t)r0*ldc + col];
                    x01 += extz[(size_t)r0*ldc + col + 1];
                    x10 += extz[(size_t)r1*ldc + col];
                    x11 += extz[(size_t)r1*ldc + col + 1];
                }
                if(C){
                    C[(size_t)r0*ldc + col]   = x00; C[(size_t)r0*ldc + col+1] = x01;
                    C[(size_t)r1*ldc + col]   = x10; C[(size_t)r1*ldc + col+1] = x11;
                }
                if(Cbh){
                    bf162 p0; p0.x=__float2bfloat16(x00); p0.y=__float2bfloat16(x01);
                    bf162 p1; p1.x=__float2bfloat16(x10); p1.y=__float2bfloat16(x11);
                    *(bf162*)&Cbh[(size_t)r0*ldc + col] = p0;
                    *(bf162*)&Cbh[(size_t)r1*ldc + col] = p1;
                    if(Cbl){
                        bf162 q0, q1;
                        q0.x=__float2bfloat16(x00-__bfloat162float(p0.x));
                        q0.y=__float2bfloat16(x01-__bfloat162float(p0.y));
                        q1.x=__float2bfloat16(x10-__bfloat162float(p1.x));
                        q1.y=__float2bfloat16(x11-__bfloat162float(p1.y));
                        *(bf162*)&Cbl[(size_t)r0*ldc + col] = q0;
                        *(bf162*)&Cbl[(size_t)r1*ldc + col] = q1;
                    }
                }
            }
        }
    }
}

__global__ void __launch_bounds__(256) split_bf16_kernel(
    const float* __restrict__ x, bf16* __restrict__ hi, bf16* __restrict__ lo, int n4)
{
    int i = blockIdx.x*blockDim.x + threadIdx.x;
    if (i >= n4) return;
    float4 v = ((const float4*)x)[i];
    bf16 h0=__float2bfloat16(v.x), h1=__float2bfloat16(v.y);
    bf16 h2=__float2bfloat16(v.z), h3=__float2bfloat16(v.w);
    bf162 a; a.x=h0; a.y=h1;
    bf162 b; b.x=h2; b.y=h3;
    bf162 c; c.x=__float2bfloat16(v.x-__bfloat162float(h0)); c.y=__float2bfloat16(v.y-__bfloat162float(h1));
    bf162 d; d.x=__float2bfloat16(v.z-__bfloat162float(h2)); d.y=__float2bfloat16(v.w-__bfloat162float(h3));
    ((bf162*)hi)[2*i]   = a;
    ((bf162*)hi)[2*i+1] = b;
    ((bf162*)lo)[2*i]   = c;
    ((bf162*)lo)[2*i+1] = d;
}

__global__ void __launch_bounds__(256) txsplit_kernel(
    const float* __restrict__ W, bf16* __restrict__ Th, bf16* __restrict__ Tl, int K, int N)
{
    __shared__ float tl[32][33];
    const int k0 = blockIdx.x<<5, n0 = blockIdx.y<<5;
    const int t = threadIdx.x, r = t>>5, c = t&31;
    #pragma unroll
    for(int j=0;j<4;j++)
        tl[r+j*8][c] = W[(size_t)(k0+r+j*8)*N + n0 + c];
    __syncthreads();
    #pragma unroll
    for(int j=0;j<4;j++){
        float x = tl[c][r+j*8];
        bf16 h = __float2bfloat16(x);
        Th[(size_t)(n0+r+j*8)*K + k0 + c] = h;
        Tl[(size_t)(n0+r+j*8)*K + k0 + c] = __float2bfloat16(x-__bfloat162float(h));
    }
}

__global__ void __launch_bounds__(256) transpose_bf_kernel(
    const float* __restrict__ v, bf16* __restrict__ vt)
{
    __shared__ bf16 tl[64][65];
    const int s0 = blockIdx.x<<6, d0 = blockIdx.y<<6, z = blockIdx.z;
    const float* vz = v + (size_t)z*SEQ*DIM;
    bf16* vtz = vt + (size_t)z*SEQ*DIM;
    const int t = threadIdx.x;
    #pragma unroll
    for(int j=0;j<16;j++){
        int idx = j*256 + t, r = idx>>6, c = idx&63;
        tl[r][c] = __float2bfloat16(vz[(size_t)(s0+r)*DIM + d0 + c]);
    }
    __syncthreads();
    #pragma unroll
    for(int j=0;j<16;j++){
        int idx = j*256 + t, r = idx>>6, c = idx&63;
        vtz[(size_t)(d0+r)*SEQ + s0 + c] = tl[c][r];
    }
}

__global__ void __launch_bounds__(256) sgemm_nn(
    const float* __restrict__ A, const float* __restrict__ B,
    const float* __restrict__ bias, float* __restrict__ C,
    int M, int N, int K)
{
    __shared__ float As[8][132];
    __shared__ float Bs[8][128];
    const int t = threadIdx.x;
    const int m0 = blockIdx.y<<7, n0 = blockIdx.x<<7;
    const int arow = t>>1, acol = (t&1)<<2;
    const int brow = t>>5, bcol = (t&31)<<2;
    const float* Ap = A + (size_t)(m0+arow)*K + acol;
    const float* Bp = B + (size_t)brow*N + n0 + bcol;
    float4 ar = *(const float4*)Ap;
    float4 br = *(const float4*)Bp;
    ull c2[8][4];
    #pragma unroll
    for(int i=0;i<8;i++){ c2[i][0]=0; c2[i][1]=0; c2[i][2]=0; c2[i][3]=0; }
    const int tm=(t>>4)<<3, tn=(t&15)<<3;
    const int nt = K>>3;
    for(int kt=0;kt<nt;kt++){
        As[acol+0][arow]=ar.x; As[acol+1][arow]=ar.y;
        As[acol+2][arow]=ar.z; As[acol+3][arow]=ar.w;
        *(float4*)&Bs[brow][bcol]=br;
        __syncthreads();
        if(kt+1<nt){
            ar = *(const float4*)(Ap + ((kt+1)<<3));
            br = *(const float4*)(Bp + (size_t)((kt+1)<<3)*N);
        }
        #pragma unroll
        for(int kk=0;kk<8;kk++){
            float4 a0=*(const float4*)&As[kk][tm];
            float4 a1=*(const float4*)&As[kk][tm+4];
            ulonglong2 w0=*(const ulonglong2*)&Bs[kk][tn];
            ulonglong2 w1=*(const ulonglong2*)&Bs[kk][tn+4];
            float a[8]={a0.x,a0.y,a0.z,a0.w,a1.x,a1.y,a1.z,a1.w};
            #pragma unroll
            for(int i=0;i<8;i++){
                ull ap = pack2(a[i],a[i]);
                c2[i][0]=fma2(ap,w0.x,c2[i][0]);
                c2[i][1]=fma2(ap,w0.y,c2[i][1]);
                c2[i][2]=fma2(ap,w1.x,c2[i][2]);
                c2[i][3]=fma2(ap,w1.y,c2[i][3]);
            }
        }
        __syncthreads();
    }
    #pragma unroll
    for(int i=0;i<8;i++){
        const int row=m0+tm+i;
        float v[8];
        #pragma unroll
        for(int p=0;p<4;p++){ float2 u=up2(c2[i][p]); v[2*p]=u.x; v[2*p+1]=u.y; }
        #pragma unroll
        for(int j=0;j<8;j++) v[j] += bias[n0+tn+j];
        *(float4*)&C[(size_t)row*N + n0+tn]   = make_float4(v[0],v[1],v[2],v[3]);
        *(float4*)&C[(size_t)row*N + n0+tn+4] = make_float4(v[4],v[5],v[6],v[7]);
    }
}

__global__ void init_slots_kernel(const float* __restrict__ noise,
                                  const float* __restrict__ mu,
                                  const float* __restrict__ sigma,
                                  float* __restrict__ slots,
                                  bf16* __restrict__ slh, bf16* __restrict__ sll)
{
    for(int idx = blockIdx.x*blockDim.x + threadIdx.x; idx < SROWS*DIM;
        idx += gridDim.x*blockDim.x){
        int d = idx & 255, ns = (idx>>8)&3, i = (idx>>10)&127, b = idx>>17;
        float val = mu[ns*DIM+d] + noise[(size_t)(((i*BSZ+b)*NS+ns))*DIM+d]*sigma[ns*DIM+d];
        slots[idx] = val;
        bf16 hv = __float2bfloat16(val);
        slh[idx] = hv;
        sll[idx] = __float2bfloat16(val - __bfloat162float(hv));
    }
}

__global__ void norm_rows_kernel(const float* __restrict__ iq,
                                 const float* __restrict__ cls,
                                 float* __restrict__ qn, float* __restrict__ clsn)
{
    const int row = blockIdx.x, lane = threadIdx.x;
    const float* src; float* dst;
    if(row < NI){ src = iq + (size_t)row*DIM; dst = qn + (size_t)row*DIM; }
    else        { src = cls + (size_t)(row-NI)*DIM; dst = clsn + (size_t)(row-NI)*DIM; }
    float4 a0=*(const float4*)(src + (lane<<2));
    float4 a1=*(const float4*)(src + 128 + (lane<<2));
    float ss=a0.x*a0.x+a0.y*a0.y+a0.z*a0.z+a0.w*a0.w
            +a1.x*a1.x+a1.y*a1.y+a1.z*a1.z+a1.w*a1.w;
    ss = wsum(ss);
    float inv = 1.0f/fmaxf(sqrtf(ss), 1e-12f);
    *(float4*)(dst+(lane<<2))     = make_float4(a0.x*inv,a0.y*inv,a0.z*inv,a0.w*inv);
    *(float4*)(dst+128+(lane<<2)) = make_float4(a1.x*inv,a1.y*inv,a1.z*inv,a1.w*inv);
}

// y = LN(x)*g + b; optional bf16 hi/lo outputs
__global__ void __launch_bounds__(256) ln_rows_kernel(
    const float* __restrict__ x, const float* __restrict__ g,
    const float* __restrict__ bb, float* __restrict__ y,
    bf16* __restrict__ yh, bf16* __restrict__ yl)
{
    const int row = (blockIdx.x<<3) + (threadIdx.x>>5);
    const int lane = threadIdx.x & 31;
    const float* xp = x + (size_t)row*DIM;
    float4 a0=*(const float4*)(xp+(lane<<2));
    float4 a1=*(const float4*)(xp+128+(lane<<2));
    float v[8]={a0.x,a0.y,a0.z,a0.w,a1.x,a1.y,a1.z,a1.w};
    float s1=0.f,s2=0.f;
    #pragma unroll
    for(int q=0;q<8;q++){ s1+=v[q]; s2+=v[q]*v[q]; }
    s1=wsum(s1); s2=wsum(s2);
    float mean=s1*(1.0f/256.0f);
    float rstd=rsqrtf(s2*(1.0f/256.0f)-mean*mean + 1e-5f);
    float4 g0=*(const float4*)(g+(lane<<2)),  g1=*(const float4*)(g+128+(lane<<2));
    float4 b0=*(const float4*)(bb+(lane<<2)), b1=*(const float4*)(bb+128+(lane<<2));
    float o[8];
    o[0]=(v[0]-mean)*rstd*g0.x+b0.x; o[1]=(v[1]-mean)*rstd*g0.y+b0.y;
    o[2]=(v[2]-mean)*rstd*g0.z+b0.z; o[3]=(v[3]-mean)*rstd*g0.w+b0.w;
    o[4]=(v[4]-mean)*rstd*g1.x+b1.x; o[5]=(v[5]-mean)*rstd*g1.y+b1.y;
    o[6]=(v[6]-mean)*rstd*g1.z+b1.z; o[7]=(v[7]-mean)*rstd*g1.w+b1.w;
    float* yp = y + (size_t)row*DIM;
    *(float4*)(yp+(lane<<2))     = make_float4(o[0],o[1],o[2],o[3]);
    *(float4*)(yp+128+(lane<<2)) = make_float4(o[4],o[5],o[6],o[7]);
    if(yh){
        bf16 hbuf[4], lbuf[4];
        #pragma unroll
        for(int q=0;q<4;q++){
            hbuf[q]=__float2bfloat16(o[q]);
            lbuf[q]=__float2bfloat16(o[q]-__bfloat162float(hbuf[q]));
        }
        *(uint2*)(yh + (size_t)row*DIM + (lane<<2)) = *(uint2*)hbuf;
        *(uint2*)(yl + (size_t)row*DIM + (lane<<2)) = *(uint2*)lbuf;
        #pragma unroll
        for(int q=0;q<4;q++){
            hbuf[q]=__float2bfloat16(o[q+4]);
            lbuf[q]=__float2bfloat16(o[q+4]-__bfloat162float(hbuf[q]));
        }
        *(uint2*)(yh + (size_t)row*DIM + 128 + (lane<<2)) = *(uint2*)hbuf;
        *(uint2*)(yl + (size_t)row*DIM + 128 + (lane<<2)) = *(uint2*)lbuf;
    }
}

__global__ void __launch_bounds__(128) final_kernel(
    const float* __restrict__ slots, const float* __restrict__ qn,
    const float* __restrict__ clsn, const float* __restrict__ alpha,
    const float* __restrict__ temp, float* __restrict__ out)
{
    __shared__ float sh[4];
    const int i = blockIdx.x, b = blockIdx.y;
    const int w = threadIdx.x>>5, lane = threadIdx.x&31;
    const size_t base = ((size_t)(b*NI + i))*NS;
    const float* qp = qn + (size_t)i*DIM;
    const float* sp = slots + (base+w)*DIM;
    float ss=0.f, dq=0.f;
    #pragma unroll
    for(int q=0;q<8;q++){
        float x=sp[lane+(q<<5)], y=qp[lane+(q<<5)];
        ss+=x*x; dq+=x*y;
    }
    ss=wsum(ss); dq=wsum(dq);
    if(lane==0) sh[w] = dq / fmaxf(sqrtf(ss), 1e-12f);
    __syncthreads();
    float m=fmaxf(fmaxf(sh[0],sh[1]),fmaxf(sh[2],sh[3]));
    float e0=expf(sh[0]-m),e1=expf(sh[1]-m),e2=expf(sh[2]-m),e3=expf(sh[3]-m);
    float inv=1.0f/(e0+e1+e2+e3);
    float a4[4]={e0*inv,e1*inv,e2*inv,e3*inv};
    __syncthreads();
    const int d0=threadIdx.x, d1=threadIdx.x+128;
    float s0=0.f, s1=0.f;
    #pragma unroll
    for(int n=0;n<4;n++){
        const float* rp = slots + (base+n)*DIM;
        s0 += a4[n]*rp[d0]; s1 += a4[n]*rp[d1];
    }
    float pp = wsum(s0*s0 + s1*s1);
    if(lane==0) sh[w]=pp;
    __syncthreads();
    float nrm = fmaxf(sqrtf(sh[0]+sh[1]+sh[2]+sh[3]), 1e-12f);
    float al = *alpha;
    const float* cp = clsn + (size_t)b*DIM;
    float f0 = cp[d0] + al*s0/nrm;
    float f1 = cp[d1] + al*s1/nrm;
    float dot = wsum(f0*qp[d0] + f1*qp[d1]);
    __syncthreads();
    if(lane==0) sh[w]=dot;
    __syncthreads();
    if(threadIdx.x==0)
        out[(size_t)b*NI + i] = (sh[0]+sh[1]+sh[2]+sh[3]) / fmaxf(*temp, 1e-4f);
}

#define GSYM(p, s) cudaGetSymbolAddress((void**)&p, s)

extern "C" void kernel_launch(void* const* d_in, const int* in_sizes, int n_in,
                              void* d_out, int out_size)
{
    const float* tokens=(const float*)d_in[0];
    const float* cls   =(const float*)d_in[1];
    const float* iq    =(const float*)d_in[2];
    const float* noise =(const float*)d_in[3];
    const float* Wk=(const float*)d_in[4],  *bk=(const float*)d_in[5];
    const float* Wv=(const float*)d_in[6],  *bv=(const float*)d_in[7];
    const float* Wqs=(const float*)d_in[8], *bqs=(const float*)d_in[9];
    const float* Wqi=(const float*)d_in[10],*bqi=(const float*)d_in[11];
    const float* ln1g=(const float*)d_in[12],*ln1b=(const float*)d_in[13];
    const float* ln2g=(const float*)d_in[14],*ln2b=(const float*)d_in[15];
    const float* Wf1=(const float*)d_in[16],*bf1=(const float*)d_in[17];
    const float* Wf2=(const float*)d_in[18],*bf2=(const float*)d_in[19];
    const float* mu=(const float*)d_in[20], *sg=(const float*)d_in[21];
    const float* alpha=(const float*)d_in[22],*temp=(const float*)d_in[23];
    float* out=(float*)d_out;

    float *v,*psum,*slots,*h,*qi,*qnp,*clsn;
    bf16 *kbf,*vt,*qbf,*P,*tokh,*tokl,*slh,*sll,*hh,*hl,*tbh,*tbl;
    bf16 *WkTh,*WkTl,*WvTh,*WvTl,*WqsTh,*WqsTl,*Wf1Th,*Wf1Tl,*Wf2Th,*Wf2Tl;
    GSYM(v,g_v); GSYM(psum,g_psum); GSYM(slots,g_slots);
    GSYM(h,g_h); GSYM(qi,g_qintent); GSYM(qnp,g_qn); GSYM(clsn,g_clsn);
    GSYM(kbf,g_kbf); GSYM(vt,g_vt); GSYM(qbf,g_qbf); GSYM(P,g_P);
    GSYM(tokh,g_tokh); GSYM(tokl,g_tokl); GSYM(slh,g_slh); GSYM(sll,g_sll);
    GSYM(hh,g_hh); GSYM(hl,g_hl); GSYM(tbh,g_tbh); GSYM(tbl,g_tbl);
    GSYM(WkTh,g_WkTh); GSYM(WkTl,g_WkTl); GSYM(WvTh,g_WvTh); GSYM(WvTl,g_WvTl);
    GSYM(WqsTh,g_WqsTh); GSYM(WqsTl,g_WqsTl);
    GSYM(Wf1Th,g_Wf1Th); GSYM(Wf1Tl,g_Wf1Tl); GSYM(Wf2Th,g_Wf2Th); GSYM(Wf2Tl,g_Wf2Tl);

    cudaFuncSetAttribute(mma_nt,  cudaFuncAttributeMaxDynamicSharedMemorySize, 65536);
    cudaFuncSetAttribute(mma_nt3, cudaFuncAttributeMaxDynamicSharedMemorySize, 131072);

    init_slots_kernel<<<4096,256>>>(noise, mu, sg, slots, slh, sll);
    norm_rows_kernel<<<NI+BSZ,32>>>(iq, cls, qnp, clsn);
    sgemm_nn<<<dim3(2,1),256>>>(iq, Wqi, bqi, qi, NI, DIM, DIM);
    split_bf16_kernel<<<(BSZ*SEQ*DIM/4+255)/256,256>>>(tokens, tokh, tokl, BSZ*SEQ*DIM/4);
    txsplit_kernel<<<dim3(DIM/32,DIM/32),256>>>(Wk, WkTh, WkTl, DIM, DIM);
    txsplit_kernel<<<dim3(DIM/32,DIM/32),256>>>(Wv, WvTh, WvTl, DIM, DIM);
    txsplit_kernel<<<dim3(DIM/32,DIM/32),256>>>(Wqs, WqsTh, WqsTl, DIM, DIM);
    txsplit_kernel<<<dim3(DIM/32,2*DIM/32),256>>>(Wf1, Wf1Th, Wf1Tl, DIM, 2*DIM);
    txsplit_kernel<<<dim3(2*DIM/32,DIM/32),256>>>(Wf2, Wf2Th, Wf2Tl, 2*DIM, DIM);
    mma_nt3<<<dim3(2,512,1),256,131072>>>(tokh, tokl, WkTh, WkTl, bk, nullptr,
                                          nullptr, kbf, nullptr, DIM, DIM, 0, 0, 0);
    mma_nt3<<<dim3(2,512,1),256,131072>>>(tokh, tokl, WvTh, WvTl, bv, nullptr,
                                          v, nullptr, nullptr, DIM, DIM, 0, 0, 0);
    transpose_bf_kernel<<<dim3(SEQ/64, DIM/64, BSZ),256>>>(v, vt);

    for(int it=0; it<3; it++){
        zero_psum_kernel<<<SROWS/256,256>>>(psum);
        mma_nt3<<<dim3(2,4,BSZ),256,131072>>>(slh, sll, WqsTh, WqsTl, bqs, qi,
                                              nullptr, qbf, nullptr, DIM, DIM,
                                              (size_t)RPB*DIM, (size_t)RPB*DIM, 1);
        mma_nt<<<dim3(SEQ/128, RPB/128, BSZ),256,65536>>>(
            qbf, kbf, P, psum, nullptr, DIM, DIM, SEQ, DIM,
            (size_t)RPB*DIM, (size_t)SEQ*DIM, (size_t)RPB*SEQ, 0, nullptr);
        mma_nt<<<dim3(DIM/128, RPB/128, BSZ),256,65536>>>(
            P, vt, nullptr, psum, slots, SEQ, SEQ, DIM, SEQ,
            (size_t)RPB*SEQ, (size_t)DIM*SEQ, (size_t)RPB*DIM, 1, slots);
        ln_rows_kernel<<<SROWS/8,256>>>(slots, ln1g, ln1b, slots, nullptr, nullptr);
        ln_rows_kernel<<<SROWS/8,256>>>(slots, ln2g, ln2b, h, hh, hl);
        mma_nt3<<<dim3(4,128,1),256,131072>>>(hh, hl, Wf1Th, Wf1Tl, bf1, nullptr,
                                              nullptr, tbh, tbl, 2*DIM, DIM, 0, 0, 2);
        mma_nt3<<<dim3(2,128,1),256,131072>>>(tbh, tbl, Wf2Th, Wf2Tl, bf2, slots,
                                              slots, slh, sll, DIM, 2*DIM, 0, 0, 3);
    }
    final_kernel<<<dim3(NI,BSZ),128>>>(slots, qnp, clsn, alpha, temp, out);
}

// round 9
// speedup vs baseline: 12.1113x; 1.4605x over previous
#include <cuda_runtime.h>
#include <cuda_bf16.h>
#include <cstdint>
#include <math.h>

#define NI 128
#define BSZ 32
#define NS 4
#define SEQ 2048
#define DIM 256
#define SROWS (NI*BSZ*NS)
#define RPB (NI*NS)

typedef unsigned long long ull;
typedef __nv_bfloat16 bf16;
typedef __nv_bfloat162 bf162;

__device__ bf16 g_kbf[BSZ*SEQ*DIM];
__device__ bf16 g_vbf[BSZ*SEQ*DIM];
__device__ bf16 g_vt[BSZ*SEQ*DIM];
__device__ bf16 g_qbf[SROWS*DIM];
__device__ bf16 g_P[(size_t)BSZ*RPB*SEQ];
__device__ float g_psum[SROWS];
__device__ float g_slots[SROWS*DIM];
__device__ float g_qintent[NI*DIM];
__device__ float g_qn[NI*DIM];
__device__ float g_clsn[BSZ*DIM];
__device__ bf16 g_tokh[BSZ*SEQ*DIM];
__device__ bf16 g_slh[SROWS*DIM];
__device__ bf16 g_sll[SROWS*DIM];
__device__ bf16 g_hh[SROWS*DIM];
__device__ bf16 g_tbh[SROWS*2*DIM];
__device__ bf16 g_WkTh[DIM*DIM];
__device__ bf16 g_WvTh[DIM*DIM];
__device__ bf16 g_WqsTh[DIM*DIM];
__device__ bf16 g_WqsTl[DIM*DIM];
__device__ bf16 g_Wf1Th[2*DIM*DIM];
__device__ bf16 g_Wf2Th[2*DIM*DIM];

__device__ __forceinline__ ull fma2(ull a, ull b, ull c){
    ull d; asm("fma.rn.f32x2 %0, %1, %2, %3;" : "=l"(d) : "l"(a),"l"(b),"l"(c)); return d;
}
__device__ __forceinline__ ull pack2(float x, float y){
    ull d; asm("mov.b64 %0, {%1, %2};" : "=l"(d) : "f"(x),"f"(y)); return d;
}
__device__ __forceinline__ float2 up2(ull v){
    float2 r; asm("mov.b64 {%0, %1}, %2;" : "=f"(r.x),"=f"(r.y) : "l"(v)); return r;
}
__device__ __forceinline__ float wsum(float v){
    #pragma unroll
    for(int o=16;o>0;o>>=1) v += __shfl_xor_sync(0xffffffffu, v, o);
    return v;
}
__device__ __forceinline__ uint32_t smem_u32(const void* p){
    uint32_t a; asm("{ .reg .u64 t; cvta.to.shared.u64 t, %1; cvt.u32.u64 %0, t; }" : "=r"(a) : "l"(p));
    return a;
}
#define SW128(o) ((o) ^ (((o)>>3)&0x70))
__device__ __forceinline__ void ldsm4(uint32_t& r0,uint32_t& r1,uint32_t& r2,uint32_t& r3,uint32_t a){
    asm volatile("ldmatrix.sync.aligned.m8n8.x4.shared.b16 {%0,%1,%2,%3}, [%4];"
        : "=r"(r0),"=r"(r1),"=r"(r2),"=r"(r3) : "r"(a) : "memory");
}
__device__ __forceinline__ void mma16816(float* c,uint32_t a0,uint32_t a1,uint32_t a2,uint32_t a3,uint32_t b0,uint32_t b1){
    asm volatile("mma.sync.aligned.m16n8k16.row.col.f32.bf16.bf16.f32 "
        "{%0,%1,%2,%3},{%4,%5,%6,%7},{%8,%9},{%0,%1,%2,%3};"
        : "+f"(c[0]),"+f"(c[1]),"+f"(c[2]),"+f"(c[3])
        : "r"(a0),"r"(a1),"r"(a2),"r"(a3),"r"(b0),"r"(b1));
}
__device__ __forceinline__ void cpa16(uint32_t d, const void* s){
    asm volatile("cp.async.cg.shared.global [%0], [%1], 16;" :: "r"(d), "l"(s));
}
#define CP_COMMIT() asm volatile("cp.async.commit_group;" ::: "memory")
#define CP_WAIT0()  asm volatile("cp.async.wait_group 0;" ::: "memory")
__device__ __forceinline__ float geluf(float x){
    return 0.5f*x*(1.0f+erff(x*0.70710678118654752f));
}

__global__ void zero_psum_kernel(float* __restrict__ p){
    p[blockIdx.x*256 + threadIdx.x] = 0.f;
}

// ============ bf16 NT GEMM, 1-pass: C[M,N] = A[M,K] @ B[N,K]^T ============
// modes: 0 softmax (Pb=exp(acc/16), psum atomics); 1 upd (C=acc/psum+res);
// 2 bias -> Pb bf16; 4 gelu(acc+bias) -> Pb bf16;
// 5 acc+bias+res -> C fp32 + Pb(hi)/Pl(lo)
__global__ void __launch_bounds__(256) mma_nt(
    const bf16* __restrict__ A, const bf16* __restrict__ B,
    bf16* __restrict__ Pb, bf16* __restrict__ Pl,
    float* __restrict__ psum, float* __restrict__ C,
    int lda, int ldb, int ldc, int K,
    size_t sA, size_t sB, size_t sC, int mode,
    const float* __restrict__ res, const float* __restrict__ bias)
{
    extern __shared__ char sm[];
    const uint32_t su = smem_u32(sm);
    const int t = threadIdx.x, wid = t>>5, lane = t&31, z = blockIdx.z;
    const int m0 = blockIdx.y<<7, n0 = blockIdx.x<<7;
    A += (size_t)z*sA + (size_t)m0*lda;
    B += (size_t)z*sB + (size_t)n0*ldb;
    const int row_ld = t>>3, col_ld = t&7;
    const uint32_t swoff = SW128((uint32_t)(row_ld*128 + col_ld*16));
    const int nsteps = K>>6;
    float acc[2][8][4];
    #pragma unroll
    for(int i=0;i<2;i++)
        #pragma unroll
        for(int j=0;j<8;j++){ acc[i][j][0]=0.f; acc[i][j][1]=0.f; acc[i][j][2]=0.f; acc[i][j][3]=0.f; }
    {
        const bf16* Ag = A + col_ld*8;
        const bf16* Bg = B + col_ld*8;
        #pragma unroll
        for(int j=0;j<4;j++){
            cpa16(su + swoff + j*4096, Ag + (size_t)(row_ld + j*32)*lda);
            cpa16(su + 16384 + swoff + j*4096, Bg + (size_t)(row_ld + j*32)*ldb);
        }
        CP_COMMIT(); CP_WAIT0();
    }
    __syncthreads();
    const int mw = (wid&3)<<5, nw = (wid>>2)<<6;
    for(int s=0;s<nsteps;s++){
        const uint32_t bufc = su + (uint32_t)((s&1)*32768);
        if(s+1<nsteps){
            const uint32_t bufn = su + (uint32_t)(((s+1)&1)*32768);
            const bf16* Ag = A + (size_t)(s+1)*64 + col_ld*8;
            const bf16* Bg = B + (size_t)(s+1)*64 + col_ld*8;
            #pragma unroll
            for(int j=0;j<4;j++){
                cpa16(bufn + swoff + j*4096, Ag + (size_t)(row_ld + j*32)*lda);
                cpa16(bufn + 16384 + swoff + j*4096, Bg + (size_t)(row_ld + j*32)*ldb);
            }
            CP_COMMIT();
        }
        #pragma unroll
        for(int kk=0;kk<4;kk++){
            const int kb = kk*32 + ((lane>>4)*16);
            uint32_t a[2][4];
            #pragma unroll
            for(int mf=0;mf<2;mf++){
                int row = mw + mf*16 + (lane&15);
                ldsm4(a[mf][0],a[mf][1],a[mf][2],a[mf][3], bufc + SW128((uint32_t)(row*128 + kb)));
            }
            #pragma unroll
            for(int ng=0;ng<4;ng++){
                int row = nw + ng*16 + (lane&15);
                uint32_t b0,b1,b2,b3;
                ldsm4(b0,b1,b2,b3, bufc + 16384 + SW128((uint32_t)(row*128 + kb)));
                #pragma unroll
                for(int mf=0;mf<2;mf++){
                    mma16816(acc[mf][ng*2+0], a[mf][0],a[mf][1],a[mf][2],a[mf][3], b0, b2);
                    mma16816(acc[mf][ng*2+1], a[mf][0],a[mf][1],a[mf][2],a[mf][3], b1, b3);
                }
            }
        }
        if(s+1<nsteps) CP_WAIT0();
        __syncthreads();
    }
    const int gr = lane>>2, gc = (lane&3)<<1;
    if(mode==0){
        Pb += (size_t)z*sC;
        #pragma unroll
        for(int mf=0;mf<2;mf++){
            const int r0 = m0 + mw + mf*16 + gr, r1 = r0 + 8;
            float s0=0.f, s1=0.f;
            #pragma unroll
            for(int ng=0;ng<4;ng++){
                #pragma unroll
                for(int h=0;h<2;h++){
                    const int col = n0 + nw + ng*16 + h*8 + gc;
                    float* cc = acc[mf][ng*2+h];
                    float e00=__expf(cc[0]*0.0625f), e01=__expf(cc[1]*0.0625f);
                    float e10=__expf(cc[2]*0.0625f), e11=__expf(cc[3]*0.0625f);
                    bf162 p0; p0.x=__float2bfloat16(e00); p0.y=__float2bfloat16(e01);
                    bf162 p1; p1.x=__float2bfloat16(e10); p1.y=__float2bfloat16(e11);
                    *(bf162*)&Pb[(size_t)r0*ldc + col] = p0;
                    *(bf162*)&Pb[(size_t)r1*ldc + col] = p1;
                    s0 += e00+e01; s1 += e10+e11;
                }
            }
            s0 += __shfl_xor_sync(0xffffffffu, s0, 1);
            s0 += __shfl_xor_sync(0xffffffffu, s0, 2);
            s1 += __shfl_xor_sync(0xffffffffu, s1, 1);
            s1 += __shfl_xor_sync(0xffffffffu, s1, 2);
            if((lane&3)==0){
                atomicAdd(&psum[z*RPB + r0], s0);
                atomicAdd(&psum[z*RPB + r1], s1);
            }
        }
    } else if(mode==1){
        C += (size_t)z*sC;
        const float* rz = res + (size_t)z*sC;
        #pragma unroll
        for(int mf=0;mf<2;mf++){
            const int r0 = m0 + mw + mf*16 + gr, r1 = r0 + 8;
            const float i0 = 1.0f/psum[z*RPB + r0];
            const float i1 = 1.0f/psum[z*RPB + r1];
            #pragma unroll
            for(int ng=0;ng<4;ng++){
                #pragma unroll
                for(int h=0;h<2;h++){
                    const int col = n0 + nw + ng*16 + h*8 + gc;
                    float* cc = acc[mf][ng*2+h];
                    C[(size_t)r0*ldc + col]   = cc[0]*i0 + rz[(size_t)r0*ldc + col];
                    C[(size_t)r0*ldc + col+1] = cc[1]*i0 + rz[(size_t)r0*ldc + col+1];
                    C[(size_t)r1*ldc + col]   = cc[2]*i1 + rz[(size_t)r1*ldc + col];
                    C[(size_t)r1*ldc + col+1] = cc[3]*i1 + rz[(size_t)r1*ldc + col+1];
                }
            }
        }
    } else {
        #pragma unroll
        for(int mf=0;mf<2;mf++){
            const int r0 = m0 + mw + mf*16 + gr, r1 = r0 + 8;
            #pragma unroll
            for(int ng=0;ng<4;ng++){
                #pragma unroll
                for(int h=0;h<2;h++){
                    const int col = n0 + nw + ng*16 + h*8 + gc;
                    float* cc = acc[mf][ng*2+h];
                    float b0=bias[col], b1=bias[col+1];
                    float x00=cc[0]+b0, x01=cc[1]+b1, x10=cc[2]+b0, x11=cc[3]+b1;
                    if(mode==4){ x00=geluf(x00); x01=geluf(x01); x10=geluf(x10); x11=geluf(x11); }
                    if(mode==5){
                        x00 += res[(size_t)r0*ldc + col];
                        x01 += res[(size_t)r0*ldc + col + 1];
                        x10 += res[(size_t)r1*ldc + col];
                        x11 += res[(size_t)r1*ldc + col + 1];
                        C[(size_t)r0*ldc + col]   = x00; C[(size_t)r0*ldc + col+1] = x01;
                        C[(size_t)r1*ldc + col]   = x10; C[(size_t)r1*ldc + col+1] = x11;
                    }
                    bf162 p0; p0.x=__float2bfloat16(x00); p0.y=__float2bfloat16(x01);
                    bf162 p1; p1.x=__float2bfloat16(x10); p1.y=__float2bfloat16(x11);
                    *(bf162*)&Pb[(size_t)r0*ldc + col] = p0;
                    *(bf162*)&Pb[(size_t)r1*ldc + col] = p1;
                    if(mode==5){
                        bf162 q0, q1;
                        q0.x=__float2bfloat16(x00-__bfloat162float(p0.x));
                        q0.y=__float2bfloat16(x01-__bfloat162float(p0.y));
                        q1.x=__float2bfloat16(x10-__bfloat162float(p1.x));
                        q1.y=__float2bfloat16(x11-__bfloat162float(p1.y));
                        *(bf162*)&Pl[(size_t)r0*ldc + col] = q0;
                        *(bf162*)&Pl[(size_t)r1*ldc + col] = q1;
                    }
                }
            }
        }
    }
}

// ============ split-bf16 3-pass NT GEMM (qslot only): Cbh = bf16(A@B^T + bias + ext) ============
__global__ void __launch_bounds__(256) mma_nt3(
    const bf16* __restrict__ Ah, const bf16* __restrict__ Al,
    const bf16* __restrict__ Bh, const bf16* __restrict__ Bl,
    const float* __restrict__ bias, const float* __restrict__ ext,
    bf16* __restrict__ Cbh, int ldc, int K, size_t sA, size_t sC)
{
    extern __shared__ char sm[];
    const uint32_t su = smem_u32(sm);
    const int t = threadIdx.x, wid = t>>5, lane = t&31, z = blockIdx.z;
    const int m0 = blockIdx.y<<7, n0 = blockIdx.x<<7;
    Ah += (size_t)z*sA + (size_t)m0*K;
    Al += (size_t)z*sA + (size_t)m0*K;
    Bh += (size_t)n0*K;
    Bl += (size_t)n0*K;
    const int row_ld = t>>3, col_ld = t&7;
    const uint32_t swoff = SW128((uint32_t)(row_ld*128 + col_ld*16));
    const int nsteps = K>>6;
    float acc[2][8][4];
    #pragma unroll
    for(int i=0;i<2;i++)
        #pragma unroll
        for(int j=0;j<8;j++){ acc[i][j][0]=0.f; acc[i][j][1]=0.f; acc[i][j][2]=0.f; acc[i][j][3]=0.f; }
    {
        #pragma unroll
        for(int j=0;j<4;j++){
            size_t ro = (size_t)(row_ld + j*32)*K + col_ld*8;
            cpa16(su +         swoff + j*4096, Ah + ro);
            cpa16(su + 16384 + swoff + j*4096, Al + ro);
            cpa16(su + 32768 + swoff + j*4096, Bh + ro);
            cpa16(su + 49152 + swoff + j*4096, Bl + ro);
        }
        CP_COMMIT(); CP_WAIT0();
    }
    __syncthreads();
    const int mw = (wid&3)<<5, nw = (wid>>2)<<6;
    for(int s=0;s<nsteps;s++){
        const uint32_t bufc = su + (uint32_t)((s&1)*65536);
        if(s+1<nsteps){
            const uint32_t bufn = su + (uint32_t)(((s+1)&1)*65536);
            const size_t ko = (size_t)(s+1)*64 + col_ld*8;
            #pragma unroll
            for(int j=0;j<4;j++){
                size_t ro = (size_t)(row_ld + j*32)*K + ko;
                cpa16(bufn +         swoff + j*4096, Ah + ro);
                cpa16(bufn + 16384 + swoff + j*4096, Al + ro);
                cpa16(bufn + 32768 + swoff + j*4096, Bh + ro);
                cpa16(bufn + 49152 + swoff + j*4096, Bl + ro);
            }
            CP_COMMIT();
        }
        #pragma unroll
        for(int kk=0;kk<4;kk++){
            const int kb = kk*32 + ((lane>>4)*16);
            uint32_t ah[2][4], al[2][4];
            #pragma unroll
            for(int mf=0;mf<2;mf++){
                int row = mw + mf*16 + (lane&15);
                uint32_t so = SW128((uint32_t)(row*128 + kb));
                ldsm4(ah[mf][0],ah[mf][1],ah[mf][2],ah[mf][3], bufc + so);
                ldsm4(al[mf][0],al[mf][1],al[mf][2],al[mf][3], bufc + 16384 + so);
            }
            #pragma unroll
            for(int ng=0;ng<4;ng++){
                int row = nw + ng*16 + (lane&15);
                uint32_t so = SW128((uint32_t)(row*128 + kb));
                uint32_t bh0,bh1,bh2,bh3, bl0,bl1,bl2,bl3;
                ldsm4(bh0,bh1,bh2,bh3, bufc + 32768 + so);
                ldsm4(bl0,bl1,bl2,bl3, bufc + 49152 + so);
                #pragma unroll
                for(int mf=0;mf<2;mf++){
                    mma16816(acc[mf][ng*2+0], ah[mf][0],ah[mf][1],ah[mf][2],ah[mf][3], bh0, bh2);
                    mma16816(acc[mf][ng*2+1], ah[mf][0],ah[mf][1],ah[mf][2],ah[mf][3], bh1, bh3);
                    mma16816(acc[mf][ng*2+0], ah[mf][0],ah[mf][1],ah[mf][2],ah[mf][3], bl0, bl2);
                    mma16816(acc[mf][ng*2+1], ah[mf][0],ah[mf][1],ah[mf][2],ah[mf][3], bl1, bl3);
                    mma16816(acc[mf][ng*2+0], al[mf][0],al[mf][1],al[mf][2],al[mf][3], bh0, bh2);
                    mma16816(acc[mf][ng*2+1], al[mf][0],al[mf][1],al[mf][2],al[mf][3], bh1, bh3);
                }
            }
        }
        if(s+1<nsteps) CP_WAIT0();
        __syncthreads();
    }
    Cbh += (size_t)z*sC;
    const int gr = lane>>2, gc = (lane&3)<<1;
    #pragma unroll
    for(int mf=0;mf<2;mf++){
        const int r0 = m0 + mw + mf*16 + gr, r1 = r0 + 8;
        #pragma unroll
        for(int ng=0;ng<4;ng++){
            #pragma unroll
            for(int h=0;h<2;h++){
                const int col = n0 + nw + ng*16 + h*8 + gc;
                float* cc = acc[mf][ng*2+h];
                float b0=bias[col], b1=bias[col+1];
                float x00=cc[0]+b0+ext[(size_t)(r0>>2)*ldc + col];
                float x01=cc[1]+b1+ext[(size_t)(r0>>2)*ldc + col + 1];
                float x10=cc[2]+b0+ext[(size_t)(r1>>2)*ldc + col];
                float x11=cc[3]+b1+ext[(size_t)(r1>>2)*ldc + col + 1];
                bf162 p0; p0.x=__float2bfloat16(x00); p0.y=__float2bfloat16(x01);
                bf162 p1; p1.x=__float2bfloat16(x10); p1.y=__float2bfloat16(x11);
                *(bf162*)&Cbh[(size_t)r0*ldc + col] = p0;
                *(bf162*)&Cbh[(size_t)r1*ldc + col] = p1;
            }
        }
    }
}

__global__ void __launch_bounds__(256) f2bf_kernel(
    const float* __restrict__ x, bf16* __restrict__ y, int n4)
{
    int i = blockIdx.x*blockDim.x + threadIdx.x;
    if (i >= n4) return;
    float4 v = ((const float4*)x)[i];
    bf162 a; a.x=__float2bfloat16(v.x); a.y=__float2bfloat16(v.y);
    bf162 b; b.x=__float2bfloat16(v.z); b.y=__float2bfloat16(v.w);
    ((bf162*)y)[2*i] = a;
    ((bf162*)y)[2*i+1] = b;
}

__global__ void __launch_bounds__(256) txsplit_kernel(
    const float* __restrict__ W, bf16* __restrict__ Th, bf16* __restrict__ Tl, int K, int N)
{
    __shared__ float tl[32][33];
    const int k0 = blockIdx.x<<5, n0 = blockIdx.y<<5;
    const int t = threadIdx.x, r = t>>5, c = t&31;
    #pragma unroll
    for(int j=0;j<4;j++)
        tl[r+j*8][c] = W[(size_t)(k0+r+j*8)*N + n0 + c];
    __syncthreads();
    #pragma unroll
    for(int j=0;j<4;j++){
        float x = tl[c][r+j*8];
        bf16 h = __float2bfloat16(x);
        Th[(size_t)(n0+r+j*8)*K + k0 + c] = h;
        if(Tl) Tl[(size_t)(n0+r+j*8)*K + k0 + c] = __float2bfloat16(x-__bfloat162float(h));
    }
}

// transpose bf16: v[b][s][d] -> vt[b][d][s]
__global__ void __launch_bounds__(256) transpose_bf_kernel(
    const bf16* __restrict__ v, bf16* __restrict__ vt)
{
    __shared__ bf16 tl[64][65];
    const int s0 = blockIdx.x<<6, d0 = blockIdx.y<<6, z = blockIdx.z;
    const bf16* vz = v + (size_t)z*SEQ*DIM;
    bf16* vtz = vt + (size_t)z*SEQ*DIM;
    const int t = threadIdx.x;
    #pragma unroll
    for(int j=0;j<16;j++){
        int idx = j*256 + t, r = idx>>6, c = idx&63;
        tl[r][c] = vz[(size_t)(s0+r)*DIM + d0 + c];
    }
    __syncthreads();
    #pragma unroll
    for(int j=0;j<16;j++){
        int idx = j*256 + t, r = idx>>6, c = idx&63;
        vtz[(size_t)(d0+r)*SEQ + s0 + c] = tl[c][r];
    }
}

__global__ void __launch_bounds__(256) sgemm_nn(
    const float* __restrict__ A, const float* __restrict__ B,
    const float* __restrict__ bias, float* __restrict__ C,
    int M, int N, int K)
{
    __shared__ float As[8][132];
    __shared__ float Bs[8][128];
    const int t = threadIdx.x;
    const int m0 = blockIdx.y<<7, n0 = blockIdx.x<<7;
    const int arow = t>>1, acol = (t&1)<<2;
    const int brow = t>>5, bcol = (t&31)<<2;
    const float* Ap = A + (size_t)(m0+arow)*K + acol;
    const float* Bp = B + (size_t)brow*N + n0 + bcol;
    float4 ar = *(const float4*)Ap;
    float4 br = *(const float4*)Bp;
    ull c2[8][4];
    #pragma unroll
    for(int i=0;i<8;i++){ c2[i][0]=0; c2[i][1]=0; c2[i][2]=0; c2[i][3]=0; }
    const int tm=(t>>4)<<3, tn=(t&15)<<3;
    const int nt = K>>3;
    for(int kt=0;kt<nt;kt++){
        As[acol+0][arow]=ar.x; As[acol+1][arow]=ar.y;
        As[acol+2][arow]=ar.z; As[acol+3][arow]=ar.w;
        *(float4*)&Bs[brow][bcol]=br;
        __syncthreads();
        if(kt+1<nt){
            ar = *(const float4*)(Ap + ((kt+1)<<3));
            br = *(const float4*)(Bp + (size_t)((kt+1)<<3)*N);
        }
        #pragma unroll
        for(int kk=0;kk<8;kk++){
            float4 a0=*(const float4*)&As[kk][tm];
            float4 a1=*(const float4*)&As[kk][tm+4];
            ulonglong2 w0=*(const ulonglong2*)&Bs[kk][tn];
            ulonglong2 w1=*(const ulonglong2*)&Bs[kk][tn+4];
            float a[8]={a0.x,a0.y,a0.z,a0.w,a1.x,a1.y,a1.z,a1.w};
            #pragma unroll
            for(int i=0;i<8;i++){
                ull ap = pack2(a[i],a[i]);
                c2[i][0]=fma2(ap,w0.x,c2[i][0]);
                c2[i][1]=fma2(ap,w0.y,c2[i][1]);
                c2[i][2]=fma2(ap,w1.x,c2[i][2]);
                c2[i][3]=fma2(ap,w1.y,c2[i][3]);
            }
        }
        __syncthreads();
    }
    #pragma unroll
    for(int i=0;i<8;i++){
        const int row=m0+tm+i;
        float v[8];
        #pragma unroll
        for(int p=0;p<4;p++){ float2 u=up2(c2[i][p]); v[2*p]=u.x; v[2*p+1]=u.y; }
        #pragma unroll
        for(int j=0;j<8;j++) v[j] += bias[n0+tn+j];
        *(float4*)&C[(size_t)row*N + n0+tn]   = make_float4(v[0],v[1],v[2],v[3]);
        *(float4*)&C[(size_t)row*N + n0+tn+4] = make_float4(v[4],v[5],v[6],v[7]);
    }
}

__global__ void init_slots_kernel(const float* __restrict__ noise,
                                  const float* __restrict__ mu,
                                  const float* __restrict__ sigma,
                                  float* __restrict__ slots,
                                  bf16* __restrict__ slh, bf16* __restrict__ sll)
{
    for(int idx = blockIdx.x*blockDim.x + threadIdx.x; idx < SROWS*DIM;
        idx += gridDim.x*blockDim.x){
        int d = idx & 255, ns = (idx>>8)&3, i = (idx>>10)&127, b = idx>>17;
        float val = mu[ns*DIM+d] + noise[(size_t)(((i*BSZ+b)*NS+ns))*DIM+d]*sigma[ns*DIM+d];
        slots[idx] = val;
        bf16 hv = __float2bfloat16(val);
        slh[idx] = hv;
        sll[idx] = __float2bfloat16(val - __bfloat162float(hv));
    }
}

__global__ void norm_rows_kernel(const float* __restrict__ iq,
                                 const float* __restrict__ cls,
                                 float* __restrict__ qn, float* __restrict__ clsn)
{
    const int row = blockIdx.x, lane = threadIdx.x;
    const float* src; float* dst;
    if(row < NI){ src = iq + (size_t)row*DIM; dst = qn + (size_t)row*DIM; }
    else        { src = cls + (size_t)(row-NI)*DIM; dst = clsn + (size_t)(row-NI)*DIM; }
    float4 a0=*(const float4*)(src + (lane<<2));
    float4 a1=*(const float4*)(src + 128 + (lane<<2));
    float ss=a0.x*a0.x+a0.y*a0.y+a0.z*a0.z+a0.w*a0.w
            +a1.x*a1.x+a1.y*a1.y+a1.z*a1.z+a1.w*a1.w;
    ss = wsum(ss);
    float inv = 1.0f/fmaxf(sqrtf(ss), 1e-12f);
    *(float4*)(dst+(lane<<2))     = make_float4(a0.x*inv,a0.y*inv,a0.z*inv,a0.w*inv);
    *(float4*)(dst+128+(lane<<2)) = make_float4(a1.x*inv,a1.y*inv,a1.z*inv,a1.w*inv);
}

// fused: slots = LN1(x); hh = bf16(LN2(slots))
__global__ void __launch_bounds__(256) ln_fused_kernel(
    float* __restrict__ slots,
    const float* __restrict__ g1, const float* __restrict__ b1,
    const float* __restrict__ g2, const float* __restrict__ b2,
    bf16* __restrict__ hh)
{
    const int row = (blockIdx.x<<3) + (threadIdx.x>>5);
    const int lane = threadIdx.x & 31;
    float* xp = slots + (size_t)row*DIM;
    float4 a0=*(const float4*)(xp+(lane<<2));
    float4 a1=*(const float4*)(xp+128+(lane<<2));
    float v[8]={a0.x,a0.y,a0.z,a0.w,a1.x,a1.y,a1.z,a1.w};
    float s1=0.f,s2=0.f;
    #pragma unroll
    for(int q=0;q<8;q++){ s1+=v[q]; s2+=v[q]*v[q]; }
    s1=wsum(s1); s2=wsum(s2);
    float mean=s1*(1.0f/256.0f);
    float rstd=rsqrtf(s2*(1.0f/256.0f)-mean*mean + 1e-5f);
    float4 g10=*(const float4*)(g1+(lane<<2)),  g11=*(const float4*)(g1+128+(lane<<2));
    float4 b10=*(const float4*)(b1+(lane<<2)),  b11=*(const float4*)(b1+128+(lane<<2));
    float o[8];
    o[0]=(v[0]-mean)*rstd*g10.x+b10.x; o[1]=(v[1]-mean)*rstd*g10.y+b10.y;
    o[2]=(v[2]-mean)*rstd*g10.z+b10.z; o[3]=(v[3]-mean)*rstd*g10.w+b10.w;
    o[4]=(v[4]-mean)*rstd*g11.x+b11.x; o[5]=(v[5]-mean)*rstd*g11.y+b11.y;
    o[6]=(v[6]-mean)*rstd*g11.z+b11.z; o[7]=(v[7]-mean)*rstd*g11.w+b11.w;
    *(float4*)(xp+(lane<<2))     = make_float4(o[0],o[1],o[2],o[3]);
    *(float4*)(xp+128+(lane<<2)) = make_float4(o[4],o[5],o[6],o[7]);
    // LN2 on o
    float t1=0.f,t2=0.f;
    #pragma unroll
    for(int q=0;q<8;q++){ t1+=o[q]; t2+=o[q]*o[q]; }
    t1=wsum(t1); t2=wsum(t2);
    float mean2=t1*(1.0f/256.0f);
    float rstd2=rsqrtf(t2*(1.0f/256.0f)-mean2*mean2 + 1e-5f);
    float4 g20=*(const float4*)(g2+(lane<<2)),  g21=*(const float4*)(g2+128+(lane<<2));
    float4 b20=*(const float4*)(b2+(lane<<2)),  b21=*(const float4*)(b2+128+(lane<<2));
    bf16 hb[8];
    hb[0]=__float2bfloat16((o[0]-mean2)*rstd2*g20.x+b20.x);
    hb[1]=__float2bfloat16((o[1]-mean2)*rstd2*g20.y+b20.y);
    hb[2]=__float2bfloat16((o[2]-mean2)*rstd2*g20.z+b20.z);
    hb[3]=__float2bfloat16((o[3]-mean2)*rstd2*g20.w+b20.w);
    hb[4]=__float2bfloat16((o[4]-mean2)*rstd2*g21.x+b21.x);
    hb[5]=__float2bfloat16((o[5]-mean2)*rstd2*g21.y+b21.y);
    hb[6]=__float2bfloat16((o[6]-mean2)*rstd2*g21.z+b21.z);
    hb[7]=__float2bfloat16((o[7]-mean2)*rstd2*g21.w+b21.w);
    *(uint2*)(hh + (size_t)row*DIM + (lane<<2))       = *(uint2*)hb;
    *(uint2*)(hh + (size_t)row*DIM + 128 + (lane<<2)) = *(uint2*)(hb+4);
}

__global__ void __launch_bounds__(128) final_kernel(
    const float* __restrict__ slots, const float* __restrict__ qn,
    const float* __restrict__ clsn, const float* __restrict__ alpha,
    const float* __restrict__ temp, float* __restrict__ out)
{
    __shared__ float sh[4];
    const int i = blockIdx.x, b = blockIdx.y;
    const int w = threadIdx.x>>5, lane = threadIdx.x&31;
    const size_t base = ((size_t)(b*NI + i))*NS;
    const float* qp = qn + (size_t)i*DIM;
    const float* sp = slots + (base+w)*DIM;
    float ss=0.f, dq=0.f;
    #pragma unroll
    for(int q=0;q<8;q++){
        float x=sp[lane+(q<<5)], y=qp[lane+(q<<5)];
        ss+=x*x; dq+=x*y;
    }
    ss=wsum(ss); dq=wsum(dq);
    if(lane==0) sh[w] = dq / fmaxf(sqrtf(ss), 1e-12f);
    __syncthreads();
    float m=fmaxf(fmaxf(sh[0],sh[1]),fmaxf(sh[2],sh[3]));
    float e0=expf(sh[0]-m),e1=expf(sh[1]-m),e2=expf(sh[2]-m),e3=expf(sh[3]-m);
    float inv=1.0f/(e0+e1+e2+e3);
    float a4[4]={e0*inv,e1*inv,e2*inv,e3*inv};
    __syncthreads();
    const int d0=threadIdx.x, d1=threadIdx.x+128;
    float s0=0.f, s1=0.f;
    #pragma unroll
    for(int n=0;n<4;n++){
        const float* rp = slots + (base+n)*DIM;
        s0 += a4[n]*rp[d0]; s1 += a4[n]*rp[d1];
    }
    float pp = wsum(s0*s0 + s1*s1);
    if(lane==0) sh[w]=pp;
    __syncthreads();
    float nrm = fmaxf(sqrtf(sh[0]+sh[1]+sh[2]+sh[3]), 1e-12f);
    float al = *alpha;
    const float* cp = clsn + (size_t)b*DIM;
    float f0 = cp[d0] + al*s0/nrm;
    float f1 = cp[d1] + al*s1/nrm;
    float dot = wsum(f0*qp[d0] + f1*qp[d1]);
    __syncthreads();
    if(lane==0) sh[w]=dot;
    __syncthreads();
    if(threadIdx.x==0)
        out[(size_t)b*NI + i] = (sh[0]+sh[1]+sh[2]+sh[3]) / fmaxf(*temp, 1e-4f);
}

#define GSYM(p, s) cudaGetSymbolAddress((void**)&p, s)

extern "C" void kernel_launch(void* const* d_in, const int* in_sizes, int n_in,
                              void* d_out, int out_size)
{
    const float* tokens=(const float*)d_in[0];
    const float* cls   =(const float*)d_in[1];
    const float* iq    =(const float*)d_in[2];
    const float* noise =(const float*)d_in[3];
    const float* Wk=(const float*)d_in[4],  *bk=(const float*)d_in[5];
    const float* Wv=(const float*)d_in[6],  *bv=(const float*)d_in[7];
    const float* Wqs=(const float*)d_in[8], *bqs=(const float*)d_in[9];
    const float* Wqi=(const float*)d_in[10],*bqi=(const float*)d_in[11];
    const float* ln1g=(const float*)d_in[12],*ln1b=(const float*)d_in[13];
    const float* ln2g=(const float*)d_in[14],*ln2b=(const float*)d_in[15];
    const float* Wf1=(const float*)d_in[16],*bf1=(const float*)d_in[17];
    const float* Wf2=(const float*)d_in[18],*bf2=(const float*)d_in[19];
    const float* mu=(const float*)d_in[20], *sg=(const float*)d_in[21];
    const float* alpha=(const float*)d_in[22],*temp=(const float*)d_in[23];
    float* out=(float*)d_out;

    float *psum,*slots,*qi,*qnp,*clsn;
    bf16 *kbf,*vbf,*vt,*qbf,*P,*tokh,*slh,*sll,*hh,*tbh;
    bf16 *WkTh,*WvTh,*WqsTh,*WqsTl,*Wf1Th,*Wf2Th;
    GSYM(psum,g_psum); GSYM(slots,g_slots);
    GSYM(qi,g_qintent); GSYM(qnp,g_qn); GSYM(clsn,g_clsn);
    GSYM(kbf,g_kbf); GSYM(vbf,g_vbf); GSYM(vt,g_vt); GSYM(qbf,g_qbf); GSYM(P,g_P);
    GSYM(tokh,g_tokh); GSYM(slh,g_slh); GSYM(sll,g_sll);
    GSYM(hh,g_hh); GSYM(tbh,g_tbh);
    GSYM(WkTh,g_WkTh); GSYM(WvTh,g_WvTh);
    GSYM(WqsTh,g_WqsTh); GSYM(WqsTl,g_WqsTl);
    GSYM(Wf1Th,g_Wf1Th); GSYM(Wf2Th,g_Wf2Th);

    cudaFuncSetAttribute(mma_nt,  cudaFuncAttributeMaxDynamicSharedMemorySize, 65536);
    cudaFuncSetAttribute(mma_nt3, cudaFuncAttributeMaxDynamicSharedMemorySize, 131072);

    init_slots_kernel<<<4096,256>>>(noise, mu, sg, slots, slh, sll);
    norm_rows_kernel<<<NI+BSZ,32>>>(iq, cls, qnp, clsn);
    sgemm_nn<<<dim3(2,1),256>>>(iq, Wqi, bqi, qi, NI, DIM, DIM);
    f2bf_kernel<<<(BSZ*SEQ*DIM/4+255)/256,256>>>(tokens, tokh, BSZ*SEQ*DIM/4);
    txsplit_kernel<<<dim3(DIM/32,DIM/32),256>>>(Wk, WkTh, nullptr, DIM, DIM);
    txsplit_kernel<<<dim3(DIM/32,DIM/32),256>>>(Wv, WvTh, nullptr, DIM, DIM);
    txsplit_kernel<<<dim3(DIM/32,DIM/32),256>>>(Wqs, WqsTh, WqsTl, DIM, DIM);
    txsplit_kernel<<<dim3(DIM/32,2*DIM/32),256>>>(Wf1, Wf1Th, nullptr, DIM, 2*DIM);
    txsplit_kernel<<<dim3(2*DIM/32,DIM/32),256>>>(Wf2, Wf2Th, nullptr, 2*DIM, DIM);
    // k/v projections: 1-pass bf16, bf16 out
    mma_nt<<<dim3(2,512,1),256,65536>>>(tokh, WkTh, kbf, nullptr, nullptr, nullptr,
                                        DIM, DIM, DIM, DIM, 0,0,0, 2, nullptr, bk);
    mma_nt<<<dim3(2,512,1),256,65536>>>(tokh, WvTh, vbf, nullptr, nullptr, nullptr,
                                        DIM, DIM, DIM, DIM, 0,0,0, 2, nullptr, bv);
    transpose_bf_kernel<<<dim3(SEQ/64, DIM/64, BSZ),256>>>(vbf, vt);

    for(int it=0; it<3; it++){
        zero_psum_kernel<<<SROWS/256,256>>>(psum);
        mma_nt3<<<dim3(2,4,BSZ),256,131072>>>(slh, sll, WqsTh, WqsTl, bqs, qi,
                                              qbf, DIM, DIM, (size_t)RPB*DIM, (size_t)RPB*DIM);
        mma_nt<<<dim3(SEQ/128, RPB/128, BSZ),256,65536>>>(
            qbf, kbf, P, nullptr, psum, nullptr, DIM, DIM, SEQ, DIM,
            (size_t)RPB*DIM, (size_t)SEQ*DIM, (size_t)RPB*SEQ, 0, nullptr, nullptr);
        mma_nt<<<dim3(DIM/128, RPB/128, BSZ),256,65536>>>(
            P, vt, nullptr, nullptr, psum, slots, SEQ, SEQ, DIM, SEQ,
            (size_t)RPB*SEQ, (size_t)DIM*SEQ, (size_t)RPB*DIM, 1, slots, nullptr);
        ln_fused_kernel<<<SROWS/8,256>>>(slots, ln1g, ln1b, ln2g, ln2b, hh);
        mma_nt<<<dim3(4,128,1),256,65536>>>(hh, Wf1Th, tbh, nullptr, nullptr, nullptr,
                                            DIM, DIM, 2*DIM, DIM, 0,0,0, 4, nullptr, bf1);
        mma_nt<<<dim3(2,128,1),256,65536>>>(tbh, Wf2Th, slh, sll, nullptr, slots,
                                            2*DIM, 2*DIM, DIM, 2*DIM, 0,0,0, 5, slots, bf2);
    }
    final_kernel<<<dim3(NI,BSZ),128>>>(slots, qnp, clsn, alpha, temp, out);
}

// round 10
// speedup vs baseline: 12.3870x; 1.0228x over previous
#include <cuda_runtime.h>
#include <cuda_bf16.h>
#include <cstdint>
#include <math.h>

#define NI 128
#define BSZ 32
#define NS 4
#define SEQ 2048
#define DIM 256
#define SROWS (NI*BSZ*NS)
#define RPB (NI*NS)

typedef unsigned long long ull;
typedef __nv_bfloat16 bf16;
typedef __nv_bfloat162 bf162;

__device__ bf16 g_kbf[BSZ*SEQ*DIM];
__device__ bf16 g_vbf[BSZ*SEQ*DIM];
__device__ bf16 g_vt[BSZ*SEQ*DIM];
__device__ bf16 g_qbf[SROWS*DIM];
__device__ bf16 g_P[(size_t)BSZ*RPB*SEQ];
__device__ float g_psum[SROWS];
__device__ float g_slots[SROWS*DIM];
__device__ float g_qintent[NI*DIM];
__device__ float g_qn[NI*DIM];
__device__ float g_clsn[BSZ*DIM];
__device__ bf16 g_tokh[BSZ*SEQ*DIM];
__device__ bf16 g_slh[SROWS*DIM];
__device__ bf16 g_sll[SROWS*DIM];
__device__ bf16 g_hh[SROWS*DIM];
__device__ bf16 g_tbh[SROWS*2*DIM];
__device__ bf16 g_WkvTh[2*DIM*DIM];      // rows 0-255: Wk^T, 256-511: Wv^T
__device__ float g_bkv[2*DIM];
__device__ bf16 g_WqsTh[DIM*DIM];
__device__ bf16 g_WqsTl[DIM*DIM];
__device__ bf16 g_Wf1Th[2*DIM*DIM];
__device__ bf16 g_Wf2Th[2*DIM*DIM];

__device__ __forceinline__ ull fma2(ull a, ull b, ull c){
    ull d; asm("fma.rn.f32x2 %0, %1, %2, %3;" : "=l"(d) : "l"(a),"l"(b),"l"(c)); return d;
}
__device__ __forceinline__ ull pack2(float x, float y){
    ull d; asm("mov.b64 %0, {%1, %2};" : "=l"(d) : "f"(x),"f"(y)); return d;
}
__device__ __forceinline__ float2 up2(ull v){
    float2 r; asm("mov.b64 {%0, %1}, %2;" : "=f"(r.x),"=f"(r.y) : "l"(v)); return r;
}
__device__ __forceinline__ float wsum(float v){
    #pragma unroll
    for(int o=16;o>0;o>>=1) v += __shfl_xor_sync(0xffffffffu, v, o);
    return v;
}
__device__ __forceinline__ uint32_t smem_u32(const void* p){
    uint32_t a; asm("{ .reg .u64 t; cvta.to.shared.u64 t, %1; cvt.u32.u64 %0, t; }" : "=r"(a) : "l"(p));
    return a;
}
#define SW128(o) ((o) ^ (((o)>>3)&0x70))
__device__ __forceinline__ void ldsm4(uint32_t& r0,uint32_t& r1,uint32_t& r2,uint32_t& r3,uint32_t a){
    asm volatile("ldmatrix.sync.aligned.m8n8.x4.shared.b16 {%0,%1,%2,%3}, [%4];"
        : "=r"(r0),"=r"(r1),"=r"(r2),"=r"(r3) : "r"(a) : "memory");
}
__device__ __forceinline__ void mma16816(float* c,uint32_t a0,uint32_t a1,uint32_t a2,uint32_t a3,uint32_t b0,uint32_t b1){
    asm volatile("mma.sync.aligned.m16n8k16.row.col.f32.bf16.bf16.f32 "
        "{%0,%1,%2,%3},{%4,%5,%6,%7},{%8,%9},{%0,%1,%2,%3};"
        : "+f"(c[0]),"+f"(c[1]),"+f"(c[2]),"+f"(c[3])
        : "r"(a0),"r"(a1),"r"(a2),"r"(a3),"r"(b0),"r"(b1));
}
__device__ __forceinline__ void cpa16(uint32_t d, const void* s){
    asm volatile("cp.async.cg.shared.global [%0], [%1], 16;" :: "r"(d), "l"(s));
}
#define CP_COMMIT() asm volatile("cp.async.commit_group;" ::: "memory")
#define CP_WAIT0()  asm volatile("cp.async.wait_group 0;" ::: "memory")
__device__ __forceinline__ float geluf(float x){
    return 0.5f*x*(1.0f+erff(x*0.70710678118654752f));
}

// ============ bf16 NT GEMM, 1-pass: C[M,N] = A[M,K] @ B[N,K]^T ============
// modes: 0 softmax (Pb=exp(acc/16), psum atomics); 1 upd (C=acc/psum+res);
// 4 gelu(acc+bias) -> Pb bf16; 5 acc+bias+res -> C fp32 + Pb(hi)/Pl(lo);
// 6 kv-merged: cols<256 -> Pb (ld 256), cols>=256 -> Pl (ld 256), +bias[512]
__global__ void __launch_bounds__(256,2) mma_nt(
    const bf16* __restrict__ A, const bf16* __restrict__ B,
    bf16* __restrict__ Pb, bf16* __restrict__ Pl,
    float* __restrict__ psum, float* __restrict__ C,
    int lda, int ldb, int ldc, int K,
    size_t sA, size_t sB, size_t sC, int mode,
    const float* __restrict__ res, const float* __restrict__ bias)
{
    extern __shared__ char sm[];
    const uint32_t su = smem_u32(sm);
    const int t = threadIdx.x, wid = t>>5, lane = t&31, z = blockIdx.z;
    const int m0 = blockIdx.y<<7, n0 = blockIdx.x<<7;
    A += (size_t)z*sA + (size_t)m0*lda;
    B += (size_t)z*sB + (size_t)n0*ldb;
    const int row_ld = t>>3, col_ld = t&7;
    const uint32_t swoff = SW128((uint32_t)(row_ld*128 + col_ld*16));
    const int nsteps = K>>6;
    float acc[2][8][4];
    #pragma unroll
    for(int i=0;i<2;i++)
        #pragma unroll
        for(int j=0;j<8;j++){ acc[i][j][0]=0.f; acc[i][j][1]=0.f; acc[i][j][2]=0.f; acc[i][j][3]=0.f; }
    {
        const bf16* Ag = A + col_ld*8;
        const bf16* Bg = B + col_ld*8;
        #pragma unroll
        for(int j=0;j<4;j++){
            cpa16(su + swoff + j*4096, Ag + (size_t)(row_ld + j*32)*lda);
            cpa16(su + 16384 + swoff + j*4096, Bg + (size_t)(row_ld + j*32)*ldb);
        }
        CP_COMMIT(); CP_WAIT0();
    }
    __syncthreads();
    const int mw = (wid&3)<<5, nw = (wid>>2)<<6;
    for(int s=0;s<nsteps;s++){
        const uint32_t bufc = su + (uint32_t)((s&1)*32768);
        if(s+1<nsteps){
            const uint32_t bufn = su + (uint32_t)(((s+1)&1)*32768);
            const bf16* Ag = A + (size_t)(s+1)*64 + col_ld*8;
            const bf16* Bg = B + (size_t)(s+1)*64 + col_ld*8;
            #pragma unroll
            for(int j=0;j<4;j++){
                cpa16(bufn + swoff + j*4096, Ag + (size_t)(row_ld + j*32)*lda);
                cpa16(bufn + 16384 + swoff + j*4096, Bg + (size_t)(row_ld + j*32)*ldb);
            }
            CP_COMMIT();
        }
        #pragma unroll
        for(int kk=0;kk<4;kk++){
            const int kb = kk*32 + ((lane>>4)*16);
            uint32_t a[2][4];
            #pragma unroll
            for(int mf=0;mf<2;mf++){
                int row = mw + mf*16 + (lane&15);
                ldsm4(a[mf][0],a[mf][1],a[mf][2],a[mf][3], bufc + SW128((uint32_t)(row*128 + kb)));
            }
            #pragma unroll
            for(int ng=0;ng<4;ng++){
                int row = nw + ng*16 + (lane&15);
                uint32_t b0,b1,b2,b3;
                ldsm4(b0,b1,b2,b3, bufc + 16384 + SW128((uint32_t)(row*128 + kb)));
                #pragma unroll
                for(int mf=0;mf<2;mf++){
                    mma16816(acc[mf][ng*2+0], a[mf][0],a[mf][1],a[mf][2],a[mf][3], b0, b2);
                    mma16816(acc[mf][ng*2+1], a[mf][0],a[mf][1],a[mf][2],a[mf][3], b1, b3);
                }
            }
        }
        if(s+1<nsteps) CP_WAIT0();
        __syncthreads();
    }
    const int gr = lane>>2, gc = (lane&3)<<1;
    if(mode==0){
        Pb += (size_t)z*sC;
        #pragma unroll
        for(int mf=0;mf<2;mf++){
            const int r0 = m0 + mw + mf*16 + gr, r1 = r0 + 8;
            float s0=0.f, s1=0.f;
            #pragma unroll
            for(int ng=0;ng<4;ng++){
                #pragma unroll
                for(int h=0;h<2;h++){
                    const int col = n0 + nw + ng*16 + h*8 + gc;
                    float* cc = acc[mf][ng*2+h];
                    float e00=__expf(cc[0]*0.0625f), e01=__expf(cc[1]*0.0625f);
                    float e10=__expf(cc[2]*0.0625f), e11=__expf(cc[3]*0.0625f);
                    bf162 p0; p0.x=__float2bfloat16(e00); p0.y=__float2bfloat16(e01);
                    bf162 p1; p1.x=__float2bfloat16(e10); p1.y=__float2bfloat16(e11);
                    *(bf162*)&Pb[(size_t)r0*ldc + col] = p0;
                    *(bf162*)&Pb[(size_t)r1*ldc + col] = p1;
                    s0 += e00+e01; s1 += e10+e11;
                }
            }
            s0 += __shfl_xor_sync(0xffffffffu, s0, 1);
            s0 += __shfl_xor_sync(0xffffffffu, s0, 2);
            s1 += __shfl_xor_sync(0xffffffffu, s1, 1);
            s1 += __shfl_xor_sync(0xffffffffu, s1, 2);
            if((lane&3)==0){
                atomicAdd(&psum[z*RPB + r0], s0);
                atomicAdd(&psum[z*RPB + r1], s1);
            }
        }
    } else if(mode==1){
        C += (size_t)z*sC;
        const float* rz = res + (size_t)z*sC;
        #pragma unroll
        for(int mf=0;mf<2;mf++){
            const int r0 = m0 + mw + mf*16 + gr, r1 = r0 + 8;
            const float i0 = 1.0f/psum[z*RPB + r0];
            const float i1 = 1.0f/psum[z*RPB + r1];
            #pragma unroll
            for(int ng=0;ng<4;ng++){
                #pragma unroll
                for(int h=0;h<2;h++){
                    const int col = n0 + nw + ng*16 + h*8 + gc;
                    float* cc = acc[mf][ng*2+h];
                    C[(size_t)r0*ldc + col]   = cc[0]*i0 + rz[(size_t)r0*ldc + col];
                    C[(size_t)r0*ldc + col+1] = cc[1]*i0 + rz[(size_t)r0*ldc + col+1];
                    C[(size_t)r1*ldc + col]   = cc[2]*i1 + rz[(size_t)r1*ldc + col];
                    C[(size_t)r1*ldc + col+1] = cc[3]*i1 + rz[(size_t)r1*ldc + col+1];
                }
            }
        }
    } else if(mode==6){
        #pragma unroll
        for(int mf=0;mf<2;mf++){
            const int r0 = m0 + mw + mf*16 + gr, r1 = r0 + 8;
            #pragma unroll
            for(int ng=0;ng<4;ng++){
                #pragma unroll
                for(int h=0;h<2;h++){
                    const int col = n0 + nw + ng*16 + h*8 + gc;
                    float* cc = acc[mf][ng*2+h];
                    float b0=bias[col], b1=bias[col+1];
                    float x00=cc[0]+b0, x01=cc[1]+b1, x10=cc[2]+b0, x11=cc[3]+b1;
                    bf162 p0; p0.x=__float2bfloat16(x00); p0.y=__float2bfloat16(x01);
                    bf162 p1; p1.x=__float2bfloat16(x10); p1.y=__float2bfloat16(x11);
                    bf16* dst = (col < 256) ? Pb : Pl;
                    const int c2 = col & 255;
                    *(bf162*)&dst[(size_t)r0*256 + c2] = p0;
                    *(bf162*)&dst[(size_t)r1*256 + c2] = p1;
                }
            }
        }
    } else {
        #pragma unroll
        for(int mf=0;mf<2;mf++){
            const int r0 = m0 + mw + mf*16 + gr, r1 = r0 + 8;
            #pragma unroll
            for(int ng=0;ng<4;ng++){
                #pragma unroll
                for(int h=0;h<2;h++){
                    const int col = n0 + nw + ng*16 + h*8 + gc;
                    float* cc = acc[mf][ng*2+h];
                    float b0=bias[col], b1=bias[col+1];
                    float x00=cc[0]+b0, x01=cc[1]+b1, x10=cc[2]+b0, x11=cc[3]+b1;
                    if(mode==4){ x00=geluf(x00); x01=geluf(x01); x10=geluf(x10); x11=geluf(x11); }
                    if(mode==5){
                        x00 += res[(size_t)r0*ldc + col];
                        x01 += res[(size_t)r0*ldc + col + 1];
                        x10 += res[(size_t)r1*ldc + col];
                        x11 += res[(size_t)r1*ldc + col + 1];
                        C[(size_t)r0*ldc + col]   = x00; C[(size_t)r0*ldc + col+1] = x01;
                        C[(size_t)r1*ldc + col]   = x10; C[(size_t)r1*ldc + col+1] = x11;
                    }
                    bf162 p0; p0.x=__float2bfloat16(x00); p0.y=__float2bfloat16(x01);
                    bf162 p1; p1.x=__float2bfloat16(x10); p1.y=__float2bfloat16(x11);
                    *(bf162*)&Pb[(size_t)r0*ldc + col] = p0;
                    *(bf162*)&Pb[(size_t)r1*ldc + col] = p1;
                    if(mode==5){
                        bf162 q0, q1;
                        q0.x=__float2bfloat16(x00-__bfloat162float(p0.x));
                        q0.y=__float2bfloat16(x01-__bfloat162float(p0.y));
                        q1.x=__float2bfloat16(x10-__bfloat162float(p1.x));
                        q1.y=__float2bfloat16(x11-__bfloat162float(p1.y));
                        *(bf162*)&Pl[(size_t)r0*ldc + col] = q0;
                        *(bf162*)&Pl[(size_t)r1*ldc + col] = q1;
                    }
                }
            }
        }
    }
}

// ============ split-bf16 3-pass NT GEMM (qslot): Cbh = bf16(A@B^T + bias + ext) ============
// blockIdx.x==0 CTAs also zero psum rows [z*RPB+m0, +128) before the mainloop.
__global__ void __launch_bounds__(256) mma_nt3(
    const bf16* __restrict__ Ah, const bf16* __restrict__ Al,
    const bf16* __restrict__ Bh, const bf16* __restrict__ Bl,
    const float* __restrict__ bias, const float* __restrict__ ext,
    bf16* __restrict__ Cbh, float* __restrict__ psum,
    int ldc, int K, size_t sA, size_t sC)
{
    extern __shared__ char sm[];
    const uint32_t su = smem_u32(sm);
    const int t = threadIdx.x, wid = t>>5, lane = t&31, z = blockIdx.z;
    const int m0 = blockIdx.y<<7, n0 = blockIdx.x<<7;
    if(blockIdx.x==0 && t<128) psum[z*RPB + m0 + t] = 0.f;
    Ah += (size_t)z*sA + (size_t)m0*K;
    Al += (size_t)z*sA + (size_t)m0*K;
    Bh += (size_t)n0*K;
    Bl += (size_t)n0*K;
    const int row_ld = t>>3, col_ld = t&7;
    const uint32_t swoff = SW128((uint32_t)(row_ld*128 + col_ld*16));
    const int nsteps = K>>6;
    float acc[2][8][4];
    #pragma unroll
    for(int i=0;i<2;i++)
        #pragma unroll
        for(int j=0;j<8;j++){ acc[i][j][0]=0.f; acc[i][j][1]=0.f; acc[i][j][2]=0.f; acc[i][j][3]=0.f; }
    {
        #pragma unroll
        for(int j=0;j<4;j++){
            size_t ro = (size_t)(row_ld + j*32)*K + col_ld*8;
            cpa16(su +         swoff + j*4096, Ah + ro);
            cpa16(su + 16384 + swoff + j*4096, Al + ro);
            cpa16(su + 32768 + swoff + j*4096, Bh + ro);
            cpa16(su + 49152 + swoff + j*4096, Bl + ro);
        }
        CP_COMMIT(); CP_WAIT0();
    }
    __syncthreads();
    const int mw = (wid&3)<<5, nw = (wid>>2)<<6;
    for(int s=0;s<nsteps;s++){
        const uint32_t bufc = su + (uint32_t)((s&1)*65536);
        if(s+1<nsteps){
            const uint32_t bufn = su + (uint32_t)(((s+1)&1)*65536);
            const size_t ko = (size_t)(s+1)*64 + col_ld*8;
            #pragma unroll
            for(int j=0;j<4;j++){
                size_t ro = (size_t)(row_ld + j*32)*K + ko;
                cpa16(bufn +         swoff + j*4096, Ah + ro);
                cpa16(bufn + 16384 + swoff + j*4096, Al + ro);
                cpa16(bufn + 32768 + swoff + j*4096, Bh + ro);
                cpa16(bufn + 49152 + swoff + j*4096, Bl + ro);
            }
            CP_COMMIT();
        }
        #pragma unroll
        for(int kk=0;kk<4;kk++){
            const int kb = kk*32 + ((lane>>4)*16);
            uint32_t ah[2][4], al[2][4];
            #pragma unroll
            for(int mf=0;mf<2;mf++){
                int row = mw + mf*16 + (lane&15);
                uint32_t so = SW128((uint32_t)(row*128 + kb));
                ldsm4(ah[mf][0],ah[mf][1],ah[mf][2],ah[mf][3], bufc + so);
                ldsm4(al[mf][0],al[mf][1],al[mf][2],al[mf][3], bufc + 16384 + so);
            }
            #pragma unroll
            for(int ng=0;ng<4;ng++){
                int row = nw + ng*16 + (lane&15);
                uint32_t so = SW128((uint32_t)(row*128 + kb));
                uint32_t bh0,bh1,bh2,bh3, bl0,bl1,bl2,bl3;
                ldsm4(bh0,bh1,bh2,bh3, bufc + 32768 + so);
                ldsm4(bl0,bl1,bl2,bl3, bufc + 49152 + so);
                #pragma unroll
                for(int mf=0;mf<2;mf++){
                    mma16816(acc[mf][ng*2+0], ah[mf][0],ah[mf][1],ah[mf][2],ah[mf][3], bh0, bh2);
                    mma16816(acc[mf][ng*2+1], ah[mf][0],ah[mf][1],ah[mf][2],ah[mf][3], bh1, bh3);
                    mma16816(acc[mf][ng*2+0], ah[mf][0],ah[mf][1],ah[mf][2],ah[mf][3], bl0, bl2);
                    mma16816(acc[mf][ng*2+1], ah[mf][0],ah[mf][1],ah[mf][2],ah[mf][3], bl1, bl3);
                    mma16816(acc[mf][ng*2+0], al[mf][0],al[mf][1],al[mf][2],al[mf][3], bh0, bh2);
                    mma16816(acc[mf][ng*2+1], al[mf][0],al[mf][1],al[mf][2],al[mf][3], bh1, bh3);
                }
            }
        }
        if(s+1<nsteps) CP_WAIT0();
        __syncthreads();
    }
    Cbh += (size_t)z*sC;
    const int gr = lane>>2, gc = (lane&3)<<1;
    #pragma unroll
    for(int mf=0;mf<2;mf++){
        const int r0 = m0 + mw + mf*16 + gr, r1 = r0 + 8;
        #pragma unroll
        for(int ng=0;ng<4;ng++){
            #pragma unroll
            for(int h=0;h<2;h++){
                const int col = n0 + nw + ng*16 + h*8 + gc;
                float* cc = acc[mf][ng*2+h];
                float b0=bias[col], b1=bias[col+1];
                float x00=cc[0]+b0+ext[(size_t)(r0>>2)*ldc + col];
                float x01=cc[1]+b1+ext[(size_t)(r0>>2)*ldc + col + 1];
                float x10=cc[2]+b0+ext[(size_t)(r1>>2)*ldc + col];
                float x11=cc[3]+b1+ext[(size_t)(r1>>2)*ldc + col + 1];
                bf162 p0; p0.x=__float2bfloat16(x00); p0.y=__float2bfloat16(x01);
                bf162 p1; p1.x=__float2bfloat16(x10); p1.y=__float2bfloat16(x11);
                *(bf162*)&Cbh[(size_t)r0*ldc + col] = p0;
                *(bf162*)&Cbh[(size_t)r1*ldc + col] = p1;
            }
        }
    }
}

__global__ void __launch_bounds__(256) f2bf_kernel(
    const float* __restrict__ x, bf16* __restrict__ y, int n4)
{
    int i = blockIdx.x*blockDim.x + threadIdx.x;
    if (i >= n4) return;
    float4 v = ((const float4*)x)[i];
    bf162 a; a.x=__float2bfloat16(v.x); a.y=__float2bfloat16(v.y);
    bf162 b; b.x=__float2bfloat16(v.z); b.y=__float2bfloat16(v.w);
    ((bf162*)y)[2*i] = a;
    ((bf162*)y)[2*i+1] = b;
}

// one kernel preps ALL weights: z: 0=Wk->Wkv[0:256), 1=Wv->Wkv[256:512), 2=Wqs(h+l),
// 3=Wf1, 4=Wf2; z==0,block(8,0) also concats bias kv.
__global__ void __launch_bounds__(256) prep_weights_kernel(
    const float* __restrict__ Wk, const float* __restrict__ Wv,
    const float* __restrict__ Wqs, const float* __restrict__ Wf1,
    const float* __restrict__ Wf2, const float* __restrict__ bk,
    const float* __restrict__ bv,
    bf16* __restrict__ WkvTh, bf16* __restrict__ WqsTh, bf16* __restrict__ WqsTl,
    bf16* __restrict__ Wf1Th, bf16* __restrict__ Wf2Th, float* __restrict__ bkv)
{
    __shared__ float tl[32][33];
    const int zz = blockIdx.z, t = threadIdx.x, r = t>>5, c = t&31;
    if(zz==0 && blockIdx.x==8 && blockIdx.y==0){
        bkv[t] = bk[t]; bkv[256+t] = bv[t];
        return;
    }
    const float* W; bf16 *Th, *Tl=nullptr; int K, N, noff=0;
    if(zz==0){ W=Wk; Th=WkvTh; K=DIM; N=DIM; }
    else if(zz==1){ W=Wv; Th=WkvTh; K=DIM; N=DIM; noff=256; }
    else if(zz==2){ W=Wqs; Th=WqsTh; Tl=WqsTl; K=DIM; N=DIM; }
    else if(zz==3){ W=Wf1; Th=Wf1Th; K=DIM; N=2*DIM; }
    else { W=Wf2; Th=Wf2Th; K=2*DIM; N=DIM; }
    const int k0 = blockIdx.x<<5, n0 = blockIdx.y<<5;
    if(k0 >= K || n0 >= N) return;
    #pragma unroll
    for(int j=0;j<4;j++)
        tl[r+j*8][c] = W[(size_t)(k0+r+j*8)*N + n0 + c];
    __syncthreads();
    #pragma unroll
    for(int j=0;j<4;j++){
        float x = tl[c][r+j*8];
        bf16 h = __float2bfloat16(x);
        Th[(size_t)(noff+n0+r+j*8)*K + k0 + c] = h;
        if(Tl) Tl[(size_t)(n0+r+j*8)*K + k0 + c] = __float2bfloat16(x-__bfloat162float(h));
    }
}

// transpose bf16: v[b][s][d] -> vt[b][d][s]
__global__ void __launch_bounds__(256) transpose_bf_kernel(
    const bf16* __restrict__ v, bf16* __restrict__ vt)
{
    __shared__ bf16 tl[64][65];
    const int s0 = blockIdx.x<<6, d0 = blockIdx.y<<6, z = blockIdx.z;
    const bf16* vz = v + (size_t)z*SEQ*DIM;
    bf16* vtz = vt + (size_t)z*SEQ*DIM;
    const int t = threadIdx.x;
    #pragma unroll
    for(int j=0;j<16;j++){
        int idx = j*256 + t, r = idx>>6, c = idx&63;
        tl[r][c] = vz[(size_t)(s0+r)*DIM + d0 + c];
    }
    __syncthreads();
    #pragma unroll
    for(int j=0;j<16;j++){
        int idx = j*256 + t, r = idx>>6, c = idx&63;
        vtz[(size_t)(d0+r)*SEQ + s0 + c] = tl[c][r];
    }
}

__global__ void __launch_bounds__(256) sgemm_nn(
    const float* __restrict__ A, const float* __restrict__ B,
    const float* __restrict__ bias, float* __restrict__ C,
    int M, int N, int K)
{
    __shared__ float As[8][132];
    __shared__ float Bs[8][128];
    const int t = threadIdx.x;
    const int m0 = blockIdx.y<<7, n0 = blockIdx.x<<7;
    const int arow = t>>1, acol = (t&1)<<2;
    const int brow = t>>5, bcol = (t&31)<<2;
    const float* Ap = A + (size_t)(m0+arow)*K + acol;
    const float* Bp = B + (size_t)brow*N + n0 + bcol;
    float4 ar = *(const float4*)Ap;
    float4 br = *(const float4*)Bp;
    ull c2[8][4];
    #pragma unroll
    for(int i=0;i<8;i++){ c2[i][0]=0; c2[i][1]=0; c2[i][2]=0; c2[i][3]=0; }
    const int tm=(t>>4)<<3, tn=(t&15)<<3;
    const int nt = K>>3;
    for(int kt=0;kt<nt;kt++){
        As[acol+0][arow]=ar.x; As[acol+1][arow]=ar.y;
        As[acol+2][arow]=ar.z; As[acol+3][arow]=ar.w;
        *(float4*)&Bs[brow][bcol]=br;
        __syncthreads();
        if(kt+1<nt){
            ar = *(const float4*)(Ap + ((kt+1)<<3));
            br = *(const float4*)(Bp + (size_t)((kt+1)<<3)*N);
        }
        #pragma unroll
        for(int kk=0;kk<8;kk++){
            float4 a0=*(const float4*)&As[kk][tm];
            float4 a1=*(const float4*)&As[kk][tm+4];
            ulonglong2 w0=*(const ulonglong2*)&Bs[kk][tn];
            ulonglong2 w1=*(const ulonglong2*)&Bs[kk][tn+4];
            float a[8]={a0.x,a0.y,a0.z,a0.w,a1.x,a1.y,a1.z,a1.w};
            #pragma unroll
            for(int i=0;i<8;i++){
                ull ap = pack2(a[i],a[i]);
                c2[i][0]=fma2(ap,w0.x,c2[i][0]);
                c2[i][1]=fma2(ap,w0.y,c2[i][1]);
                c2[i][2]=fma2(ap,w1.x,c2[i][2]);
                c2[i][3]=fma2(ap,w1.y,c2[i][3]);
            }
        }
        __syncthreads();
    }
    #pragma unroll
    for(int i=0;i<8;i++){
        const int row=m0+tm+i;
        float v[8];
        #pragma unroll
        for(int p=0;p<4;p++){ float2 u=up2(c2[i][p]); v[2*p]=u.x; v[2*p+1]=u.y; }
        #pragma unroll
        for(int j=0;j<8;j++) v[j] += bias[n0+tn+j];
        *(float4*)&C[(size_t)row*N + n0+tn]   = make_float4(v[0],v[1],v[2],v[3]);
        *(float4*)&C[(size_t)row*N + n0+tn+4] = make_float4(v[4],v[5],v[6],v[7]);
    }
}

__global__ void init_slots_kernel(const float* __restrict__ noise,
                                  const float* __restrict__ mu,
                                  const float* __restrict__ sigma,
                                  float* __restrict__ slots,
                                  bf16* __restrict__ slh, bf16* __restrict__ sll)
{
    for(int idx = blockIdx.x*blockDim.x + threadIdx.x; idx < SROWS*DIM;
        idx += gridDim.x*blockDim.x){
        int d = idx & 255, ns = (idx>>8)&3, i = (idx>>10)&127, b = idx>>17;
        float val = mu[ns*DIM+d] + noise[(size_t)(((i*BSZ+b)*NS+ns))*DIM+d]*sigma[ns*DIM+d];
        slots[idx] = val;
        bf16 hv = __float2bfloat16(val);
        slh[idx] = hv;
        sll[idx] = __float2bfloat16(val - __bfloat162float(hv));
    }
}

__global__ void norm_rows_kernel(const float* __restrict__ iq,
                                 const float* __restrict__ cls,
                                 float* __restrict__ qn, float* __restrict__ clsn)
{
    const int row = blockIdx.x, lane = threadIdx.x;
    const float* src; float* dst;
    if(row < NI){ src = iq + (size_t)row*DIM; dst = qn + (size_t)row*DIM; }
    else        { src = cls + (size_t)(row-NI)*DIM; dst = clsn + (size_t)(row-NI)*DIM; }
    float4 a0=*(const float4*)(src + (lane<<2));
    float4 a1=*(const float4*)(src + 128 + (lane<<2));
    float ss=a0.x*a0.x+a0.y*a0.y+a0.z*a0.z+a0.w*a0.w
            +a1.x*a1.x+a1.y*a1.y+a1.z*a1.z+a1.w*a1.w;
    ss = wsum(ss);
    float inv = 1.0f/fmaxf(sqrtf(ss), 1e-12f);
    *(float4*)(dst+(lane<<2))     = make_float4(a0.x*inv,a0.y*inv,a0.z*inv,a0.w*inv);
    *(float4*)(dst+128+(lane<<2)) = make_float4(a1.x*inv,a1.y*inv,a1.z*inv,a1.w*inv);
}

// fused: slots = LN1(x); hh = bf16(LN2(slots))
__global__ void __launch_bounds__(256) ln_fused_kernel(
    float* __restrict__ slots,
    const float* __restrict__ g1, const float* __restrict__ b1,
    const float* __restrict__ g2, const float* __restrict__ b2,
    bf16* __restrict__ hh)
{
    const int row = (blockIdx.x<<3) + (threadIdx.x>>5);
    const int lane = threadIdx.x & 31;
    float* xp = slots + (size_t)row*DIM;
    float4 a0=*(const float4*)(xp+(lane<<2));
    float4 a1=*(const float4*)(xp+128+(lane<<2));
    float v[8]={a0.x,a0.y,a0.z,a0.w,a1.x,a1.y,a1.z,a1.w};
    float s1=0.f,s2=0.f;
    #pragma unroll
    for(int q=0;q<8;q++){ s1+=v[q]; s2+=v[q]*v[q]; }
    s1=wsum(s1); s2=wsum(s2);
    float mean=s1*(1.0f/256.0f);
    float rstd=rsqrtf(s2*(1.0f/256.0f)-mean*mean + 1e-5f);
    float4 g10=*(const float4*)(g1+(lane<<2)),  g11=*(const float4*)(g1+128+(lane<<2));
    float4 b10=*(const float4*)(b1+(lane<<2)),  b11=*(const float4*)(b1+128+(lane<<2));
    float o[8];
    o[0]=(v[0]-mean)*rstd*g10.x+b10.x; o[1]=(v[1]-mean)*rstd*g10.y+b10.y;
    o[2]=(v[2]-mean)*rstd*g10.z+b10.z; o[3]=(v[3]-mean)*rstd*g10.w+b10.w;
    o[4]=(v[4]-mean)*rstd*g11.x+b11.x; o[5]=(v[5]-mean)*rstd*g11.y+b11.y;
    o[6]=(v[6]-mean)*rstd*g11.z+b11.z; o[7]=(v[7]-mean)*rstd*g11.w+b11.w;
    *(float4*)(xp+(lane<<2))     = make_float4(o[0],o[1],o[2],o[3]);
    *(float4*)(xp+128+(lane<<2)) = make_float4(o[4],o[5],o[6],o[7]);
    float t1=0.f,t2=0.f;
    #pragma unroll
    for(int q=0;q<8;q++){ t1+=o[q]; t2+=o[q]*o[q]; }
    t1=wsum(t1); t2=wsum(t2);
    float mean2=t1*(1.0f/256.0f);
    float rstd2=rsqrtf(t2*(1.0f/256.0f)-mean2*mean2 + 1e-5f);
    float4 g20=*(const float4*)(g2+(lane<<2)),  g21=*(const float4*)(g2+128+(lane<<2));
    float4 b20=*(const float4*)(b2+(lane<<2)),  b21=*(const float4*)(b2+128+(lane<<2));
    bf16 hb[8];
    hb[0]=__float2bfloat16((o[0]-mean2)*rstd2*g20.x+b20.x);
    hb[1]=__float2bfloat16((o[1]-mean2)*rstd2*g20.y+b20.y);
    hb[2]=__float2bfloat16((o[2]-mean2)*rstd2*g20.z+b20.z);
    hb[3]=__float2bfloat16((o[3]-mean2)*rstd2*g20.w+b20.w);
    hb[4]=__float2bfloat16((o[4]-mean2)*rstd2*g21.x+b21.x);
    hb[5]=__float2bfloat16((o[5]-mean2)*rstd2*g21.y+b21.y);
    hb[6]=__float2bfloat16((o[6]-mean2)*rstd2*g21.z+b21.z);
    hb[7]=__float2bfloat16((o[7]-mean2)*rstd2*g21.w+b21.w);
    *(uint2*)(hh + (size_t)row*DIM + (lane<<2))       = *(uint2*)hb;
    *(uint2*)(hh + (size_t)row*DIM + 128 + (lane<<2)) = *(uint2*)(hb+4);
}

__global__ void __launch_bounds__(128) final_kernel(
    const float* __restrict__ slots, const float* __restrict__ qn,
    const float* __restrict__ clsn, const float* __restrict__ alpha,
    const float* __restrict__ temp, float* __restrict__ out)
{
    __shared__ float sh[4];
    const int i = blockIdx.x, b = blockIdx.y;
    const int w = threadIdx.x>>5, lane = threadIdx.x&31;
    const size_t base = ((size_t)(b*NI + i))*NS;
    const float* qp = qn + (size_t)i*DIM;
    const float* sp = slots + (base+w)*DIM;
    float ss=0.f, dq=0.f;
    #pragma unroll
    for(int q=0;q<8;q++){
        float x=sp[lane+(q<<5)], y=qp[lane+(q<<5)];
        ss+=x*x; dq+=x*y;
    }
    ss=wsum(ss); dq=wsum(dq);
    if(lane==0) sh[w] = dq / fmaxf(sqrtf(ss), 1e-12f);
    __syncthreads();
    float m=fmaxf(fmaxf(sh[0],sh[1]),fmaxf(sh[2],sh[3]));
    float e0=expf(sh[0]-m),e1=expf(sh[1]-m),e2=expf(sh[2]-m),e3=expf(sh[3]-m);
    float inv=1.0f/(e0+e1+e2+e3);
    float a4[4]={e0*inv,e1*inv,e2*inv,e3*inv};
    __syncthreads();
    const int d0=threadIdx.x, d1=threadIdx.x+128;
    float s0=0.f, s1=0.f;
    #pragma unroll
    for(int n=0;n<4;n++){
        const float* rp = slots + (base+n)*DIM;
        s0 += a4[n]*rp[d0]; s1 += a4[n]*rp[d1];
    }
    float pp = wsum(s0*s0 + s1*s1);
    if(lane==0) sh[w]=pp;
    __syncthreads();
    float nrm = fmaxf(sqrtf(sh[0]+sh[1]+sh[2]+sh[3]), 1e-12f);
    float al = *alpha;
    const float* cp = clsn + (size_t)b*DIM;
    float f0 = cp[d0] + al*s0/nrm;
    float f1 = cp[d1] + al*s1/nrm;
    float dot = wsum(f0*qp[d0] + f1*qp[d1]);
    __syncthreads();
    if(lane==0) sh[w]=dot;
    __syncthreads();
    if(threadIdx.x==0)
        out[(size_t)b*NI + i] = (sh[0]+sh[1]+sh[2]+sh[3]) / fmaxf(*temp, 1e-4f);
}

#define GSYM(p, s) cudaGetSymbolAddress((void**)&p, s)

extern "C" void kernel_launch(void* const* d_in, const int* in_sizes, int n_in,
                              void* d_out, int out_size)
{
    const float* tokens=(const float*)d_in[0];
    const float* cls   =(const float*)d_in[1];
    const float* iq    =(const float*)d_in[2];
    const float* noise =(const float*)d_in[3];
    const float* Wk=(const float*)d_in[4],  *bk=(const float*)d_in[5];
    const float* Wv=(const float*)d_in[6],  *bv=(const float*)d_in[7];
    const float* Wqs=(const float*)d_in[8], *bqs=(const float*)d_in[9];
    const float* Wqi=(const float*)d_in[10],*bqi=(const float*)d_in[11];
    const float* ln1g=(const float*)d_in[12],*ln1b=(const float*)d_in[13];
    const float* ln2g=(const float*)d_in[14],*ln2b=(const float*)d_in[15];
    const float* Wf1=(const float*)d_in[16],*bf1=(const float*)d_in[17];
    const float* Wf2=(const float*)d_in[18],*bf2=(const float*)d_in[19];
    const float* mu=(const float*)d_in[20], *sg=(const float*)d_in[21];
    const float* alpha=(const float*)d_in[22],*temp=(const float*)d_in[23];
    float* out=(float*)d_out;

    float *psum,*slots,*qi,*qnp,*clsn,*bkv;
    bf16 *kbf,*vbf,*vt,*qbf,*P,*tokh,*slh,*sll,*hh,*tbh;
    bf16 *WkvTh,*WqsTh,*WqsTl,*Wf1Th,*Wf2Th;
    GSYM(psum,g_psum); GSYM(slots,g_slots);
    GSYM(qi,g_qintent); GSYM(qnp,g_qn); GSYM(clsn,g_clsn); GSYM(bkv,g_bkv);
    GSYM(kbf,g_kbf); GSYM(vbf,g_vbf); GSYM(vt,g_vt); GSYM(qbf,g_qbf); GSYM(P,g_P);
    GSYM(tokh,g_tokh); GSYM(slh,g_slh); GSYM(sll,g_sll);
    GSYM(hh,g_hh); GSYM(tbh,g_tbh);
    GSYM(WkvTh,g_WkvTh);
    GSYM(WqsTh,g_WqsTh); GSYM(WqsTl,g_WqsTl);
    GSYM(Wf1Th,g_Wf1Th); GSYM(Wf2Th,g_Wf2Th);

    cudaFuncSetAttribute(mma_nt,  cudaFuncAttributeMaxDynamicSharedMemorySize, 65536);
    cudaFuncSetAttribute(mma_nt3, cudaFuncAttributeMaxDynamicSharedMemorySize, 131072);

    init_slots_kernel<<<4096,256>>>(noise, mu, sg, slots, slh, sll);
    norm_rows_kernel<<<NI+BSZ,32>>>(iq, cls, qnp, clsn);
    sgemm_nn<<<dim3(2,1),256>>>(iq, Wqi, bqi, qi, NI, DIM, DIM);
    f2bf_kernel<<<(BSZ*SEQ*DIM/4+255)/256,256>>>(tokens, tokh, BSZ*SEQ*DIM/4);
    prep_weights_kernel<<<dim3(17,16,5),256>>>(Wk, Wv, Wqs, Wf1, Wf2, bk, bv,
                                               WkvTh, WqsTh, WqsTl, Wf1Th, Wf2Th, bkv);
    // merged k+v projection: N=512 (cols<256 -> kbf, >=256 -> vbf)
    mma_nt<<<dim3(4,512,1),256,65536>>>(tokh, WkvTh, kbf, vbf, nullptr, nullptr,
                                        DIM, DIM, 512, DIM, 0,0,0, 6, nullptr, bkv);
    transpose_bf_kernel<<<dim3(SEQ/64, DIM/64, BSZ),256>>>(vbf, vt);

    for(int it=0; it<3; it++){
        mma_nt3<<<dim3(2,4,BSZ),256,131072>>>(slh, sll, WqsTh, WqsTl, bqs, qi,
                                              qbf, psum, DIM, DIM, (size_t)RPB*DIM, (size_t)RPB*DIM);
        mma_nt<<<dim3(SEQ/128, RPB/128, BSZ),256,65536>>>(
            qbf, kbf, P, nullptr, psum, nullptr, DIM, DIM, SEQ, DIM,
            (size_t)RPB*DIM, (size_t)SEQ*DIM, (size_t)RPB*SEQ, 0, nullptr, nullptr);
        mma_nt<<<dim3(DIM/128, RPB/128, BSZ),256,65536>>>(
            P, vt, nullptr, nullptr, psum, slots, SEQ, SEQ, DIM, SEQ,
            (size_t)RPB*SEQ, (size_t)DIM*SEQ, (size_t)RPB*DIM, 1, slots, nullptr);
        ln_fused_kernel<<<SROWS/8,256>>>(slots, ln1g, ln1b, ln2g, ln2b, hh);
        mma_nt<<<dim3(4,128,1),256,65536>>>(hh, Wf1Th, tbh, nullptr, nullptr, nullptr,
                                            DIM, DIM, 2*DIM, DIM, 0,0,0, 4, nullptr, bf1);
        mma_nt<<<dim3(2,128,1),256,65536>>>(tbh, Wf2Th, slh, sll, nullptr, slots,
                                            2*DIM, 2*DIM, DIM, 2*DIM, 0,0,0, 5, slots, bf2);
    }
    final_kernel<<<dim3(NI,BSZ),128>>>(slots, qnp, clsn, alpha, temp, out);
}